// round 6
// baseline (speedup 1.0000x reference)
#include <cuda_runtime.h>
#include <cuda_fp16.h>
#include <math.h>
#include <stdint.h>

// ---------------- problem constants ----------------
#define Nn   10000
#define Bb   8
#define Tt   12
#define Ff   8
#define Hh   64
#define Ee   320000
#define HOR  12
#define Mm   (Bb*Nn)          // 80000 rows
#define KCAT 320              // 5*H
#define CDEC 96               // F*HOR

// ---------------- scratch (__device__ globals; no cudaMalloc) ----------------
__device__ float g_h0[Mm*Hh];
__device__ float g_z0[Mm*Hh];
__device__ float g_z1[Mm*Hh];
__device__ float g_z2[Mm*Hh];
__device__ float g_z3[Mm*Hh];
__device__ __half g_h16[Mm*Hh];
__device__ __half g_z016[Mm*Hh];
__device__ __half g_z216[Mm*Hh];
__device__ float g_gx[(size_t)Mm * Tt * 192];     // precomputed input-side gates
__device__ int   g_src[Ee], g_tgt[Ee];
__device__ int   g_rowptr_f[Nn+1], g_rowptr_b[Nn+1];
__device__ int   g_cnt_f[Nn], g_cnt_b[Nn], g_cur_f[Nn], g_cur_b[Nn];
__device__ float g_deg_f[Nn], g_deg_b[Nn];
__device__ int   g_adjn_f[Ee]; __device__ float g_adjw_f[Ee];
__device__ int   g_adjn_b[Ee]; __device__ float g_adjw_b[Ee];
__device__ float g_W2[KCAT*CDEC];
__device__ float g_b2[CDEC];
__device__ int   g_flag64;
__device__ float g_bhh_stage[192];

// weight images: [prec][192 n][72 k] halves, per matrix. prec0=hi, prec1=lo.
#define WIMG_H 13824          // halves per precision
__device__ __half g_BihImg[2*WIMG_H];
__device__ __half g_BhhImg[2*WIMG_H];

// ---------------- helpers (base-PTX only) ----------------
__device__ __forceinline__ uint32_t smem_u32(const void* p) {
    uint32_t a;
    asm("{ .reg .u64 t; cvta.to.shared.u64 t, %1; cvt.u32.u64 %0, t; }" : "=r"(a) : "l"(p));
    return a;
}
__device__ __forceinline__ void ldmat4(uint32_t* f, uint32_t addr) {
    asm volatile("ldmatrix.sync.aligned.m8n8.x4.shared.b16 {%0,%1,%2,%3}, [%4];"
        : "=r"(f[0]), "=r"(f[1]), "=r"(f[2]), "=r"(f[3]) : "r"(addr));
}
__device__ __forceinline__ void mma16816(float* c, const uint32_t* a, uint32_t b0, uint32_t b1) {
    asm volatile("mma.sync.aligned.m16n8k16.row.col.f32.f16.f16.f32 "
        "{%0,%1,%2,%3}, {%4,%5,%6,%7}, {%8,%9}, {%0,%1,%2,%3};"
        : "+f"(c[0]), "+f"(c[1]), "+f"(c[2]), "+f"(c[3])
        : "r"(a[0]), "r"(a[1]), "r"(a[2]), "r"(a[3]), "r"(b0), "r"(b1));
}
#define CPA16(sa, gp) asm volatile("cp.async.cg.shared.global [%0], [%1], 16;" :: "r"(sa), "l"(gp))
#define CPA_WAIT()    asm volatile("cp.async.wait_all;" ::: "memory")

__device__ __forceinline__ float sigf(float x)  { return 1.f / (1.f + __expf(-x)); }
__device__ __forceinline__ float tanhff(float x){ float e = __expf(2.f*x); return 1.f - 2.f/(e + 1.f); }

// ---------------- edge dtype detection & conversion ----------------
__global__ void k_detect(const unsigned int* ei_raw) {
    bool all0 = true;
    for (int i = 0; i < 16; i++)
        if (ei_raw[2*i + 1] != 0u) all0 = false;
    g_flag64 = all0 ? 1 : 0;
}

__global__ void k_convert(const void* ei) {
    int e = blockIdx.x * blockDim.x + threadIdx.x;
    if (e >= Ee) return;
    if (g_flag64) {
        const long long* p = (const long long*)ei;
        g_src[e] = (int)p[e];
        g_tgt[e] = (int)p[Ee + e];
    } else {
        const int* p = (const int*)ei;
        g_src[e] = p[e];
        g_tgt[e] = p[Ee + e];
    }
}

__global__ void k_zero() {
    int i = blockIdx.x * blockDim.x + threadIdx.x;
    if (i < Nn) {
        g_cnt_f[i] = 0; g_cnt_b[i] = 0;
        g_cur_f[i] = 0; g_cur_b[i] = 0;
        g_deg_f[i] = 0.f; g_deg_b[i] = 0.f;
    }
}

// ---------------- W2 = filt_W @ dec_W ; b2 = filt_b @ dec_W + dec_b ----------------
__global__ void k_w2(const float* __restrict__ filtW, const float* __restrict__ filtB,
                     const float* __restrict__ decW,  const float* __restrict__ decB) {
    int c = threadIdx.x;
    int k = blockIdx.x;
    if (k < KCAT) {
        float acc = 0.f;
        for (int j = 0; j < Hh; j++) acc += filtW[k*Hh + j] * decW[j*CDEC + c];
        g_W2[k*CDEC + c] = acc;
    } else {
        float acc = decB[c];
        for (int j = 0; j < Hh; j++) acc += filtB[j] * decW[j*CDEC + c];
        g_b2[c] = acc;
    }
}

// ---------------- weight hi/lo split: [prec][192][72] images ----------------
__global__ void k_prepw(const float* __restrict__ Wih, const float* __restrict__ Whh) {
    int idx = blockIdx.x * blockDim.x + threadIdx.x;
    if (idx >= 4*WIMG_H) return;
    int mat  = idx / (2*WIMG_H);          // 0 = Wih, 1 = Whh
    int rem  = idx % (2*WIMG_H);
    int prec = rem / WIMG_H;
    int p    = rem % WIMG_H;
    int n = p / 72, k = p % 72;
    const float* W = mat ? Whh : Wih;
    float val = (k < 64) ? W[n*Hh + k] : 0.f;
    __half hi = __float2half_rn(val);
    __half v  = prec ? __float2half_rn(val - __half2float(hi)) : hi;
    (mat ? g_BhhImg : g_BihImg)[rem] = v;
}

__global__ void k_bias(const float* __restrict__ bhh) {
    if (threadIdx.x < 192) g_bhh_stage[threadIdx.x] = bhh[threadIdx.x];
}

// ================= k_gx: parallel encoder + gx for ALL steps =================
// tile = 64 rows of one t; 256 threads (8 warps: 2Mw x 4Nw). N=192, K=64.
// smem: A hi [64][72]h, A lo @9216B (both reused as sE [64][68]f after mma),
//       B Wih img hi+lo @18432B (55296B), sEw @73728B (2048B), bih @75776B (768B).
#define GX_SA_LO  9216
#define GX_SB     18432
#define GX_SEW    73728
#define GX_SBIH   75776
#define GX_SMEM   76544

__global__ __launch_bounds__(256, 2)
void k_gx(const float* __restrict__ x,
          const float* __restrict__ encW, const float* __restrict__ encB,
          const float* __restrict__ nodeEmb, const float* __restrict__ bih)
{
    extern __shared__ __align__(16) char smraw[];
    __half* sA   = (__half*)smraw;
    float*  sE   = (float*)smraw;
    float*  sEw  = (float*)(smraw + GX_SEW);
    float*  sBih = (float*)(smraw + GX_SBIH);

    int tid  = threadIdx.x;
    int lane = tid & 31;
    int wid  = tid >> 5;
    int mw   = wid & 1;
    int nw   = wid >> 1;
    int T    = blockIdx.x / 1250;
    int m0   = (blockIdx.x % 1250) * 64;

    {
        const uint4* src = (const uint4*)g_BihImg;
        uint4* dst = (uint4*)(smraw + GX_SB);
        for (int i = tid; i < (2*WIMG_H*2)/16; i += 256) dst[i] = src[i];
    }
    for (int i = tid; i < 512; i += 256) sEw[i] = encW[i];
    if (tid < 192) sBih[tid] = bih[tid];
    __syncthreads();

    int r  = tid >> 2;
    int kq = (tid & 3) * 16;
    int m  = m0 + r, bq = m / Nn, nq = m - bq * Nn;

    // ---- A build: Xe hi/lo ----
    {
        float xv[8];
        const float4* xp = (const float4*)&x[(((size_t)bq*Tt + T)*Nn + nq)*Ff];
        float4 x0 = xp[0], x1 = xp[1];
        xv[0]=x0.x; xv[1]=x0.y; xv[2]=x0.z; xv[3]=x0.w;
        xv[4]=x1.x; xv[5]=x1.y; xv[6]=x1.z; xv[7]=x1.w;
        #pragma unroll
        for (int jj = 0; jj < 16; jj += 2) {
            int k = kq + jj;
            float v0 = __ldg(&encB[k])   + __ldg(&nodeEmb[nq*Hh + k]);
            float v1 = __ldg(&encB[k+1]) + __ldg(&nodeEmb[nq*Hh + k + 1]);
            #pragma unroll
            for (int f = 0; f < 8; f++) {
                v0 += xv[f] * sEw[f*64 + k];
                v1 += xv[f] * sEw[f*64 + k + 1];
            }
            __half h0 = __float2half_rn(v0), h1 = __float2half_rn(v1);
            __half l0 = __float2half_rn(v0 - __half2float(h0));
            __half l1 = __float2half_rn(v1 - __half2float(h1));
            *(__half2*)(sA + r*72 + k) = __halves2half2(h0, h1);
            *(__half2*)((__half*)(smraw + GX_SA_LO) + r*72 + k) = __halves2half2(l0, l1);
        }
    }
    __syncthreads();

    // ---- 3-pass mma: N=192, K=64 ----
    float acc[2][6][4];
    #pragma unroll
    for (int i = 0; i < 2; i++)
        #pragma unroll
        for (int j = 0; j < 6; j++)
            #pragma unroll
            for (int q = 0; q < 4; q++) acc[i][j][q] = 0.f;

    uint32_t sb = smem_u32(smraw);
    int arow  = lane & 15;
    int acol8 = (lane >> 4) * 8;
    int bn    = lane >> 2;
    int bc2   = 2 * (lane & 3);

    #pragma unroll
    for (int p = 0; p < 3; p++) {
        uint32_t aB = sb + ((p == 1) ? GX_SA_LO : 0);
        uint32_t bB = sb + GX_SB + ((p == 2) ? WIMG_H*2 : 0);
        #pragma unroll
        for (int ks = 0; ks < 4; ks++) {
            uint32_t afr[2][4];
            #pragma unroll
            for (int mt = 0; mt < 2; mt++)
                ldmat4(afr[mt], aB + ((mw*32 + mt*16 + arow)*72 + ks*16 + acol8) * 2);
            #pragma unroll
            for (int nt = 0; nt < 6; nt++) {
                int n = nw*48 + nt*8 + bn;
                uint32_t bo = (bB - sb) + (n*72 + ks*16 + bc2) * 2;
                uint32_t b0 = *(const uint32_t*)(smraw + bo);
                uint32_t b1 = *(const uint32_t*)(smraw + bo + 16);
                mma16816(acc[0][nt], afr[0], b0, b1);
                mma16816(acc[1][nt], afr[1], b0, b1);
            }
        }
    }
    __syncthreads();

    // ---- 3 output stages of 64 cols through sE (stride 68) ----
    int g  = lane >> 2;
    int c2 = 2 * (lane & 3);
    size_t gbase = ((size_t)T * Mm + m0 + r) * 192;
    #pragma unroll
    for (int s = 0; s < 3; s++) {
        #pragma unroll
        for (int mt = 0; mt < 2; mt++)
            #pragma unroll
            for (int q2 = 0; q2 < 2; q2++) {
                int row = mw*32 + mt*16 + g + q2*8;
                #pragma unroll
                for (int nt = 0; nt < 6; nt++) {
                    int col = nw*48 + nt*8 + c2;
                    if (col >= 64*s && col < 64*s + 64)
                        *(float2*)&sE[row*68 + col - 64*s] =
                            make_float2(acc[mt][nt][q2*2], acc[mt][nt][q2*2 + 1]);
                }
            }
        __syncthreads();
        float4* go = (float4*)&g_gx[gbase + 64*s + kq];
        #pragma unroll
        for (int q = 0; q < 4; q++) {
            int c = kq + q*4;
            go[q] = make_float4(sE[r*68 + c]   + sBih[64*s + c],
                                sE[r*68 + c+1] + sBih[64*s + c + 1],
                                sE[r*68 + c+2] + sBih[64*s + c + 2],
                                sE[r*68 + c+3] + sBih[64*s + c + 3]);
        }
        __syncthreads();
    }
}

// ================= serial GRU: gh = h@Whh only, gx prefetched =================
// 128 rows/block, 512 threads (16 warps: 4Mw x 4Nw). N=192, K=64.
// smem bytes:
//   0       A hi/lo [128][72]h (36864) — overlaid by sE ghn [128][68]f (34816)
//   36864   B Whh image hi+lo (55296)
//   92160   sH [128][68]f (34816)
//   126976  gx buf [128][196]f (100352)
//   227328  bhh (768)   total 228096
#define SER_SA_LO  18432
#define SER_SB     36864
#define SER_SH     92160
#define SER_SGX    126976
#define SER_SBIAS  227328
#define SER_SMEM   228096

__global__ __launch_bounds__(512, 1)
void k_gru_ser()
{
    extern __shared__ __align__(16) char smraw[];
    __half* sA   = (__half*)smraw;
    float*  sE   = (float*)smraw;
    float*  sH   = (float*)(smraw + SER_SH);
    float*  sGx  = (float*)(smraw + SER_SGX);
    float*  sBhh = (float*)(smraw + SER_SBIAS);

    int tid  = threadIdx.x;
    int lane = tid & 31;
    int wid  = tid >> 5;
    int mw   = wid & 3;
    int nw   = wid >> 2;
    int m0   = blockIdx.x * 128;

    {
        const uint4* src = (const uint4*)g_BhhImg;
        uint4* dst = (uint4*)(smraw + SER_SB);
        for (int i = tid; i < (2*WIMG_H*2)/16; i += 512) dst[i] = src[i];
    }
    if (tid < 192) sBhh[tid] = g_bhh_stage[tid];
    {
        float4* z4 = (float4*)sH;
        for (int i = tid; i < (128*68)/4; i += 512) z4[i] = make_float4(0.f,0.f,0.f,0.f);
        float4* a4 = (float4*)smraw;
        for (int i = tid; i < 36864/16; i += 512) a4[i] = make_float4(0.f,0.f,0.f,0.f);
    }
    __syncthreads();

    int r  = tid >> 2;
    int kq = (tid & 3) * 16;
    int m  = m0 + r;

    uint32_t sb = smem_u32(smraw);
    uint32_t sgx_b = sb + SER_SGX;
    int arow  = lane & 15;
    int acol8 = (lane >> 4) * 8;
    int bn    = lane >> 2;
    int bc2   = 2 * (lane & 3);
    int g     = lane >> 2;
    int c2    = 2 * (lane & 3);

    for (int t = 0; t < Tt; t++) {
        // prefetch this step's gx (each thread copies exactly what it consumes at gates)
        {
            const float* gsrc = &g_gx[((size_t)t * Mm + m) * 192];
            #pragma unroll
            for (int gr = 0; gr < 3; gr++)
                #pragma unroll
                for (int q = 0; q < 4; q++) {
                    int col = gr*64 + kq + q*4;
                    CPA16(sgx_b + (r*196 + col)*4, gsrc + col);
                }
        }

        // A build from sH (skip at t=0: h = 0)
        if (t > 0) {
            #pragma unroll
            for (int jj = 0; jj < 16; jj += 2) {
                float v0 = sH[r*68 + kq + jj], v1 = sH[r*68 + kq + jj + 1];
                __half h0 = __float2half_rn(v0), h1 = __float2half_rn(v1);
                __half l0 = __float2half_rn(v0 - __half2float(h0));
                __half l1 = __float2half_rn(v1 - __half2float(h1));
                *(__half2*)(sA + r*72 + kq + jj) = __halves2half2(h0, h1);
                *(__half2*)((__half*)(smraw + SER_SA_LO) + r*72 + kq + jj) = __halves2half2(l0, l1);
            }
        }
        __syncthreads();

        float acc[2][6][4];
        if (t > 0) {
            #pragma unroll
            for (int i = 0; i < 2; i++)
                #pragma unroll
                for (int j = 0; j < 6; j++)
                    #pragma unroll
                    for (int q = 0; q < 4; q++) acc[i][j][q] = 0.f;

            #pragma unroll
            for (int p = 0; p < 3; p++) {
                uint32_t aB = sb + ((p == 1) ? SER_SA_LO : 0);
                uint32_t bB = sb + SER_SB + ((p == 2) ? WIMG_H*2 : 0);
                #pragma unroll
                for (int ks = 0; ks < 4; ks++) {
                    uint32_t afr[2][4];
                    #pragma unroll
                    for (int mt = 0; mt < 2; mt++)
                        ldmat4(afr[mt], aB + ((mw*32 + mt*16 + arow)*72 + ks*16 + acol8) * 2);
                    #pragma unroll
                    for (int nt = 0; nt < 6; nt++) {
                        int n = nw*48 + nt*8 + bn;
                        uint32_t bo = (bB - sb) + (n*72 + ks*16 + bc2) * 2;
                        uint32_t b0 = *(const uint32_t*)(smraw + bo);
                        uint32_t b1 = *(const uint32_t*)(smraw + bo + 16);
                        mma16816(acc[0][nt], afr[0], b0, b1);
                        mma16816(acc[1][nt], afr[1], b0, b1);
                    }
                }
            }
        }
        CPA_WAIT();
        __syncthreads();

        // epilogue: RMW gh_r,gh_z into gx buf; ghn -> sE (A region, now dead)
        if (t > 0) {
            #pragma unroll
            for (int mt = 0; mt < 2; mt++)
                #pragma unroll
                for (int q2 = 0; q2 < 2; q2++) {
                    int row = mw*32 + mt*16 + g + q2*8;
                    #pragma unroll
                    for (int nt = 0; nt < 6; nt++) {
                        int col = nw*48 + nt*8 + c2;
                        float vx = acc[mt][nt][q2*2], vy = acc[mt][nt][q2*2+1];
                        if (col < 128) {
                            float2* gp = (float2*)&sGx[row*196 + col];
                            float2 old = *gp;
                            old.x += vx; old.y += vy;
                            *gp = old;
                        } else {
                            *(float2*)&sE[row*68 + col - 128] = make_float2(vx, vy);
                        }
                    }
                }
        }
        __syncthreads();

        // gates: thread owns sH[r][kq..kq+15] exclusively
        {
            #pragma unroll
            for (int jj = 0; jj < 16; jj++) {
                int j = kq + jj;
                float rv = sGx[r*196 + j]       + sBhh[j];
                float zv = sGx[r*196 + 64 + j]  + sBhh[64 + j];
                float xn = sGx[r*196 + 128 + j];
                float hn = (t > 0) ? (sE[r*68 + j] + sBhh[128 + j]) : sBhh[128 + j];
                float rg = sigf(rv);
                float zg = sigf(zv);
                float ng = tanhff(xn + rg * hn);
                sH[r*68 + j] = (1.f - zg) * ng + zg * sH[r*68 + j];
            }
        }
        __syncthreads();
    }

    // write final hidden state (fp32 + fp16)
    {
        float4* dst = (float4*)(g_h0 + (size_t)m*Hh + kq);
        __half2* d16 = (__half2*)(g_h16 + (size_t)m*Hh + kq);
        #pragma unroll
        for (int q = 0; q < 4; q++) {
            float4 v = *(float4*)&sH[r*68 + kq + q*4];
            dst[q] = v;
            d16[q*2]   = __halves2half2(__float2half_rn(v.x), __float2half_rn(v.y));
            d16[q*2+1] = __halves2half2(__float2half_rn(v.z), __float2half_rn(v.w));
        }
    }
}

// ---------------- CSR build ----------------
__global__ void k_count(const float* __restrict__ ew) {
    int e = blockIdx.x * blockDim.x + threadIdx.x;
    if (e >= Ee) return;
    int s = g_src[e], t = g_tgt[e];
    float w = ew[e];
    atomicAdd(&g_cnt_f[t], 1);  atomicAdd(&g_deg_f[t], w);
    atomicAdd(&g_cnt_b[s], 1);  atomicAdd(&g_deg_b[s], w);
}

__global__ void k_scan() {
    __shared__ int sbuf[1024];
    __shared__ int sOff;
    int tid = threadIdx.x;
    for (int which = 0; which < 2; ++which) {
        const int* cnt = which ? g_cnt_b : g_cnt_f;
        int* rp        = which ? g_rowptr_b : g_rowptr_f;
        if (tid == 0) { sOff = 0; rp[0] = 0; }
        __syncthreads();
        for (int base = 0; base < Nn; base += 1024) {
            int i = base + tid;
            int v = (i < Nn) ? cnt[i] : 0;
            sbuf[tid] = v;
            __syncthreads();
            for (int d = 1; d < 1024; d <<= 1) {
                int add = (tid >= d) ? sbuf[tid - d] : 0;
                __syncthreads();
                sbuf[tid] += add;
                __syncthreads();
            }
            if (i < Nn) rp[i + 1] = sOff + sbuf[tid];
            __syncthreads();
            if (tid == 0) sOff += sbuf[1023];
            __syncthreads();
        }
        __syncthreads();
    }
}

__global__ void k_fill(const float* __restrict__ ew) {
    int e = blockIdx.x * blockDim.x + threadIdx.x;
    if (e >= Ee) return;
    int s = g_src[e], t = g_tgt[e];
    float w = ew[e];
    float df = g_deg_f[t]; df = (df == 0.f) ? 1.f : df;
    int pf = g_rowptr_f[t] + atomicAdd(&g_cur_f[t], 1);
    g_adjn_f[pf] = s;  g_adjw_f[pf] = w / df;
    float db = g_deg_b[s]; db = (db == 0.f) ? 1.f : db;
    int pb = g_rowptr_b[s] + atomicAdd(&g_cur_b[s], 1);
    g_adjn_b[pb] = t;  g_adjw_b[pb] = w / db;
}

// ---------------- diffusion propagation (fp16 gather, fp32 accumulate) ----------------
__device__ __forceinline__ void prop16(const __half* __restrict__ hin,
                                       float* __restrict__ outF,
                                       __half* __restrict__ outH,   // may be null
                                       const int* __restrict__ rowptr,
                                       const int* __restrict__ adjn,
                                       const float* __restrict__ adjw,
                                       int node, int lane) {
    int beg = rowptr[node], end = rowptr[node + 1];
    float acc[Bb][2];
    #pragma unroll
    for (int b = 0; b < Bb; b++) { acc[b][0] = 0.f; acc[b][1] = 0.f; }
    for (int e = beg; e < end; e++) {
        int s = adjn[e];
        float w = adjw[e];
        #pragma unroll
        for (int b = 0; b < Bb; b++) {
            __half2 hv = ((const __half2*)(hin + ((size_t)b * Nn + s) * Hh))[lane];
            float2 f = __half22float2(hv);
            acc[b][0] += f.x * w;
            acc[b][1] += f.y * w;
        }
    }
    #pragma unroll
    for (int b = 0; b < Bb; b++) {
        size_t o = ((size_t)b * Nn + node) * Hh + 2*lane;
        *(float2*)&outF[o] = make_float2(acc[b][0], acc[b][1]);
        if (outH)
            *(__half2*)&outH[o] = __halves2half2(__float2half_rn(acc[b][0]),
                                                 __float2half_rn(acc[b][1]));
    }
}

__global__ void k_prop_h1() {
    int gw   = (blockIdx.x * blockDim.x + threadIdx.x) >> 5;
    int lane = threadIdx.x & 31;
    if (gw >= 2*Nn) return;
    if (gw < Nn) prop16(g_h16, g_z0, g_z016, g_rowptr_f, g_adjn_f, g_adjw_f, gw, lane);
    else         prop16(g_h16, g_z2, g_z216, g_rowptr_b, g_adjn_b, g_adjw_b, gw - Nn, lane);
}

__global__ void k_prop_h2() {
    int gw   = (blockIdx.x * blockDim.x + threadIdx.x) >> 5;
    int lane = threadIdx.x & 31;
    if (gw >= 2*Nn) return;
    if (gw < Nn) prop16(g_z016, g_z1, (__half*)0, g_rowptr_f, g_adjn_f, g_adjw_f, gw, lane);
    else         prop16(g_z216, g_z3, (__half*)0, g_rowptr_b, g_adjn_b, g_adjw_b, gw - Nn, lane);
}

// ---------------- fused filt+dec GEMM + output permute ----------------
#define FIN_SMEM ((KCAT*CDEC + KCAT*65) * 4)

__global__ __launch_bounds__(256, 1)
void k_final(float* __restrict__ out) {
    extern __shared__ float smf[];
    float* sW = smf;
    float* sA = smf + KCAT*CDEC;

    int tid = threadIdx.x;
    int m0  = blockIdx.x * 64;

    for (int idx = tid; idx < KCAT*CDEC; idx += 256) sW[idx] = g_W2[idx];

    const float* srcs[5] = { g_h0, g_z0, g_z1, g_z2, g_z3 };
    #pragma unroll
    for (int a = 0; a < 5; a++) {
        const float* S = srcs[a];
        for (int idx = tid; idx < 64*64; idx += 256) {
            int r = idx >> 6, k = idx & 63;
            sA[(a*64 + k)*65 + r] = S[(size_t)(m0 + r) * Hh + k];
        }
    }
    __syncthreads();

    int gc = tid & 31, rt = tid >> 5;
    float acc[8][3];
    #pragma unroll
    for (int i = 0; i < 8; i++)
        #pragma unroll
        for (int j = 0; j < 3; j++) acc[i][j] = 0.f;

    #pragma unroll 2
    for (int k = 0; k < KCAT; k++) {
        float av[8];
        #pragma unroll
        for (int i = 0; i < 8; i++) av[i] = sA[k*65 + rt*8 + i];
        float wv[3];
        #pragma unroll
        for (int j = 0; j < 3; j++) wv[j] = sW[k*CDEC + gc + 32*j];
        #pragma unroll
        for (int i = 0; i < 8; i++)
            #pragma unroll
            for (int j = 0; j < 3; j++) acc[i][j] += av[i] * wv[j];
    }

    #pragma unroll
    for (int i = 0; i < 8; i++) {
        int m = m0 + rt*8 + i;
        int b = m / Nn, n = m - b * Nn;
        #pragma unroll
        for (int j = 0; j < 3; j++) {
            int c = gc + 32*j;
            int tt = c >> 3, f = c & 7;
            out[(((size_t)b * HOR + tt) * Nn + n) * Ff + f] = acc[i][j] + g_b2[c];
        }
    }
}

// ---------------- launch ----------------
extern "C" void kernel_launch(void* const* d_in, const int* in_sizes, int n_in,
                              void* d_out, int out_size) {
    const float* x     = (const float*)d_in[0];
    const void*  ei    = d_in[1];
    const float* ew    = (const float*)d_in[2];
    const float* encW  = (const float*)d_in[3];
    const float* encB  = (const float*)d_in[4];
    const float* nemb  = (const float*)d_in[5];
    const float* Wih   = (const float*)d_in[6];
    const float* Whh   = (const float*)d_in[7];
    const float* bih   = (const float*)d_in[8];
    const float* bhh   = (const float*)d_in[9];
    const float* filtW = (const float*)d_in[10];
    const float* filtB = (const float*)d_in[11];
    const float* decW  = (const float*)d_in[12];
    const float* decB  = (const float*)d_in[13];
    float* out = (float*)d_out;

    cudaFuncSetAttribute(k_gx,      cudaFuncAttributeMaxDynamicSharedMemorySize, GX_SMEM);
    cudaFuncSetAttribute(k_gru_ser, cudaFuncAttributeMaxDynamicSharedMemorySize, SER_SMEM);
    cudaFuncSetAttribute(k_final,   cudaFuncAttributeMaxDynamicSharedMemorySize, FIN_SMEM);

    k_detect<<<1, 1>>>((const unsigned int*)ei);
    k_convert<<<(Ee + 255) / 256, 256>>>(ei);
    k_zero<<<(Nn + 255) / 256, 256>>>();
    k_w2<<<KCAT + 1, CDEC>>>(filtW, filtB, decW, decB);
    k_prepw<<<(4*WIMG_H + 255) / 256, 256>>>(Wih, Whh);
    k_bias<<<1, 192>>>(bhh);

    k_gx<<<Tt * 1250, 256, GX_SMEM>>>(x, encW, encB, nemb, bih);
    k_gru_ser<<<Mm / 128, 512, SER_SMEM>>>();

    k_count<<<(Ee + 255) / 256, 256>>>(ew);
    k_scan<<<1, 1024>>>();
    k_fill<<<(Ee + 255) / 256, 256>>>(ew);
    k_prop_h1<<<(2*Nn*32 + 255) / 256, 256>>>();
    k_prop_h2<<<(2*Nn*32 + 255) / 256, 256>>>();

    k_final<<<Mm / 64, 256, FIN_SMEM>>>(out);
}

// round 7
// speedup vs baseline: 1.0005x; 1.0005x over previous
#include <cuda_runtime.h>
#include <cuda_fp16.h>
#include <math.h>
#include <stdint.h>

// ---------------- problem constants ----------------
#define Nn   10000
#define Bb   8
#define Tt   12
#define Ff   8
#define Hh   64
#define Ee   320000
#define HOR  12
#define Mm   (Bb*Nn)          // 80000 rows
#define KCAT 320              // 5*H
#define CDEC 96               // F*HOR

// ---------------- scratch (__device__ globals; no cudaMalloc) ----------------
__device__ float g_h0[Mm*Hh];
__device__ float g_z0[Mm*Hh];
__device__ float g_z1[Mm*Hh];
__device__ float g_z2[Mm*Hh];
__device__ float g_z3[Mm*Hh];
__device__ __half g_h16[Mm*Hh];
__device__ __half g_z016[Mm*Hh];
__device__ __half g_z216[Mm*Hh];
__device__ float g_gx[(size_t)Mm * Tt * 192];     // precomputed input-side gates
__device__ int   g_src[Ee], g_tgt[Ee];
__device__ int   g_rowptr_f[Nn+1], g_rowptr_b[Nn+1];
__device__ int   g_cnt_f[Nn], g_cnt_b[Nn], g_cur_f[Nn], g_cur_b[Nn];
__device__ float g_deg_f[Nn], g_deg_b[Nn];
__device__ int   g_adjn_f[Ee]; __device__ float g_adjw_f[Ee];
__device__ int   g_adjn_b[Ee]; __device__ float g_adjw_b[Ee];
__device__ float g_W2[KCAT*CDEC];
__device__ float g_b2[CDEC];
__device__ int   g_flag64;
__device__ float g_bhh_stage[192];

// weight images: [prec][192 n][72 k] halves, per matrix. prec0=hi, prec1=lo.
#define WIMG_H 13824          // halves per precision
__device__ __half g_BihImg[2*WIMG_H];
__device__ __half g_BhhImg[2*WIMG_H];

// ---------------- helpers (base-PTX only) ----------------
__device__ __forceinline__ uint32_t smem_u32(const void* p) {
    uint32_t a;
    asm("{ .reg .u64 t; cvta.to.shared.u64 t, %1; cvt.u32.u64 %0, t; }" : "=r"(a) : "l"(p));
    return a;
}
__device__ __forceinline__ void ldmat4(uint32_t* f, uint32_t addr) {
    asm volatile("ldmatrix.sync.aligned.m8n8.x4.shared.b16 {%0,%1,%2,%3}, [%4];"
        : "=r"(f[0]), "=r"(f[1]), "=r"(f[2]), "=r"(f[3]) : "r"(addr));
}
__device__ __forceinline__ void mma16816(float* c, const uint32_t* a, uint32_t b0, uint32_t b1) {
    asm volatile("mma.sync.aligned.m16n8k16.row.col.f32.f16.f16.f32 "
        "{%0,%1,%2,%3}, {%4,%5,%6,%7}, {%8,%9}, {%0,%1,%2,%3};"
        : "+f"(c[0]), "+f"(c[1]), "+f"(c[2]), "+f"(c[3])
        : "r"(a[0]), "r"(a[1]), "r"(a[2]), "r"(a[3]), "r"(b0), "r"(b1));
}
#define CPA16(sa, gp) asm volatile("cp.async.cg.shared.global [%0], [%1], 16;" :: "r"(sa), "l"(gp))
#define CPA_WAIT()    asm volatile("cp.async.wait_all;" ::: "memory")

__device__ __forceinline__ float sigf(float x)  { return 1.f / (1.f + __expf(-x)); }
__device__ __forceinline__ float tanhff(float x){ float e = __expf(2.f*x); return 1.f - 2.f/(e + 1.f); }

// ---------------- edge dtype detection & conversion ----------------
__global__ void k_detect(const unsigned int* ei_raw) {
    bool all0 = true;
    for (int i = 0; i < 16; i++)
        if (ei_raw[2*i + 1] != 0u) all0 = false;
    g_flag64 = all0 ? 1 : 0;
}

__global__ void k_convert(const void* ei) {
    int e = blockIdx.x * blockDim.x + threadIdx.x;
    if (e >= Ee) return;
    if (g_flag64) {
        const long long* p = (const long long*)ei;
        g_src[e] = (int)p[e];
        g_tgt[e] = (int)p[Ee + e];
    } else {
        const int* p = (const int*)ei;
        g_src[e] = p[e];
        g_tgt[e] = p[Ee + e];
    }
}

__global__ void k_zero() {
    int i = blockIdx.x * blockDim.x + threadIdx.x;
    if (i < Nn) {
        g_cnt_f[i] = 0; g_cnt_b[i] = 0;
        g_cur_f[i] = 0; g_cur_b[i] = 0;
        g_deg_f[i] = 0.f; g_deg_b[i] = 0.f;
    }
}

// ---------------- W2 = filt_W @ dec_W ; b2 = filt_b @ dec_W + dec_b ----------------
__global__ void k_w2(const float* __restrict__ filtW, const float* __restrict__ filtB,
                     const float* __restrict__ decW,  const float* __restrict__ decB) {
    int c = threadIdx.x;
    int k = blockIdx.x;
    if (k < KCAT) {
        float acc = 0.f;
        for (int j = 0; j < Hh; j++) acc += filtW[k*Hh + j] * decW[j*CDEC + c];
        g_W2[k*CDEC + c] = acc;
    } else {
        float acc = decB[c];
        for (int j = 0; j < Hh; j++) acc += filtB[j] * decW[j*CDEC + c];
        g_b2[c] = acc;
    }
}

// ---------------- weight hi/lo split: [prec][192][72] images ----------------
__global__ void k_prepw(const float* __restrict__ Wih, const float* __restrict__ Whh) {
    int idx = blockIdx.x * blockDim.x + threadIdx.x;
    if (idx >= 4*WIMG_H) return;
    int mat  = idx / (2*WIMG_H);          // 0 = Wih, 1 = Whh
    int rem  = idx % (2*WIMG_H);
    int prec = rem / WIMG_H;
    int p    = rem % WIMG_H;
    int n = p / 72, k = p % 72;
    const float* W = mat ? Whh : Wih;
    float val = (k < 64) ? W[n*Hh + k] : 0.f;
    __half hi = __float2half_rn(val);
    __half v  = prec ? __float2half_rn(val - __half2float(hi)) : hi;
    (mat ? g_BhhImg : g_BihImg)[rem] = v;
}

__global__ void k_bias(const float* __restrict__ bhh) {
    if (threadIdx.x < 192) g_bhh_stage[threadIdx.x] = bhh[threadIdx.x];
}

// ================= k_gx: parallel encoder + gx for ALL steps =================
// tile = 64 rows of one t; 256 threads (8 warps: 2Mw x 4Nw). N=192, K=64.
// smem: A hi [64][72]h, A lo @9216B (both reused as sE [64][68]f after mma),
//       B Wih img hi+lo @18432B (55296B), sEw @73728B (2048B), bih @75776B (768B).
#define GX_SA_LO  9216
#define GX_SB     18432
#define GX_SEW    73728
#define GX_SBIH   75776
#define GX_SMEM   76544

__global__ __launch_bounds__(256, 2)
void k_gx(const float* __restrict__ x,
          const float* __restrict__ encW, const float* __restrict__ encB,
          const float* __restrict__ nodeEmb, const float* __restrict__ bih)
{
    extern __shared__ __align__(16) char smraw[];
    __half* sA   = (__half*)smraw;
    float*  sE   = (float*)smraw;
    float*  sEw  = (float*)(smraw + GX_SEW);
    float*  sBih = (float*)(smraw + GX_SBIH);

    int tid  = threadIdx.x;
    int lane = tid & 31;
    int wid  = tid >> 5;
    int mw   = wid & 1;
    int nw   = wid >> 1;
    int T    = blockIdx.x / 1250;
    int m0   = (blockIdx.x % 1250) * 64;

    {
        const uint4* src = (const uint4*)g_BihImg;
        uint4* dst = (uint4*)(smraw + GX_SB);
        for (int i = tid; i < (2*WIMG_H*2)/16; i += 256) dst[i] = src[i];
    }
    for (int i = tid; i < 512; i += 256) sEw[i] = encW[i];
    if (tid < 192) sBih[tid] = bih[tid];
    __syncthreads();

    int r  = tid >> 2;
    int kq = (tid & 3) * 16;
    int m  = m0 + r, bq = m / Nn, nq = m - bq * Nn;

    // ---- A build: Xe hi/lo ----
    {
        float xv[8];
        const float4* xp = (const float4*)&x[(((size_t)bq*Tt + T)*Nn + nq)*Ff];
        float4 x0 = xp[0], x1 = xp[1];
        xv[0]=x0.x; xv[1]=x0.y; xv[2]=x0.z; xv[3]=x0.w;
        xv[4]=x1.x; xv[5]=x1.y; xv[6]=x1.z; xv[7]=x1.w;
        #pragma unroll
        for (int jj = 0; jj < 16; jj += 2) {
            int k = kq + jj;
            float v0 = __ldg(&encB[k])   + __ldg(&nodeEmb[nq*Hh + k]);
            float v1 = __ldg(&encB[k+1]) + __ldg(&nodeEmb[nq*Hh + k + 1]);
            #pragma unroll
            for (int f = 0; f < 8; f++) {
                v0 += xv[f] * sEw[f*64 + k];
                v1 += xv[f] * sEw[f*64 + k + 1];
            }
            __half h0 = __float2half_rn(v0), h1 = __float2half_rn(v1);
            __half l0 = __float2half_rn(v0 - __half2float(h0));
            __half l1 = __float2half_rn(v1 - __half2float(h1));
            *(__half2*)(sA + r*72 + k) = __halves2half2(h0, h1);
            *(__half2*)((__half*)(smraw + GX_SA_LO) + r*72 + k) = __halves2half2(l0, l1);
        }
    }
    __syncthreads();

    // ---- 3-pass mma: N=192, K=64 ----
    float acc[2][6][4];
    #pragma unroll
    for (int i = 0; i < 2; i++)
        #pragma unroll
        for (int j = 0; j < 6; j++)
            #pragma unroll
            for (int q = 0; q < 4; q++) acc[i][j][q] = 0.f;

    uint32_t sb = smem_u32(smraw);
    int arow  = lane & 15;
    int acol8 = (lane >> 4) * 8;
    int bn    = lane >> 2;
    int bc2   = 2 * (lane & 3);

    #pragma unroll
    for (int p = 0; p < 3; p++) {
        uint32_t aB = sb + ((p == 1) ? GX_SA_LO : 0);
        uint32_t bB = sb + GX_SB + ((p == 2) ? WIMG_H*2 : 0);
        #pragma unroll
        for (int ks = 0; ks < 4; ks++) {
            uint32_t afr[2][4];
            #pragma unroll
            for (int mt = 0; mt < 2; mt++)
                ldmat4(afr[mt], aB + ((mw*32 + mt*16 + arow)*72 + ks*16 + acol8) * 2);
            #pragma unroll
            for (int nt = 0; nt < 6; nt++) {
                int n = nw*48 + nt*8 + bn;
                uint32_t bo = (bB - sb) + (n*72 + ks*16 + bc2) * 2;
                uint32_t b0 = *(const uint32_t*)(smraw + bo);
                uint32_t b1 = *(const uint32_t*)(smraw + bo + 16);
                mma16816(acc[0][nt], afr[0], b0, b1);
                mma16816(acc[1][nt], afr[1], b0, b1);
            }
        }
    }
    __syncthreads();

    // ---- 3 output stages of 64 cols through sE (stride 68) ----
    int g  = lane >> 2;
    int c2 = 2 * (lane & 3);
    size_t gbase = ((size_t)T * Mm + m0 + r) * 192;
    #pragma unroll
    for (int s = 0; s < 3; s++) {
        #pragma unroll
        for (int mt = 0; mt < 2; mt++)
            #pragma unroll
            for (int q2 = 0; q2 < 2; q2++) {
                int row = mw*32 + mt*16 + g + q2*8;
                #pragma unroll
                for (int nt = 0; nt < 6; nt++) {
                    int col = nw*48 + nt*8 + c2;
                    if (col >= 64*s && col < 64*s + 64)
                        *(float2*)&sE[row*68 + col - 64*s] =
                            make_float2(acc[mt][nt][q2*2], acc[mt][nt][q2*2 + 1]);
                }
            }
        __syncthreads();
        float4* go = (float4*)&g_gx[gbase + 64*s + kq];
        #pragma unroll
        for (int q = 0; q < 4; q++) {
            int c = kq + q*4;
            go[q] = make_float4(sE[r*68 + c]   + sBih[64*s + c],
                                sE[r*68 + c+1] + sBih[64*s + c + 1],
                                sE[r*68 + c+2] + sBih[64*s + c + 2],
                                sE[r*68 + c+3] + sBih[64*s + c + 3]);
        }
        __syncthreads();
    }
}

// ================= serial GRU: gh = h@Whh only, gx prefetched =================
// 128 rows/block, 512 threads (16 warps: 4Mw x 4Nw). N=192, K=64.
// smem bytes:
//   0       A hi/lo [128][72]h (36864) — overlaid by sE ghn [128][68]f (34816)
//   36864   B Whh image hi+lo (55296)
//   92160   sH [128][68]f (34816)
//   126976  gx buf [128][196]f (100352)
//   227328  bhh (768)   total 228096
#define SER_SA_LO  18432
#define SER_SB     36864
#define SER_SH     92160
#define SER_SGX    126976
#define SER_SBIAS  227328
#define SER_SMEM   228096

__global__ __launch_bounds__(512, 1)
void k_gru_ser()
{
    extern __shared__ __align__(16) char smraw[];
    __half* sA   = (__half*)smraw;
    float*  sE   = (float*)smraw;
    float*  sH   = (float*)(smraw + SER_SH);
    float*  sGx  = (float*)(smraw + SER_SGX);
    float*  sBhh = (float*)(smraw + SER_SBIAS);

    int tid  = threadIdx.x;
    int lane = tid & 31;
    int wid  = tid >> 5;
    int mw   = wid & 3;
    int nw   = wid >> 2;
    int m0   = blockIdx.x * 128;

    {
        const uint4* src = (const uint4*)g_BhhImg;
        uint4* dst = (uint4*)(smraw + SER_SB);
        for (int i = tid; i < (2*WIMG_H*2)/16; i += 512) dst[i] = src[i];
    }
    if (tid < 192) sBhh[tid] = g_bhh_stage[tid];
    {
        float4* z4 = (float4*)sH;
        for (int i = tid; i < (128*68)/4; i += 512) z4[i] = make_float4(0.f,0.f,0.f,0.f);
        float4* a4 = (float4*)smraw;
        for (int i = tid; i < 36864/16; i += 512) a4[i] = make_float4(0.f,0.f,0.f,0.f);
    }
    __syncthreads();

    int r  = tid >> 2;
    int kq = (tid & 3) * 16;
    int m  = m0 + r;

    uint32_t sb = smem_u32(smraw);
    uint32_t sgx_b = sb + SER_SGX;
    int arow  = lane & 15;
    int acol8 = (lane >> 4) * 8;
    int bn    = lane >> 2;
    int bc2   = 2 * (lane & 3);
    int g     = lane >> 2;
    int c2    = 2 * (lane & 3);

    for (int t = 0; t < Tt; t++) {
        // prefetch this step's gx (each thread copies exactly what it consumes at gates)
        {
            const float* gsrc = &g_gx[((size_t)t * Mm + m) * 192];
            #pragma unroll
            for (int gr = 0; gr < 3; gr++)
                #pragma unroll
                for (int q = 0; q < 4; q++) {
                    int col = gr*64 + kq + q*4;
                    CPA16(sgx_b + (r*196 + col)*4, gsrc + col);
                }
        }

        // A build from sH (skip at t=0: h = 0)
        if (t > 0) {
            #pragma unroll
            for (int jj = 0; jj < 16; jj += 2) {
                float v0 = sH[r*68 + kq + jj], v1 = sH[r*68 + kq + jj + 1];
                __half h0 = __float2half_rn(v0), h1 = __float2half_rn(v1);
                __half l0 = __float2half_rn(v0 - __half2float(h0));
                __half l1 = __float2half_rn(v1 - __half2float(h1));
                *(__half2*)(sA + r*72 + kq + jj) = __halves2half2(h0, h1);
                *(__half2*)((__half*)(smraw + SER_SA_LO) + r*72 + kq + jj) = __halves2half2(l0, l1);
            }
        }
        __syncthreads();

        float acc[2][6][4];
        if (t > 0) {
            #pragma unroll
            for (int i = 0; i < 2; i++)
                #pragma unroll
                for (int j = 0; j < 6; j++)
                    #pragma unroll
                    for (int q = 0; q < 4; q++) acc[i][j][q] = 0.f;

            #pragma unroll
            for (int p = 0; p < 3; p++) {
                uint32_t aB = sb + ((p == 1) ? SER_SA_LO : 0);
                uint32_t bB = sb + SER_SB + ((p == 2) ? WIMG_H*2 : 0);
                #pragma unroll
                for (int ks = 0; ks < 4; ks++) {
                    uint32_t afr[2][4];
                    #pragma unroll
                    for (int mt = 0; mt < 2; mt++)
                        ldmat4(afr[mt], aB + ((mw*32 + mt*16 + arow)*72 + ks*16 + acol8) * 2);
                    #pragma unroll
                    for (int nt = 0; nt < 6; nt++) {
                        int n = nw*48 + nt*8 + bn;
                        uint32_t bo = (bB - sb) + (n*72 + ks*16 + bc2) * 2;
                        uint32_t b0 = *(const uint32_t*)(smraw + bo);
                        uint32_t b1 = *(const uint32_t*)(smraw + bo + 16);
                        mma16816(acc[0][nt], afr[0], b0, b1);
                        mma16816(acc[1][nt], afr[1], b0, b1);
                    }
                }
            }
        }
        CPA_WAIT();
        __syncthreads();

        // epilogue: RMW gh_r,gh_z into gx buf; ghn -> sE (A region, now dead)
        if (t > 0) {
            #pragma unroll
            for (int mt = 0; mt < 2; mt++)
                #pragma unroll
                for (int q2 = 0; q2 < 2; q2++) {
                    int row = mw*32 + mt*16 + g + q2*8;
                    #pragma unroll
                    for (int nt = 0; nt < 6; nt++) {
                        int col = nw*48 + nt*8 + c2;
                        float vx = acc[mt][nt][q2*2], vy = acc[mt][nt][q2*2+1];
                        if (col < 128) {
                            float2* gp = (float2*)&sGx[row*196 + col];
                            float2 old = *gp;
                            old.x += vx; old.y += vy;
                            *gp = old;
                        } else {
                            *(float2*)&sE[row*68 + col - 128] = make_float2(vx, vy);
                        }
                    }
                }
        }
        __syncthreads();

        // gates: thread owns sH[r][kq..kq+15] exclusively
        {
            #pragma unroll
            for (int jj = 0; jj < 16; jj++) {
                int j = kq + jj;
                float rv = sGx[r*196 + j]       + sBhh[j];
                float zv = sGx[r*196 + 64 + j]  + sBhh[64 + j];
                float xn = sGx[r*196 + 128 + j];
                float hn = (t > 0) ? (sE[r*68 + j] + sBhh[128 + j]) : sBhh[128 + j];
                float rg = sigf(rv);
                float zg = sigf(zv);
                float ng = tanhff(xn + rg * hn);
                sH[r*68 + j] = (1.f - zg) * ng + zg * sH[r*68 + j];
            }
        }
        __syncthreads();
    }

    // write final hidden state (fp32 + fp16)
    {
        float4* dst = (float4*)(g_h0 + (size_t)m*Hh + kq);
        __half2* d16 = (__half2*)(g_h16 + (size_t)m*Hh + kq);
        #pragma unroll
        for (int q = 0; q < 4; q++) {
            float4 v = *(float4*)&sH[r*68 + kq + q*4];
            dst[q] = v;
            d16[q*2]   = __halves2half2(__float2half_rn(v.x), __float2half_rn(v.y));
            d16[q*2+1] = __halves2half2(__float2half_rn(v.z), __float2half_rn(v.w));
        }
    }
}

// ---------------- CSR build ----------------
__global__ void k_count(const float* __restrict__ ew) {
    int e = blockIdx.x * blockDim.x + threadIdx.x;
    if (e >= Ee) return;
    int s = g_src[e], t = g_tgt[e];
    float w = ew[e];
    atomicAdd(&g_cnt_f[t], 1);  atomicAdd(&g_deg_f[t], w);
    atomicAdd(&g_cnt_b[s], 1);  atomicAdd(&g_deg_b[s], w);
}

__global__ void k_scan() {
    __shared__ int sbuf[1024];
    __shared__ int sOff;
    int tid = threadIdx.x;
    for (int which = 0; which < 2; ++which) {
        const int* cnt = which ? g_cnt_b : g_cnt_f;
        int* rp        = which ? g_rowptr_b : g_rowptr_f;
        if (tid == 0) { sOff = 0; rp[0] = 0; }
        __syncthreads();
        for (int base = 0; base < Nn; base += 1024) {
            int i = base + tid;
            int v = (i < Nn) ? cnt[i] : 0;
            sbuf[tid] = v;
            __syncthreads();
            for (int d = 1; d < 1024; d <<= 1) {
                int add = (tid >= d) ? sbuf[tid - d] : 0;
                __syncthreads();
                sbuf[tid] += add;
                __syncthreads();
            }
            if (i < Nn) rp[i + 1] = sOff + sbuf[tid];
            __syncthreads();
            if (tid == 0) sOff += sbuf[1023];
            __syncthreads();
        }
        __syncthreads();
    }
}

__global__ void k_fill(const float* __restrict__ ew) {
    int e = blockIdx.x * blockDim.x + threadIdx.x;
    if (e >= Ee) return;
    int s = g_src[e], t = g_tgt[e];
    float w = ew[e];
    float df = g_deg_f[t]; df = (df == 0.f) ? 1.f : df;
    int pf = g_rowptr_f[t] + atomicAdd(&g_cur_f[t], 1);
    g_adjn_f[pf] = s;  g_adjw_f[pf] = w / df;
    float db = g_deg_b[s]; db = (db == 0.f) ? 1.f : db;
    int pb = g_rowptr_b[s] + atomicAdd(&g_cur_b[s], 1);
    g_adjn_b[pb] = t;  g_adjw_b[pb] = w / db;
}

// ---------------- diffusion propagation (fp16 gather, fp32 accumulate) ----------------
__device__ __forceinline__ void prop16(const __half* __restrict__ hin,
                                       float* __restrict__ outF,
                                       __half* __restrict__ outH,   // may be null
                                       const int* __restrict__ rowptr,
                                       const int* __restrict__ adjn,
                                       const float* __restrict__ adjw,
                                       int node, int lane) {
    int beg = rowptr[node], end = rowptr[node + 1];
    float acc[Bb][2];
    #pragma unroll
    for (int b = 0; b < Bb; b++) { acc[b][0] = 0.f; acc[b][1] = 0.f; }
    for (int e = beg; e < end; e++) {
        int s = adjn[e];
        float w = adjw[e];
        #pragma unroll
        for (int b = 0; b < Bb; b++) {
            __half2 hv = ((const __half2*)(hin + ((size_t)b * Nn + s) * Hh))[lane];
            float2 f = __half22float2(hv);
            acc[b][0] += f.x * w;
            acc[b][1] += f.y * w;
        }
    }
    #pragma unroll
    for (int b = 0; b < Bb; b++) {
        size_t o = ((size_t)b * Nn + node) * Hh + 2*lane;
        *(float2*)&outF[o] = make_float2(acc[b][0], acc[b][1]);
        if (outH)
            *(__half2*)&outH[o] = __halves2half2(__float2half_rn(acc[b][0]),
                                                 __float2half_rn(acc[b][1]));
    }
}

__global__ void k_prop_h1() {
    int gw   = (blockIdx.x * blockDim.x + threadIdx.x) >> 5;
    int lane = threadIdx.x & 31;
    if (gw >= 2*Nn) return;
    if (gw < Nn) prop16(g_h16, g_z0, g_z016, g_rowptr_f, g_adjn_f, g_adjw_f, gw, lane);
    else         prop16(g_h16, g_z2, g_z216, g_rowptr_b, g_adjn_b, g_adjw_b, gw - Nn, lane);
}

__global__ void k_prop_h2() {
    int gw   = (blockIdx.x * blockDim.x + threadIdx.x) >> 5;
    int lane = threadIdx.x & 31;
    if (gw >= 2*Nn) return;
    if (gw < Nn) prop16(g_z016, g_z1, (__half*)0, g_rowptr_f, g_adjn_f, g_adjw_f, gw, lane);
    else         prop16(g_z216, g_z3, (__half*)0, g_rowptr_b, g_adjn_b, g_adjw_b, gw - Nn, lane);
}

// ---------------- fused filt+dec GEMM + output permute ----------------
#define FIN_SMEM ((KCAT*CDEC + KCAT*65) * 4)

__global__ __launch_bounds__(256, 1)
void k_final(float* __restrict__ out) {
    extern __shared__ float smf[];
    float* sW = smf;
    float* sA = smf + KCAT*CDEC;

    int tid = threadIdx.x;
    int m0  = blockIdx.x * 64;

    for (int idx = tid; idx < KCAT*CDEC; idx += 256) sW[idx] = g_W2[idx];

    const float* srcs[5] = { g_h0, g_z0, g_z1, g_z2, g_z3 };
    #pragma unroll
    for (int a = 0; a < 5; a++) {
        const float* S = srcs[a];
        for (int idx = tid; idx < 64*64; idx += 256) {
            int r = idx >> 6, k = idx & 63;
            sA[(a*64 + k)*65 + r] = S[(size_t)(m0 + r) * Hh + k];
        }
    }
    __syncthreads();

    int gc = tid & 31, rt = tid >> 5;
    float acc[8][3];
    #pragma unroll
    for (int i = 0; i < 8; i++)
        #pragma unroll
        for (int j = 0; j < 3; j++) acc[i][j] = 0.f;

    #pragma unroll 2
    for (int k = 0; k < KCAT; k++) {
        float av[8];
        #pragma unroll
        for (int i = 0; i < 8; i++) av[i] = sA[k*65 + rt*8 + i];
        float wv[3];
        #pragma unroll
        for (int j = 0; j < 3; j++) wv[j] = sW[k*CDEC + gc + 32*j];
        #pragma unroll
        for (int i = 0; i < 8; i++)
            #pragma unroll
            for (int j = 0; j < 3; j++) acc[i][j] += av[i] * wv[j];
    }

    #pragma unroll
    for (int i = 0; i < 8; i++) {
        int m = m0 + rt*8 + i;
        int b = m / Nn, n = m - b * Nn;
        #pragma unroll
        for (int j = 0; j < 3; j++) {
            int c = gc + 32*j;
            int tt = c >> 3, f = c & 7;
            out[(((size_t)b * HOR + tt) * Nn + n) * Ff + f] = acc[i][j] + g_b2[c];
        }
    }
}

// ---------------- launch ----------------
extern "C" void kernel_launch(void* const* d_in, const int* in_sizes, int n_in,
                              void* d_out, int out_size) {
    const float* x     = (const float*)d_in[0];
    const void*  ei    = d_in[1];
    const float* ew    = (const float*)d_in[2];
    const float* encW  = (const float*)d_in[3];
    const float* encB  = (const float*)d_in[4];
    const float* nemb  = (const float*)d_in[5];
    const float* Wih   = (const float*)d_in[6];
    const float* Whh   = (const float*)d_in[7];
    const float* bih   = (const float*)d_in[8];
    const float* bhh   = (const float*)d_in[9];
    const float* filtW = (const float*)d_in[10];
    const float* filtB = (const float*)d_in[11];
    const float* decW  = (const float*)d_in[12];
    const float* decB  = (const float*)d_in[13];
    float* out = (float*)d_out;

    cudaFuncSetAttribute(k_gx,      cudaFuncAttributeMaxDynamicSharedMemorySize, GX_SMEM);
    cudaFuncSetAttribute(k_gru_ser, cudaFuncAttributeMaxDynamicSharedMemorySize, SER_SMEM);
    cudaFuncSetAttribute(k_final,   cudaFuncAttributeMaxDynamicSharedMemorySize, FIN_SMEM);

    k_detect<<<1, 1>>>((const unsigned int*)ei);
    k_convert<<<(Ee + 255) / 256, 256>>>(ei);
    k_zero<<<(Nn + 255) / 256, 256>>>();
    k_w2<<<KCAT + 1, CDEC>>>(filtW, filtB, decW, decB);
    k_prepw<<<(4*WIMG_H + 255) / 256, 256>>>(Wih, Whh);
    k_bias<<<1, 192>>>(bhh);

    k_gx<<<Tt * 1250, 256, GX_SMEM>>>(x, encW, encB, nemb, bih);
    k_gru_ser<<<Mm / 128, 512, SER_SMEM>>>();

    k_count<<<(Ee + 255) / 256, 256>>>(ew);
    k_scan<<<1, 1024>>>();
    k_fill<<<(Ee + 255) / 256, 256>>>(ew);
    k_prop_h1<<<(2*Nn*32 + 255) / 256, 256>>>();
    k_prop_h2<<<(2*Nn*32 + 255) / 256, 256>>>();

    k_final<<<Mm / 64, 256, FIN_SMEM>>>(out);
}

// round 8
// speedup vs baseline: 1.2235x; 1.2228x over previous
#include <cuda_runtime.h>
#include <cuda_fp16.h>
#include <math.h>
#include <stdint.h>

#define Nn   10000
#define Bb   8
#define Tt   12
#define Ff   8
#define Hh   64
#define Ee   320000
#define HOR  12
#define Mm   (Bb*Nn)
#define KCAT 320
#define CDEC 96

// ---------------- device scratch ----------------
__device__ float g_h0[Mm*Hh];
__device__ float g_z0[Mm*Hh];
__device__ float g_z1[Mm*Hh];
__device__ float g_z2[Mm*Hh];
__device__ float g_z3[Mm*Hh];
__device__ __half g_h16[Mm*Hh];
__device__ __half g_z016[Mm*Hh];
__device__ __half g_z216[Mm*Hh];
__device__ int   g_src[Ee], g_tgt[Ee];
__device__ int   g_rowptr_f[Nn+1], g_rowptr_b[Nn+1];
__device__ int   g_cnt_f[Nn], g_cnt_b[Nn], g_cur_f[Nn], g_cur_b[Nn];
__device__ float g_deg_f[Nn], g_deg_b[Nn];
__device__ int   g_adjn_f[Ee]; __device__ float g_adjw_f[Ee];
__device__ int   g_adjn_b[Ee]; __device__ float g_adjw_b[Ee];
__device__ float g_W2[KCAT*CDEC];
__device__ float g_b2[CDEC];
__device__ int   g_flag64;
__device__ float g_bhh_stage[192];
__device__ float g_Wp[192*8];                 // W' = encW@Wih, [g][f]
__device__ float g_Cnode[(size_t)Nn*192];     // C[n][g] (includes bih) — L2-hot

// fp16 hi/lo weight images
__device__ __half g_B1Img [2*128*88];   // rz: k<64 Whh, 64..71 W', 72..87 zero
__device__ __half g_B2aImg[2*64*24];    // xn: k<8 W'_n, rest zero
__device__ __half g_B2bImg[2*64*72];    // hn: k<64 Whh_n, 64..71 zero

// ---------------- helpers ----------------
__device__ __forceinline__ uint32_t smem_u32(const void* p) {
    uint32_t a;
    asm("{ .reg .u64 t; cvta.to.shared.u64 t, %1; cvt.u32.u64 %0, t; }" : "=r"(a) : "l"(p));
    return a;
}
__device__ __forceinline__ void ldmat4(uint32_t* f, uint32_t addr) {
    asm volatile("ldmatrix.sync.aligned.m8n8.x4.shared.b16 {%0,%1,%2,%3}, [%4];"
        : "=r"(f[0]), "=r"(f[1]), "=r"(f[2]), "=r"(f[3]) : "r"(addr));
}
__device__ __forceinline__ void mma16816(float* c, const uint32_t* a, uint32_t b0, uint32_t b1) {
    asm volatile("mma.sync.aligned.m16n8k16.row.col.f32.f16.f16.f32 "
        "{%0,%1,%2,%3}, {%4,%5,%6,%7}, {%8,%9}, {%0,%1,%2,%3};"
        : "+f"(c[0]), "+f"(c[1]), "+f"(c[2]), "+f"(c[3])
        : "r"(a[0]), "r"(a[1]), "r"(a[2]), "r"(a[3]), "r"(b0), "r"(b1));
}
#define CPA16(sa, gp) asm volatile("cp.async.cg.shared.global [%0], [%1], 16;" :: "r"(sa), "l"(gp))
#define CPA_WAIT()    asm volatile("cp.async.wait_all;" ::: "memory")
__device__ __forceinline__ float sigf(float x)  { return 1.f / (1.f + __expf(-x)); }
__device__ __forceinline__ float tanhff(float x){ float e = __expf(2.f*x); return 1.f - 2.f/(e + 1.f); }
__device__ __forceinline__ void h2split(float v0, float v1, __half2* hi, __half2* lo) {
    __half a = __float2half_rn(v0), b = __float2half_rn(v1);
    *hi = __halves2half2(a, b);
    *lo = __halves2half2(__float2half_rn(v0 - __half2float(a)),
                         __float2half_rn(v1 - __half2float(b)));
}

// ---------------- small prep kernels ----------------
__global__ void k_detect(const unsigned int* ei_raw) {
    bool all0 = true;
    for (int i = 0; i < 16; i++) if (ei_raw[2*i + 1] != 0u) all0 = false;
    g_flag64 = all0 ? 1 : 0;
}
__global__ void k_convert(const void* ei) {
    int e = blockIdx.x * blockDim.x + threadIdx.x;
    if (e >= Ee) return;
    if (g_flag64) {
        const long long* p = (const long long*)ei;
        g_src[e] = (int)p[e]; g_tgt[e] = (int)p[Ee + e];
    } else {
        const int* p = (const int*)ei;
        g_src[e] = p[e]; g_tgt[e] = p[Ee + e];
    }
}
__global__ void k_zero() {
    int i = blockIdx.x * blockDim.x + threadIdx.x;
    if (i < Nn) {
        g_cnt_f[i] = 0; g_cnt_b[i] = 0; g_cur_f[i] = 0; g_cur_b[i] = 0;
        g_deg_f[i] = 0.f; g_deg_b[i] = 0.f;
    }
}
__global__ void k_bias(const float* __restrict__ bhh) {
    if (threadIdx.x < 192) g_bhh_stage[threadIdx.x] = bhh[threadIdx.x];
}
__global__ void k_w2(const float* __restrict__ filtW, const float* __restrict__ filtB,
                     const float* __restrict__ decW,  const float* __restrict__ decB) {
    int c = threadIdx.x, k = blockIdx.x;
    if (k < KCAT) {
        float acc = 0.f;
        for (int j = 0; j < Hh; j++) acc += filtW[k*Hh + j] * decW[j*CDEC + c];
        g_W2[k*CDEC + c] = acc;
    } else {
        float acc = decB[c];
        for (int j = 0; j < Hh; j++) acc += filtB[j] * decW[j*CDEC + c];
        g_b2[c] = acc;
    }
}
__global__ void k_wprime(const float* __restrict__ encW, const float* __restrict__ Wih) {
    int idx = blockIdx.x * blockDim.x + threadIdx.x;
    if (idx >= 192*8) return;
    int g = idx >> 3, f = idx & 7;
    float acc = 0.f;
    for (int h = 0; h < 64; h++) acc += encW[f*64 + h] * Wih[g*64 + h];
    g_Wp[g*8 + f] = acc;
}
__global__ __launch_bounds__(192)
void k_cnode(const float* __restrict__ encB, const float* __restrict__ nodeEmb,
             const float* __restrict__ Wih,  const float* __restrict__ bih) {
    __shared__ float sEB[16][68];
    int tid = threadIdx.x, n0 = blockIdx.x * 16;
    for (int i = tid; i < 16*64; i += 192) {
        int nl = i >> 6, k = i & 63;
        sEB[nl][k] = encB[k] + nodeEmb[(n0 + nl)*64 + k];
    }
    __syncthreads();
    int c = tid;
    float w[64];
    #pragma unroll
    for (int k = 0; k < 64; k++) w[k] = Wih[c*64 + k];
    float bb = bih[c];
    for (int nl = 0; nl < 16; nl++) {
        float acc = bb;
        #pragma unroll
        for (int k = 0; k < 64; k++) acc += sEB[nl][k] * w[k];
        g_Cnode[(size_t)(n0 + nl)*192 + c] = acc;
    }
}
__global__ void k_prepw(const float* __restrict__ Whh) {
    int idx = blockIdx.x * blockDim.x + threadIdx.x;
    if (idx >= 34816) return;
    float val = 0.f; __half* dst; int prec;
    if (idx < 22528) {
        prec = idx / 11264; int rem = idx % 11264;
        int n = rem / 88, k = rem % 88;
        if (k < 64)      val = Whh[n*64 + k];
        else if (k < 72) val = g_Wp[n*8 + (k - 64)];
        dst = &g_B1Img[idx];
    } else if (idx < 25600) {
        int q = idx - 22528; prec = q / 1536; int rem = q % 1536;
        int n = rem / 24, k = rem % 24;
        if (k < 8) val = g_Wp[(128 + n)*8 + k];
        dst = &g_B2aImg[q];
    } else {
        int q = idx - 25600; prec = q / 4608; int rem = q % 4608;
        int n = rem / 72, k = rem % 72;
        if (k < 64) val = Whh[(128 + n)*64 + k];
        dst = &g_B2bImg[q];
    }
    __half hi = __float2half_rn(val);
    *dst = prec ? __float2half_rn(val - __half2float(hi)) : hi;
}

// ================= fused 12-step GRU: A=[h|x] K=72 =================
// 128 rows/block, 512 threads (16 warps: 4Mw x 4Nw).
// smem: A_hi 0 (18432), A_lo 18432 (18432), B1 36864 (45056), B2a 81920 (6144),
//       B2b 88064 (18432), SE 106496 ([128][132]f 67584), sXr 174080 (8192), bias 182272 (768)
#define GA_HI  0
#define GA_LO  18432
#define GB1    36864
#define GB2A   81920
#define GB2B   88064
#define GSE    106496
#define GXR    174080
#define GBIAS  182272
#define GRU_SMEM 183040

__global__ __launch_bounds__(512, 1)
void k_gru(const float* __restrict__ x)
{
    extern __shared__ __align__(16) char sm[];
    __half* Ahi = (__half*)(sm + GA_HI);
    __half* Alo = (__half*)(sm + GA_LO);
    float*  SE  = (float*)(sm + GSE);
    float*  sXr = (float*)(sm + GXR);
    float*  sBh = (float*)(sm + GBIAS);
    float*  sH  = SE;  // NOTE: sH is separate region? no — see below

    int tid = threadIdx.x, lane = tid & 31, wid = tid >> 5;
    int mw = wid & 3, nw = wid >> 2;
    int m0 = blockIdx.x * 128;

    // one-time loads
    {
        const uint4* s1 = (const uint4*)g_B1Img;  uint4* d1 = (uint4*)(sm + GB1);
        for (int i = tid; i < 45056/16; i += 512) d1[i] = s1[i];
        const uint4* s2 = (const uint4*)g_B2aImg; uint4* d2 = (uint4*)(sm + GB2A);
        if (tid < 6144/16) d2[tid] = s2[tid];
        const uint4* s3 = (const uint4*)g_B2bImg; uint4* d3 = (uint4*)(sm + GB2B);
        for (int i = tid; i < 18432/16; i += 512) d3[i] = s3[i];
        float4* a4 = (float4*)(sm + GA_HI);      // zero A hi+lo
        for (int i = tid; i < 36864/16; i += 512) a4[i] = make_float4(0.f,0.f,0.f,0.f);
    }
    if (tid < 192) sBh[tid] = g_bhh_stage[tid];

    int r  = tid >> 2;
    int kq = (tid & 3) * 16;
    int m  = m0 + r, bq = m / Nn, nq = m - bq * Nn;
    uint32_t sb = smem_u32(sm);

    // prefetch x[0]
    if (tid < 256) {
        int row = tid >> 1, ch = tid & 1;
        int mm = m0 + row, b2 = mm / Nn, n2 = mm - b2 * Nn;
        CPA16(sb + GXR + (row*8 + ch*4)*4, &x[(((size_t)b2*Tt + 0)*Nn + n2)*Ff + ch*4]);
    }
    CPA_WAIT();
    __syncthreads();

    float h[16];
    #pragma unroll
    for (int i = 0; i < 16; i++) h[i] = 0.f;

    int arow = lane & 15, acol8 = (lane >> 4) * 8;
    int bn = lane >> 2, bc2 = 2 * (lane & 3);
    int g = lane >> 2, c2 = 2 * (lane & 3);

    const float* Cp = &g_Cnode[(size_t)nq*192];

    for (int t = 0; t < Tt; t++) {
        int cur = t & 1;
        // ---- A-build ----
        if (t > 0) {
            #pragma unroll
            for (int jj = 0; jj < 16; jj += 2)
                h2split(h[jj], h[jj+1],
                        (__half2*)(Ahi + r*72 + kq + jj), (__half2*)(Alo + r*72 + kq + jj));
        }
        if (kq == 0) {
            #pragma unroll
            for (int f2 = 0; f2 < 8; f2 += 2)
                h2split(sXr[cur*1024 + r*8 + f2], sXr[cur*1024 + r*8 + f2 + 1],
                        (__half2*)(Ahi + r*72 + 64 + f2), (__half2*)(Alo + r*72 + 64 + f2));
        }
        __syncthreads();   // S1

        // prefetch x[t+1]
        if (t + 1 < Tt && tid < 256) {
            int row = tid >> 1, ch = tid & 1;
            int mm = m0 + row, b2 = mm / Nn, n2 = mm - b2 * Nn;
            CPA16(sb + GXR + ((1-cur)*1024 + row*8 + ch*4)*4,
                  &x[(((size_t)b2*Tt + (t+1))*Nn + n2)*Ff + ch*4]);
        }

        // ---- 3-pass hi/lo mma ----
        float acc1[2][4][4], acc2a[2][2][4], acc2b[2][2][4];
        #pragma unroll
        for (int i = 0; i < 2; i++) {
            #pragma unroll
            for (int j = 0; j < 4; j++)
                #pragma unroll
                for (int q = 0; q < 4; q++) acc1[i][j][q] = 0.f;
            #pragma unroll
            for (int j = 0; j < 2; j++)
                #pragma unroll
                for (int q = 0; q < 4; q++) { acc2a[i][j][q] = 0.f; acc2b[i][j][q] = 0.f; }
        }
        #pragma unroll
        for (int p = 0; p < 3; p++) {
            uint32_t aB  = sb + ((p == 1) ? GA_LO : GA_HI);
            uint32_t b1B = sb + GB1  + ((p == 2) ? 22528 : 0);
            uint32_t b2aB= sb + GB2A + ((p == 2) ? 3072  : 0);
            uint32_t b2bB= sb + GB2B + ((p == 2) ? 9216  : 0);
            #pragma unroll
            for (int ks = 0; ks < 5; ks++) {
                uint32_t afr[2][4];
                #pragma unroll
                for (int mt = 0; mt < 2; mt++)
                    ldmat4(afr[mt], aB + ((mw*32 + mt*16 + arow)*72 + ks*16 + acol8) * 2);
                #pragma unroll
                for (int nt = 0; nt < 4; nt++) {
                    int n = nw*32 + nt*8 + bn;
                    uint32_t bo = (b1B - sb) + (n*88 + ks*16 + bc2) * 2;
                    uint32_t b0 = *(const uint32_t*)(sm + bo);
                    uint32_t b1 = *(const uint32_t*)(sm + bo + 16);
                    mma16816(acc1[0][nt], afr[0], b0, b1);
                    mma16816(acc1[1][nt], afr[1], b0, b1);
                }
                if (ks == 4) {
                    #pragma unroll
                    for (int nt2 = 0; nt2 < 2; nt2++) {
                        int n2 = nw*16 + nt2*8 + bn;
                        uint32_t bo = (b2aB - sb) + (n2*24 + bc2) * 2;
                        uint32_t b0 = *(const uint32_t*)(sm + bo);
                        uint32_t b1 = *(const uint32_t*)(sm + bo + 16);
                        mma16816(acc2a[0][nt2], afr[0], b0, b1);
                        mma16816(acc2a[1][nt2], afr[1], b0, b1);
                    }
                } else {
                    #pragma unroll
                    for (int nt2 = 0; nt2 < 2; nt2++) {
                        int n2 = nw*16 + nt2*8 + bn;
                        uint32_t bo = (b2bB - sb) + (n2*72 + ks*16 + bc2) * 2;
                        uint32_t b0 = *(const uint32_t*)(sm + bo);
                        uint32_t b1 = *(const uint32_t*)(sm + bo + 16);
                        mma16816(acc2b[0][nt2], afr[0], b0, b1);
                        mma16816(acc2b[1][nt2], afr[1], b0, b1);
                    }
                }
            }
        }

        // ---- staging1: rz -> SE cols 0..127 ----
        #pragma unroll
        for (int mt = 0; mt < 2; mt++)
            #pragma unroll
            for (int q2 = 0; q2 < 2; q2++) {
                int row = mw*32 + mt*16 + g + q2*8;
                #pragma unroll
                for (int nt = 0; nt < 4; nt++) {
                    int col = nw*32 + nt*8 + c2;
                    *(float2*)&SE[row*132 + col] =
                        make_float2(acc1[mt][nt][q2*2], acc1[mt][nt][q2*2 + 1]);
                }
            }
        __syncthreads();   // S2

        // ---- gates-A: r,z ----
        float rg[16], zg[16];
        #pragma unroll
        for (int jj = 0; jj < 16; jj++) {
            int j = kq + jj;
            rg[jj] = sigf(SE[r*132 + j]      + Cp[j]      + sBh[j]);
            zg[jj] = sigf(SE[r*132 + 64 + j] + Cp[64 + j] + sBh[64 + j]);
        }
        __syncthreads();   // S3

        // ---- staging2: xn -> SE 0..63, hn -> SE 64..127 ----
        #pragma unroll
        for (int mt = 0; mt < 2; mt++)
            #pragma unroll
            for (int q2 = 0; q2 < 2; q2++) {
                int row = mw*32 + mt*16 + g + q2*8;
                #pragma unroll
                for (int nt2 = 0; nt2 < 2; nt2++) {
                    int col = nw*16 + nt2*8 + c2;
                    *(float2*)&SE[row*132 + col] =
                        make_float2(acc2a[mt][nt2][q2*2], acc2a[mt][nt2][q2*2 + 1]);
                    *(float2*)&SE[row*132 + 64 + col] =
                        make_float2(acc2b[mt][nt2][q2*2], acc2b[mt][nt2][q2*2 + 1]);
                }
            }
        CPA_WAIT();
        __syncthreads();   // S4

        // ---- gates-B: n gate + h update (h in registers) ----
        #pragma unroll
        for (int jj = 0; jj < 16; jj++) {
            int j = kq + jj;
            float xn = SE[r*132 + j]      + Cp[128 + j];
            float hn = SE[r*132 + 64 + j] + sBh[128 + j];
            float ng = tanhff(xn + rg[jj] * hn);
            h[jj] = (1.f - zg[jj]) * ng + zg[jj] * h[jj];
        }
    }

    // final h -> gmem (fp32 + fp16)
    {
        float4* dst = (float4*)(g_h0 + (size_t)m*Hh + kq);
        __half2* d16 = (__half2*)(g_h16 + (size_t)m*Hh + kq);
        #pragma unroll
        for (int q = 0; q < 4; q++) {
            dst[q] = make_float4(h[q*4], h[q*4+1], h[q*4+2], h[q*4+3]);
            d16[q*2]   = __halves2half2(__float2half_rn(h[q*4]),   __float2half_rn(h[q*4+1]));
            d16[q*2+1] = __halves2half2(__float2half_rn(h[q*4+2]), __float2half_rn(h[q*4+3]));
        }
    }
}

// ---------------- CSR build ----------------
__global__ void k_count(const float* __restrict__ ew) {
    int e = blockIdx.x * blockDim.x + threadIdx.x;
    if (e >= Ee) return;
    int s = g_src[e], t = g_tgt[e];
    float w = ew[e];
    atomicAdd(&g_cnt_f[t], 1);  atomicAdd(&g_deg_f[t], w);
    atomicAdd(&g_cnt_b[s], 1);  atomicAdd(&g_deg_b[s], w);
}
__global__ void k_scan() {
    __shared__ int sbuf[1024];
    __shared__ int sOff;
    int tid = threadIdx.x;
    for (int which = 0; which < 2; ++which) {
        const int* cnt = which ? g_cnt_b : g_cnt_f;
        int* rp        = which ? g_rowptr_b : g_rowptr_f;
        if (tid == 0) { sOff = 0; rp[0] = 0; }
        __syncthreads();
        for (int base = 0; base < Nn; base += 1024) {
            int i = base + tid;
            int v = (i < Nn) ? cnt[i] : 0;
            sbuf[tid] = v;
            __syncthreads();
            for (int d = 1; d < 1024; d <<= 1) {
                int add = (tid >= d) ? sbuf[tid - d] : 0;
                __syncthreads();
                sbuf[tid] += add;
                __syncthreads();
            }
            if (i < Nn) rp[i + 1] = sOff + sbuf[tid];
            __syncthreads();
            if (tid == 0) sOff += sbuf[1023];
            __syncthreads();
        }
        __syncthreads();
    }
}
__global__ void k_fill(const float* __restrict__ ew) {
    int e = blockIdx.x * blockDim.x + threadIdx.x;
    if (e >= Ee) return;
    int s = g_src[e], t = g_tgt[e];
    float w = ew[e];
    float df = g_deg_f[t]; df = (df == 0.f) ? 1.f : df;
    int pf = g_rowptr_f[t] + atomicAdd(&g_cur_f[t], 1);
    g_adjn_f[pf] = s;  g_adjw_f[pf] = w / df;
    float db = g_deg_b[s]; db = (db == 0.f) ? 1.f : db;
    int pb = g_rowptr_b[s] + atomicAdd(&g_cur_b[s], 1);
    g_adjn_b[pb] = t;  g_adjw_b[pb] = w / db;
}

// ---------------- diffusion props (fp16 gather, fp32 accumulate) ----------------
__device__ __forceinline__ void prop16(const __half* __restrict__ hin,
                                       float* __restrict__ outF, __half* __restrict__ outH,
                                       const int* __restrict__ rowptr,
                                       const int* __restrict__ adjn,
                                       const float* __restrict__ adjw,
                                       int node, int lane) {
    int beg = rowptr[node], end = rowptr[node + 1];
    float acc[Bb][2];
    #pragma unroll
    for (int b = 0; b < Bb; b++) { acc[b][0] = 0.f; acc[b][1] = 0.f; }
    for (int e = beg; e < end; e++) {
        int s = adjn[e];
        float w = adjw[e];
        #pragma unroll
        for (int b = 0; b < Bb; b++) {
            __half2 hv = ((const __half2*)(hin + ((size_t)b * Nn + s) * Hh))[lane];
            float2 f = __half22float2(hv);
            acc[b][0] += f.x * w;
            acc[b][1] += f.y * w;
        }
    }
    #pragma unroll
    for (int b = 0; b < Bb; b++) {
        size_t o = ((size_t)b * Nn + node) * Hh + 2*lane;
        *(float2*)&outF[o] = make_float2(acc[b][0], acc[b][1]);
        if (outH)
            *(__half2*)&outH[o] = __halves2half2(__float2half_rn(acc[b][0]),
                                                 __float2half_rn(acc[b][1]));
    }
}
__global__ void k_prop_h1() {
    int gw = (blockIdx.x * blockDim.x + threadIdx.x) >> 5;
    int lane = threadIdx.x & 31;
    if (gw >= 2*Nn) return;
    if (gw < Nn) prop16(g_h16, g_z0, g_z016, g_rowptr_f, g_adjn_f, g_adjw_f, gw, lane);
    else         prop16(g_h16, g_z2, g_z216, g_rowptr_b, g_adjn_b, g_adjw_b, gw - Nn, lane);
}
__global__ void k_prop_h2() {
    int gw = (blockIdx.x * blockDim.x + threadIdx.x) >> 5;
    int lane = threadIdx.x & 31;
    if (gw >= 2*Nn) return;
    if (gw < Nn) prop16(g_z016, g_z1, (__half*)0, g_rowptr_f, g_adjn_f, g_adjw_f, gw, lane);
    else         prop16(g_z216, g_z3, (__half*)0, g_rowptr_b, g_adjn_b, g_adjw_b, gw - Nn, lane);
}

// ---------------- fused filt+dec GEMM + permute ----------------
#define FIN_SMEM ((KCAT*CDEC + KCAT*65) * 4)
__global__ __launch_bounds__(256, 1)
void k_final(float* __restrict__ out) {
    extern __shared__ float smf[];
    float* sW = smf;
    float* sA = smf + KCAT*CDEC;
    int tid = threadIdx.x, m0 = blockIdx.x * 64;
    for (int idx = tid; idx < KCAT*CDEC; idx += 256) sW[idx] = g_W2[idx];
    const float* srcs[5] = { g_h0, g_z0, g_z1, g_z2, g_z3 };
    #pragma unroll
    for (int a = 0; a < 5; a++) {
        const float* S = srcs[a];
        for (int idx = tid; idx < 64*64; idx += 256) {
            int r = idx >> 6, k = idx & 63;
            sA[(a*64 + k)*65 + r] = S[(size_t)(m0 + r) * Hh + k];
        }
    }
    __syncthreads();
    int gc = tid & 31, rt = tid >> 5;
    float acc[8][3];
    #pragma unroll
    for (int i = 0; i < 8; i++)
        #pragma unroll
        for (int j = 0; j < 3; j++) acc[i][j] = 0.f;
    #pragma unroll 2
    for (int k = 0; k < KCAT; k++) {
        float av[8];
        #pragma unroll
        for (int i = 0; i < 8; i++) av[i] = sA[k*65 + rt*8 + i];
        float wv[3];
        #pragma unroll
        for (int j = 0; j < 3; j++) wv[j] = sW[k*CDEC + gc + 32*j];
        #pragma unroll
        for (int i = 0; i < 8; i++)
            #pragma unroll
            for (int j = 0; j < 3; j++) acc[i][j] += av[i] * wv[j];
    }
    #pragma unroll
    for (int i = 0; i < 8; i++) {
        int m = m0 + rt*8 + i;
        int b = m / Nn, n = m - b * Nn;
        #pragma unroll
        for (int j = 0; j < 3; j++) {
            int c = gc + 32*j;
            int tt = c >> 3, f = c & 7;
            out[(((size_t)b * HOR + tt) * Nn + n) * Ff + f] = acc[i][j] + g_b2[c];
        }
    }
}

// ---------------- launch ----------------
extern "C" void kernel_launch(void* const* d_in, const int* in_sizes, int n_in,
                              void* d_out, int out_size) {
    const float* x     = (const float*)d_in[0];
    const void*  ei    = d_in[1];
    const float* ew    = (const float*)d_in[2];
    const float* encW  = (const float*)d_in[3];
    const float* encB  = (const float*)d_in[4];
    const float* nemb  = (const float*)d_in[5];
    const float* Wih   = (const float*)d_in[6];
    const float* Whh   = (const float*)d_in[7];
    const float* bih   = (const float*)d_in[8];
    const float* bhh   = (const float*)d_in[9];
    const float* filtW = (const float*)d_in[10];
    const float* filtB = (const float*)d_in[11];
    const float* decW  = (const float*)d_in[12];
    const float* decB  = (const float*)d_in[13];
    float* out = (float*)d_out;

    cudaFuncSetAttribute(k_gru,   cudaFuncAttributeMaxDynamicSharedMemorySize, GRU_SMEM);
    cudaFuncSetAttribute(k_final, cudaFuncAttributeMaxDynamicSharedMemorySize, FIN_SMEM);

    k_detect<<<1, 1>>>((const unsigned int*)ei);
    k_convert<<<(Ee + 255) / 256, 256>>>(ei);
    k_zero<<<(Nn + 255) / 256, 256>>>();
    k_w2<<<KCAT + 1, CDEC>>>(filtW, filtB, decW, decB);
    k_wprime<<<6, 256>>>(encW, Wih);
    k_cnode<<<Nn/16, 192>>>(encB, nemb, Wih, bih);
    k_prepw<<<(34816 + 255) / 256, 256>>>(Whh);
    k_bias<<<1, 192>>>(bhh);

    k_gru<<<Mm / 128, 512, GRU_SMEM>>>(x);

    k_count<<<(Ee + 255) / 256, 256>>>(ew);
    k_scan<<<1, 1024>>>();
    k_fill<<<(Ee + 255) / 256, 256>>>(ew);
    k_prop_h1<<<(2*Nn*32 + 255) / 256, 256>>>();
    k_prop_h2<<<(2*Nn*32 + 255) / 256, 256>>>();

    k_final<<<Mm / 64, 256, FIN_SMEM>>>(out);
}

// round 10
// speedup vs baseline: 1.4568x; 1.1907x over previous
#include <cuda_runtime.h>
#include <cuda_fp16.h>
#include <math.h>
#include <stdint.h>

#define Nn   10000
#define Bb   8
#define Tt   12
#define Ff   8
#define Hh   64
#define Ee   320000
#define HOR  12
#define Mm   (Bb*Nn)
#define KCAT 320
#define CDEC 96

// ---------------- device scratch ----------------
__device__ float g_h0[Mm*Hh];
__device__ float g_z0[Mm*Hh];
__device__ float g_z1[Mm*Hh];
__device__ float g_z2[Mm*Hh];
__device__ float g_z3[Mm*Hh];
__device__ __half g_h16[Mm*Hh];
__device__ __half g_z016[Mm*Hh];
__device__ __half g_z216[Mm*Hh];
__device__ int   g_src[Ee], g_tgt[Ee];
__device__ int   g_rowptr_f[Nn+1], g_rowptr_b[Nn+1];
__device__ int   g_cnt_f[Nn], g_cnt_b[Nn], g_cur_f[Nn], g_cur_b[Nn];
__device__ float g_deg_f[Nn], g_deg_b[Nn];
__device__ int   g_adjn_f[Ee]; __device__ float g_adjw_f[Ee];
__device__ int   g_adjn_b[Ee]; __device__ float g_adjw_b[Ee];
__device__ float g_W2[KCAT*CDEC];
__device__ float g_b2[CDEC];
__device__ int   g_flag64;
__device__ float g_bhh_stage[192];
__device__ float g_Wp[192*8];                   // W' = encW@Wih
__device__ __half g_Cnode16[(size_t)Nn*192];    // C[n][g] fp16 (bih + bhh_rz folded)

// fp16 hi/lo weight images (zero-padded k-overhang)
__device__ __half g_B1Img [2*128*84];   // rz: k<64 Whh, 64..71 W', 72..83 zero
__device__ __half g_B2aImg[2*64*24];    // xn: k<8 W'_n, 8..23 zero
__device__ __half g_B2bImg[2*64*68];    // hn: k<64 Whh_n, 64..67 zero

// ---------------- helpers ----------------
__device__ __forceinline__ uint32_t smem_u32(const void* p) {
    uint32_t a;
    asm("{ .reg .u64 t; cvta.to.shared.u64 t, %1; cvt.u32.u64 %0, t; }" : "=r"(a) : "l"(p));
    return a;
}
__device__ __forceinline__ void ldmat4(uint32_t* f, uint32_t addr) {
    asm volatile("ldmatrix.sync.aligned.m8n8.x4.shared.b16 {%0,%1,%2,%3}, [%4];"
        : "=r"(f[0]), "=r"(f[1]), "=r"(f[2]), "=r"(f[3]) : "r"(addr));
}
__device__ __forceinline__ void mma16816(float* c, const uint32_t* a, uint32_t b0, uint32_t b1) {
    asm volatile("mma.sync.aligned.m16n8k16.row.col.f32.f16.f16.f32 "
        "{%0,%1,%2,%3}, {%4,%5,%6,%7}, {%8,%9}, {%0,%1,%2,%3};"
        : "+f"(c[0]), "+f"(c[1]), "+f"(c[2]), "+f"(c[3])
        : "r"(a[0]), "r"(a[1]), "r"(a[2]), "r"(a[3]), "r"(b0), "r"(b1));
}
#define CPA16(sa, gp) asm volatile("cp.async.cg.shared.global [%0], [%1], 16;" :: "r"(sa), "l"(gp))
#define CPA_WAIT()    asm volatile("cp.async.wait_all;" ::: "memory")
__device__ __forceinline__ float sigf(float x)  { return 1.f / (1.f + __expf(-x)); }
__device__ __forceinline__ float tanhff(float x){ float e = __expf(2.f*x); return 1.f - 2.f/(e + 1.f); }
__device__ __forceinline__ void h2split(float v0, float v1, __half2* hi, __half2* lo) {
    __half a = __float2half_rn(v0), b = __float2half_rn(v1);
    *hi = __halves2half2(a, b);
    *lo = __halves2half2(__float2half_rn(v0 - __half2float(a)),
                         __float2half_rn(v1 - __half2float(b)));
}

// ---------------- small prep kernels ----------------
__global__ void k_detect(const unsigned int* ei_raw) {
    bool all0 = true;
    for (int i = 0; i < 16; i++) if (ei_raw[2*i + 1] != 0u) all0 = false;
    g_flag64 = all0 ? 1 : 0;
}
__global__ void k_convert(const void* ei) {
    int e = blockIdx.x * blockDim.x + threadIdx.x;
    if (e >= Ee) return;
    if (g_flag64) {
        const long long* p = (const long long*)ei;
        g_src[e] = (int)p[e]; g_tgt[e] = (int)p[Ee + e];
    } else {
        const int* p = (const int*)ei;
        g_src[e] = p[e]; g_tgt[e] = p[Ee + e];
    }
}
__global__ void k_zero() {
    int i = blockIdx.x * blockDim.x + threadIdx.x;
    if (i < Nn) {
        g_cnt_f[i] = 0; g_cnt_b[i] = 0; g_cur_f[i] = 0; g_cur_b[i] = 0;
        g_deg_f[i] = 0.f; g_deg_b[i] = 0.f;
    }
}
__global__ void k_bias(const float* __restrict__ bhh) {
    if (threadIdx.x < 192) g_bhh_stage[threadIdx.x] = bhh[threadIdx.x];
}
__global__ void k_w2(const float* __restrict__ filtW, const float* __restrict__ filtB,
                     const float* __restrict__ decW,  const float* __restrict__ decB) {
    int c = threadIdx.x, k = blockIdx.x;
    if (k < KCAT) {
        float acc = 0.f;
        for (int j = 0; j < Hh; j++) acc += filtW[k*Hh + j] * decW[j*CDEC + c];
        g_W2[k*CDEC + c] = acc;
    } else {
        float acc = decB[c];
        for (int j = 0; j < Hh; j++) acc += filtB[j] * decW[j*CDEC + c];
        g_b2[c] = acc;
    }
}
__global__ void k_wprime(const float* __restrict__ encW, const float* __restrict__ Wih) {
    int idx = blockIdx.x * blockDim.x + threadIdx.x;
    if (idx >= 192*8) return;
    int g = idx >> 3, f = idx & 7;
    float acc = 0.f;
    for (int h = 0; h < 64; h++) acc += encW[f*64 + h] * Wih[g*64 + h];
    g_Wp[g*8 + f] = acc;
}
// C[n][g] = (encB+emb[n])@Wih + bih (+ bhh for g<128), stored fp16
__global__ __launch_bounds__(192)
void k_cnode(const float* __restrict__ encB, const float* __restrict__ nodeEmb,
             const float* __restrict__ Wih,  const float* __restrict__ bih,
             const float* __restrict__ bhh) {
    __shared__ float sEB[16][68];
    int tid = threadIdx.x, n0 = blockIdx.x * 16;
    for (int i = tid; i < 16*64; i += 192) {
        int nl = i >> 6, k = i & 63;
        sEB[nl][k] = encB[k] + nodeEmb[(n0 + nl)*64 + k];
    }
    __syncthreads();
    int c = tid;
    float w[64];
    #pragma unroll
    for (int k = 0; k < 64; k++) w[k] = Wih[c*64 + k];
    float bb = bih[c] + ((c < 128) ? bhh[c] : 0.f);
    for (int nl = 0; nl < 16; nl++) {
        float acc = bb;
        #pragma unroll
        for (int k = 0; k < 64; k++) acc += sEB[nl][k] * w[k];
        g_Cnode16[(size_t)(n0 + nl)*192 + c] = __float2half_rn(acc);
    }
}
__global__ void k_prepw(const float* __restrict__ Whh) {
    int idx = blockIdx.x * blockDim.x + threadIdx.x;
    if (idx >= 33280) return;
    float val = 0.f; __half* dst;
    if (idx < 21504) {                            // B1 [prec][128][84]
        int rem = idx % 10752;
        int n = rem / 84, k = rem % 84;
        if (k < 64)      val = Whh[n*64 + k];
        else if (k < 72) val = g_Wp[n*8 + (k - 64)];
        dst = &g_B1Img[idx];
        int prec = idx / 10752;
        __half hi = __float2half_rn(val);
        *dst = prec ? __float2half_rn(val - __half2float(hi)) : hi;
        return;
    }
    if (idx < 24576) {                            // B2a [prec][64][24]
        int q = idx - 21504;
        int prec = q / 1536; int rem = q % 1536;
        int n = rem / 24, k = rem % 24;
        if (k < 8) val = g_Wp[(128 + n)*8 + k];
        dst = &g_B2aImg[q];
        __half hi = __float2half_rn(val);
        *dst = prec ? __float2half_rn(val - __half2float(hi)) : hi;
        return;
    }
    {                                             // B2b [prec][64][68]
        int q = idx - 24576;
        int prec = q / 4352; int rem = q % 4352;
        int n = rem / 68, k = rem % 68;
        if (k < 64) val = Whh[(128 + n)*64 + k];
        dst = &g_B2bImg[q];
        __half hi = __float2half_rn(val);
        *dst = prec ? __float2half_rn(val - __half2float(hi)) : hi;
    }
}

// ================= fused 12-step GRU: A=[h|x] K=72, C resident in smem =================
// 128 rows/block, 512 threads (16 warps: 4Mw x 4Nw).
// sC row stride = 200 halves (400B, 16-aligned) — fixes R9 misaligned uint4.
#define GA_HI  0
#define GA_LO  18432
#define GB1    36864
#define GB2A   79872
#define GB2B   86016
#define GSE    103424
#define GC16   169984
#define GXR    221184
#define GBIAS  229376
#define GRU_SMEM 230144

__global__ __launch_bounds__(512, 1)
void k_gru(const float* __restrict__ x)
{
    extern __shared__ __align__(16) char sm[];
    __half* Ahi = (__half*)(sm + GA_HI);
    __half* Alo = (__half*)(sm + GA_LO);
    float*  SE  = (float*)(sm + GSE);       // [128][130]
    __half* sC  = (__half*)(sm + GC16);     // [128][200] (192 used)
    float*  sXr = (float*)(sm + GXR);
    float*  sBh = (float*)(sm + GBIAS);

    int tid = threadIdx.x, lane = tid & 31, wid = tid >> 5;
    int mw = wid & 3, nw = wid >> 2;
    int m0 = blockIdx.x * 128;

    // one-time loads: B images, C16 rows for this block, bias; zero A
    {
        const uint4* s1 = (const uint4*)g_B1Img;  uint4* d1 = (uint4*)(sm + GB1);
        for (int i = tid; i < 43008/16; i += 512) d1[i] = s1[i];
        const uint4* s2 = (const uint4*)g_B2aImg; uint4* d2 = (uint4*)(sm + GB2A);
        if (tid < 6144/16) d2[tid] = s2[tid];
        const uint4* s3 = (const uint4*)g_B2bImg; uint4* d3 = (uint4*)(sm + GB2B);
        for (int i = tid; i < 17408/16; i += 512) d3[i] = s3[i];
        float4* a4 = (float4*)(sm + GA_HI);
        for (int i = tid; i < 36864/16; i += 512) a4[i] = make_float4(0.f,0.f,0.f,0.f);
        // C16: 128 rows x 192 halves = 24 uint4 chunks/row; smem row stride 200h = 400B (aligned)
        for (int i = tid; i < 3072; i += 512) {
            int row = i / 24, ch = i % 24;
            int node = (m0 + row) % Nn;
            const uint4* srcc = (const uint4*)(g_Cnode16 + (size_t)node*192) + ch;
            *((uint4*)(sC + row*200) + ch) = *srcc;
        }
    }
    if (tid < 192) sBh[tid] = g_bhh_stage[tid];

    int r  = tid >> 2;
    int kq = (tid & 3) * 16;
    int m  = m0 + r;
    uint32_t sb = smem_u32(sm);

    // prefetch x[0]
    if (tid < 256) {
        int row = tid >> 1, ch = tid & 1;
        int mm = m0 + row, b2 = mm / Nn, n2 = mm - b2 * Nn;
        CPA16(sb + GXR + (row*8 + ch*4)*4, &x[(((size_t)b2*Tt + 0)*Nn + n2)*Ff + ch*4]);
    }
    CPA_WAIT();
    __syncthreads();

    float h[16];
    #pragma unroll
    for (int i = 0; i < 16; i++) h[i] = 0.f;

    int arow = lane & 15, acol8 = (lane >> 4) * 8;
    int bn = lane >> 2, bc2 = 2 * (lane & 3);
    int g = lane >> 2, c2 = 2 * (lane & 3);

    for (int t = 0; t < Tt; t++) {
        int cur = t & 1;
        // ---- A-build ----
        if (t > 0) {
            #pragma unroll
            for (int jj = 0; jj < 16; jj += 2)
                h2split(h[jj], h[jj+1],
                        (__half2*)(Ahi + r*72 + kq + jj), (__half2*)(Alo + r*72 + kq + jj));
        }
        if (kq == 0) {
            #pragma unroll
            for (int f2 = 0; f2 < 8; f2 += 2)
                h2split(sXr[cur*1024 + r*8 + f2], sXr[cur*1024 + r*8 + f2 + 1],
                        (__half2*)(Ahi + r*72 + 64 + f2), (__half2*)(Alo + r*72 + 64 + f2));
        }
        __syncthreads();   // S1

        // prefetch x[t+1]
        if (t + 1 < Tt && tid < 256) {
            int row = tid >> 1, ch = tid & 1;
            int mm = m0 + row, b2 = mm / Nn, n2 = mm - b2 * Nn;
            CPA16(sb + GXR + ((1-cur)*1024 + row*8 + ch*4)*4,
                  &x[(((size_t)b2*Tt + (t+1))*Nn + n2)*Ff + ch*4]);
        }

        // ---- 3-pass hi/lo mma ----
        float acc1[2][4][4], acc2a[2][2][4], acc2b[2][2][4];
        #pragma unroll
        for (int i = 0; i < 2; i++) {
            #pragma unroll
            for (int j = 0; j < 4; j++)
                #pragma unroll
                for (int q = 0; q < 4; q++) acc1[i][j][q] = 0.f;
            #pragma unroll
            for (int j = 0; j < 2; j++)
                #pragma unroll
                for (int q = 0; q < 4; q++) { acc2a[i][j][q] = 0.f; acc2b[i][j][q] = 0.f; }
        }
        #pragma unroll
        for (int p = 0; p < 3; p++) {
            uint32_t aB  = sb + ((p == 1) ? GA_LO : GA_HI);
            uint32_t b1B = sb + GB1  + ((p == 2) ? 21504 : 0);
            uint32_t b2aB= sb + GB2A + ((p == 2) ? 3072  : 0);
            uint32_t b2bB= sb + GB2B + ((p == 2) ? 8704  : 0);
            #pragma unroll
            for (int ks = 0; ks < 5; ks++) {
                uint32_t afr[2][4];
                #pragma unroll
                for (int mt = 0; mt < 2; mt++)
                    ldmat4(afr[mt], aB + ((mw*32 + mt*16 + arow)*72 + ks*16 + acol8) * 2);
                #pragma unroll
                for (int nt = 0; nt < 4; nt++) {
                    int n = nw*32 + nt*8 + bn;
                    uint32_t bo = (b1B - sb) + (n*84 + ks*16 + bc2) * 2;
                    uint32_t b0 = *(const uint32_t*)(sm + bo);
                    uint32_t b1 = *(const uint32_t*)(sm + bo + 16);
                    mma16816(acc1[0][nt], afr[0], b0, b1);
                    mma16816(acc1[1][nt], afr[1], b0, b1);
                }
                if (ks == 4) {
                    #pragma unroll
                    for (int nt2 = 0; nt2 < 2; nt2++) {
                        int n2 = nw*16 + nt2*8 + bn;
                        uint32_t bo = (b2aB - sb) + (n2*24 + bc2) * 2;
                        uint32_t b0 = *(const uint32_t*)(sm + bo);
                        uint32_t b1 = *(const uint32_t*)(sm + bo + 16);
                        mma16816(acc2a[0][nt2], afr[0], b0, b1);
                        mma16816(acc2a[1][nt2], afr[1], b0, b1);
                    }
                } else {
                    #pragma unroll
                    for (int nt2 = 0; nt2 < 2; nt2++) {
                        int n2 = nw*16 + nt2*8 + bn;
                        uint32_t bo = (b2bB - sb) + (n2*68 + ks*16 + bc2) * 2;
                        uint32_t b0 = *(const uint32_t*)(sm + bo);
                        uint32_t b1 = *(const uint32_t*)(sm + bo + 16);
                        mma16816(acc2b[0][nt2], afr[0], b0, b1);
                        mma16816(acc2b[1][nt2], afr[1], b0, b1);
                    }
                }
            }
        }

        // ---- staging1: rz -> SE cols 0..127 ----
        #pragma unroll
        for (int mt = 0; mt < 2; mt++)
            #pragma unroll
            for (int q2 = 0; q2 < 2; q2++) {
                int row = mw*32 + mt*16 + g + q2*8;
                #pragma unroll
                for (int nt = 0; nt < 4; nt++) {
                    int col = nw*32 + nt*8 + c2;
                    *(float2*)&SE[row*130 + col] =
                        make_float2(acc1[mt][nt][q2*2], acc1[mt][nt][q2*2 + 1]);
                }
            }
        __syncthreads();   // S2

        // ---- gates-A: r,z (C from smem) ----
        float rg[16], zg[16];
        #pragma unroll
        for (int jj = 0; jj < 16; jj++) {
            int j = kq + jj;
            rg[jj] = sigf(SE[r*130 + j]      + __half2float(sC[r*200 + j]));
            zg[jj] = sigf(SE[r*130 + 64 + j] + __half2float(sC[r*200 + 64 + j]));
        }
        __syncthreads();   // S3

        // ---- staging2: xn -> SE 0..63, hn -> SE 64..127 ----
        #pragma unroll
        for (int mt = 0; mt < 2; mt++)
            #pragma unroll
            for (int q2 = 0; q2 < 2; q2++) {
                int row = mw*32 + mt*16 + g + q2*8;
                #pragma unroll
                for (int nt2 = 0; nt2 < 2; nt2++) {
                    int col = nw*16 + nt2*8 + c2;
                    *(float2*)&SE[row*130 + col] =
                        make_float2(acc2a[mt][nt2][q2*2], acc2a[mt][nt2][q2*2 + 1]);
                    *(float2*)&SE[row*130 + 64 + col] =
                        make_float2(acc2b[mt][nt2][q2*2], acc2b[mt][nt2][q2*2 + 1]);
                }
            }
        CPA_WAIT();
        __syncthreads();   // S4

        // ---- gates-B: n gate + h update ----
        #pragma unroll
        for (int jj = 0; jj < 16; jj++) {
            int j = kq + jj;
            float xn = SE[r*130 + j]      + __half2float(sC[r*200 + 128 + j]);
            float hn = SE[r*130 + 64 + j] + sBh[128 + j];
            float ng = tanhff(xn + rg[jj] * hn);
            h[jj] = (1.f - zg[jj]) * ng + zg[jj] * h[jj];
        }
    }

    // final h -> gmem (fp32 + fp16)
    {
        float4* dst = (float4*)(g_h0 + (size_t)m*Hh + kq);
        __half2* d16 = (__half2*)(g_h16 + (size_t)m*Hh + kq);
        #pragma unroll
        for (int q = 0; q < 4; q++) {
            dst[q] = make_float4(h[q*4], h[q*4+1], h[q*4+2], h[q*4+3]);
            d16[q*2]   = __halves2half2(__float2half_rn(h[q*4]),   __float2half_rn(h[q*4+1]));
            d16[q*2+1] = __halves2half2(__float2half_rn(h[q*4+2]), __float2half_rn(h[q*4+3]));
        }
    }
}

// ---------------- CSR build ----------------
__global__ void k_count(const float* __restrict__ ew) {
    int e = blockIdx.x * blockDim.x + threadIdx.x;
    if (e >= Ee) return;
    int s = g_src[e], t = g_tgt[e];
    float w = ew[e];
    atomicAdd(&g_cnt_f[t], 1);  atomicAdd(&g_deg_f[t], w);
    atomicAdd(&g_cnt_b[s], 1);  atomicAdd(&g_deg_b[s], w);
}
__global__ void k_scan() {
    __shared__ int sbuf[1024];
    __shared__ int sOff;
    int tid = threadIdx.x;
    for (int which = 0; which < 2; ++which) {
        const int* cnt = which ? g_cnt_b : g_cnt_f;
        int* rp        = which ? g_rowptr_b : g_rowptr_f;
        if (tid == 0) { sOff = 0; rp[0] = 0; }
        __syncthreads();
        for (int base = 0; base < Nn; base += 1024) {
            int i = base + tid;
            int v = (i < Nn) ? cnt[i] : 0;
            sbuf[tid] = v;
            __syncthreads();
            for (int d = 1; d < 1024; d <<= 1) {
                int add = (tid >= d) ? sbuf[tid - d] : 0;
                __syncthreads();
                sbuf[tid] += add;
                __syncthreads();
            }
            if (i < Nn) rp[i + 1] = sOff + sbuf[tid];
            __syncthreads();
            if (tid == 0) sOff += sbuf[1023];
            __syncthreads();
        }
        __syncthreads();
    }
}
__global__ void k_fill(const float* __restrict__ ew) {
    int e = blockIdx.x * blockDim.x + threadIdx.x;
    if (e >= Ee) return;
    int s = g_src[e], t = g_tgt[e];
    float w = ew[e];
    float df = g_deg_f[t]; df = (df == 0.f) ? 1.f : df;
    int pf = g_rowptr_f[t] + atomicAdd(&g_cur_f[t], 1);
    g_adjn_f[pf] = s;  g_adjw_f[pf] = w / df;
    float db = g_deg_b[s]; db = (db == 0.f) ? 1.f : db;
    int pb = g_rowptr_b[s] + atomicAdd(&g_cur_b[s], 1);
    g_adjn_b[pb] = t;  g_adjw_b[pb] = w / db;
}

// ---------------- diffusion props (fp16 gather, fp32 accumulate) ----------------
__device__ __forceinline__ void prop16(const __half* __restrict__ hin,
                                       float* __restrict__ outF, __half* __restrict__ outH,
                                       const int* __restrict__ rowptr,
                                       const int* __restrict__ adjn,
                                       const float* __restrict__ adjw,
                                       int node, int lane) {
    int beg = rowptr[node], end = rowptr[node + 1];
    float acc[Bb][2];
    #pragma unroll
    for (int b = 0; b < Bb; b++) { acc[b][0] = 0.f; acc[b][1] = 0.f; }
    for (int e = beg; e < end; e++) {
        int s = adjn[e];
        float w = adjw[e];
        #pragma unroll
        for (int b = 0; b < Bb; b++) {
            __half2 hv = ((const __half2*)(hin + ((size_t)b * Nn + s) * Hh))[lane];
            float2 f = __half22float2(hv);
            acc[b][0] += f.x * w;
            acc[b][1] += f.y * w;
        }
    }
    #pragma unroll
    for (int b = 0; b < Bb; b++) {
        size_t o = ((size_t)b * Nn + node) * Hh + 2*lane;
        *(float2*)&outF[o] = make_float2(acc[b][0], acc[b][1]);
        if (outH)
            *(__half2*)&outH[o] = __halves2half2(__float2half_rn(acc[b][0]),
                                                 __float2half_rn(acc[b][1]));
    }
}
__global__ void k_prop_h1() {
    int gw = (blockIdx.x * blockDim.x + threadIdx.x) >> 5;
    int lane = threadIdx.x & 31;
    if (gw >= 2*Nn) return;
    if (gw < Nn) prop16(g_h16, g_z0, g_z016, g_rowptr_f, g_adjn_f, g_adjw_f, gw, lane);
    else         prop16(g_h16, g_z2, g_z216, g_rowptr_b, g_adjn_b, g_adjw_b, gw - Nn, lane);
}
__global__ void k_prop_h2() {
    int gw = (blockIdx.x * blockDim.x + threadIdx.x) >> 5;
    int lane = threadIdx.x & 31;
    if (gw >= 2*Nn) return;
    if (gw < Nn) prop16(g_z016, g_z1, (__half*)0, g_rowptr_f, g_adjn_f, g_adjw_f, gw, lane);
    else         prop16(g_z216, g_z3, (__half*)0, g_rowptr_b, g_adjn_b, g_adjw_b, gw - Nn, lane);
}

// ---------------- fused filt+dec GEMM + permute ----------------
#define FIN_SMEM ((KCAT*CDEC + KCAT*65) * 4)
__global__ __launch_bounds__(256, 1)
void k_final(float* __restrict__ out) {
    extern __shared__ float smf[];
    float* sW = smf;
    float* sA = smf + KCAT*CDEC;
    int tid = threadIdx.x, m0 = blockIdx.x * 64;
    for (int idx = tid; idx < KCAT*CDEC; idx += 256) sW[idx] = g_W2[idx];
    const float* srcs[5] = { g_h0, g_z0, g_z1, g_z2, g_z3 };
    #pragma unroll
    for (int a = 0; a < 5; a++) {
        const float* S = srcs[a];
        for (int idx = tid; idx < 64*64; idx += 256) {
            int r = idx >> 6, k = idx & 63;
            sA[(a*64 + k)*65 + r] = S[(size_t)(m0 + r) * Hh + k];
        }
    }
    __syncthreads();
    int gc = tid & 31, rt = tid >> 5;
    float acc[8][3];
    #pragma unroll
    for (int i = 0; i < 8; i++)
        #pragma unroll
        for (int j = 0; j < 3; j++) acc[i][j] = 0.f;
    #pragma unroll 2
    for (int k = 0; k < KCAT; k++) {
        float av[8];
        #pragma unroll
        for (int i = 0; i < 8; i++) av[i] = sA[k*65 + rt*8 + i];
        float wv[3];
        #pragma unroll
        for (int j = 0; j < 3; j++) wv[j] = sW[k*CDEC + gc + 32*j];
        #pragma unroll
        for (int i = 0; i < 8; i++)
            #pragma unroll
            for (int j = 0; j < 3; j++) acc[i][j] += av[i] * wv[j];
    }
    #pragma unroll
    for (int i = 0; i < 8; i++) {
        int m = m0 + rt*8 + i;
        int b = m / Nn, n = m - b * Nn;
        #pragma unroll
        for (int j = 0; j < 3; j++) {
            int c = gc + 32*j;
            int tt = c >> 3, f = c & 7;
            out[(((size_t)b * HOR + tt) * Nn + n) * Ff + f] = acc[i][j] + g_b2[c];
        }
    }
}

// ---------------- launch ----------------
extern "C" void kernel_launch(void* const* d_in, const int* in_sizes, int n_in,
                              void* d_out, int out_size) {
    const float* x     = (const float*)d_in[0];
    const void*  ei    = d_in[1];
    const float* ew    = (const float*)d_in[2];
    const float* encW  = (const float*)d_in[3];
    const float* encB  = (const float*)d_in[4];
    const float* nemb  = (const float*)d_in[5];
    const float* Wih   = (const float*)d_in[6];
    const float* Whh   = (const float*)d_in[7];
    const float* bih   = (const float*)d_in[8];
    const float* bhh   = (const float*)d_in[9];
    const float* filtW = (const float*)d_in[10];
    const float* filtB = (const float*)d_in[11];
    const float* decW  = (const float*)d_in[12];
    const float* decB  = (const float*)d_in[13];
    float* out = (float*)d_out;

    cudaFuncSetAttribute(k_gru,   cudaFuncAttributeMaxDynamicSharedMemorySize, GRU_SMEM);
    cudaFuncSetAttribute(k_final, cudaFuncAttributeMaxDynamicSharedMemorySize, FIN_SMEM);

    k_detect<<<1, 1>>>((const unsigned int*)ei);
    k_convert<<<(Ee + 255) / 256, 256>>>(ei);
    k_zero<<<(Nn + 255) / 256, 256>>>();
    k_w2<<<KCAT + 1, CDEC>>>(filtW, filtB, decW, decB);
    k_wprime<<<6, 256>>>(encW, Wih);
    k_cnode<<<Nn/16, 192>>>(encB, nemb, Wih, bih, bhh);
    k_prepw<<<(33280 + 255) / 256, 256>>>(Whh);
    k_bias<<<1, 192>>>(bhh);

    k_gru<<<Mm / 128, 512, GRU_SMEM>>>(x);

    k_count<<<(Ee + 255) / 256, 256>>>(ew);
    k_scan<<<1, 1024>>>();
    k_fill<<<(Ee + 255) / 256, 256>>>(ew);
    k_prop_h1<<<(2*Nn*32 + 255) / 256, 256>>>();
    k_prop_h2<<<(2*Nn*32 + 255) / 256, 256>>>();

    k_final<<<Mm / 64, 256, FIN_SMEM>>>(out);
}

// round 11
// speedup vs baseline: 1.6541x; 1.1355x over previous
#include <cuda_runtime.h>
#include <cuda_fp16.h>
#include <math.h>
#include <stdint.h>

#define Nn   10000
#define Bb   8
#define Tt   12
#define Ff   8
#define Hh   64
#define Ee   320000
#define HOR  12
#define Mm   (Bb*Nn)
#define KCAT 320
#define CDEC 96

// ---------------- device scratch ----------------
__device__ float g_h0[Mm*Hh];
__device__ float g_z0[Mm*Hh];
__device__ float g_z1[Mm*Hh];
__device__ float g_z2[Mm*Hh];
__device__ float g_z3[Mm*Hh];
__device__ __half g_h16[Mm*Hh];
__device__ __half g_z016[Mm*Hh];
__device__ __half g_z216[Mm*Hh];
__device__ int   g_src[Ee], g_tgt[Ee];
__device__ int   g_rowptr_f[Nn+1], g_rowptr_b[Nn+1];
__device__ int   g_cnt_f[Nn], g_cnt_b[Nn], g_cur_f[Nn], g_cur_b[Nn];
__device__ float g_deg_f[Nn], g_deg_b[Nn];
__device__ int   g_adjn_f[Ee]; __device__ float g_adjw_f[Ee];
__device__ int   g_adjn_b[Ee]; __device__ float g_adjw_b[Ee];
__device__ float g_W2[KCAT*CDEC];
__device__ float g_b2[CDEC];
__device__ int   g_flag64;
__device__ float g_Wp[192*8];                   // W' = encW@Wih
__device__ __half g_Cnode16[(size_t)Nn*192];    // C[n][g] fp16 (bih + bhh_rz folded)

// fp16 hi/lo weight images (zero-padded k-overhang)
__device__ __half g_B1Img [2*128*84];   // rz: k<64 Whh, 64..71 W', 72..83 zero
__device__ __half g_B2aImg[2*64*24];    // xn: k<8 W'_n, 8..23 zero
__device__ __half g_B2bImg[2*64*68];    // hn: k<64 Whh_n, 64..67 zero
__device__ __half g_W2h[2*96*360];      // k_final W2 image: [prec][96 n][5 c][72 k]

// ---------------- helpers ----------------
__device__ __forceinline__ uint32_t smem_u32(const void* p) {
    uint32_t a;
    asm("{ .reg .u64 t; cvta.to.shared.u64 t, %1; cvt.u32.u64 %0, t; }" : "=r"(a) : "l"(p));
    return a;
}
__device__ __forceinline__ void ldmat4(uint32_t* f, uint32_t addr) {
    asm volatile("ldmatrix.sync.aligned.m8n8.x4.shared.b16 {%0,%1,%2,%3}, [%4];"
        : "=r"(f[0]), "=r"(f[1]), "=r"(f[2]), "=r"(f[3]) : "r"(addr));
}
__device__ __forceinline__ void mma16816(float* c, const uint32_t* a, uint32_t b0, uint32_t b1) {
    asm volatile("mma.sync.aligned.m16n8k16.row.col.f32.f16.f16.f32 "
        "{%0,%1,%2,%3}, {%4,%5,%6,%7}, {%8,%9}, {%0,%1,%2,%3};"
        : "+f"(c[0]), "+f"(c[1]), "+f"(c[2]), "+f"(c[3])
        : "r"(a[0]), "r"(a[1]), "r"(a[2]), "r"(a[3]), "r"(b0), "r"(b1));
}
#define CPA16(sa, gp) asm volatile("cp.async.cg.shared.global [%0], [%1], 16;" :: "r"(sa), "l"(gp))
#define CPA_WAIT()    asm volatile("cp.async.wait_all;" ::: "memory")
__device__ __forceinline__ float sigf(float x)  { return 1.f / (1.f + __expf(-x)); }
__device__ __forceinline__ float tanhff(float x){ float e = __expf(2.f*x); return 1.f - 2.f/(e + 1.f); }
__device__ __forceinline__ void h2split(float v0, float v1, __half2* hi, __half2* lo) {
    __half a = __float2half_rn(v0), b = __float2half_rn(v1);
    *hi = __halves2half2(a, b);
    *lo = __halves2half2(__float2half_rn(v0 - __half2float(a)),
                         __float2half_rn(v1 - __half2float(b)));
}

// ---------------- small prep kernels ----------------
__global__ void k_detect(const unsigned int* ei_raw) {
    bool all0 = true;
    for (int i = 0; i < 16; i++) if (ei_raw[2*i + 1] != 0u) all0 = false;
    g_flag64 = all0 ? 1 : 0;
}
__global__ void k_convert(const void* ei) {
    int e = blockIdx.x * blockDim.x + threadIdx.x;
    if (e >= Ee) return;
    if (g_flag64) {
        const long long* p = (const long long*)ei;
        g_src[e] = (int)p[e]; g_tgt[e] = (int)p[Ee + e];
    } else {
        const int* p = (const int*)ei;
        g_src[e] = p[e]; g_tgt[e] = p[Ee + e];
    }
}
__global__ void k_zero() {
    int i = blockIdx.x * blockDim.x + threadIdx.x;
    if (i < Nn) {
        g_cnt_f[i] = 0; g_cnt_b[i] = 0; g_cur_f[i] = 0; g_cur_b[i] = 0;
        g_deg_f[i] = 0.f; g_deg_b[i] = 0.f;
    }
}
__global__ void k_w2(const float* __restrict__ filtW, const float* __restrict__ filtB,
                     const float* __restrict__ decW,  const float* __restrict__ decB) {
    int c = threadIdx.x, k = blockIdx.x;
    if (k < KCAT) {
        float acc = 0.f;
        for (int j = 0; j < Hh; j++) acc += filtW[k*Hh + j] * decW[j*CDEC + c];
        g_W2[k*CDEC + c] = acc;
    } else {
        float acc = decB[c];
        for (int j = 0; j < Hh; j++) acc += filtB[j] * decW[j*CDEC + c];
        g_b2[c] = acc;
    }
}
// W2 fp16 hi/lo image [prec][96][5][72]
__global__ void k_w2img() {
    int idx = blockIdx.x * blockDim.x + threadIdx.x;
    if (idx >= 2*96*360) return;
    int prec = idx / 34560, rem = idx % 34560;
    int n = rem / 360, q = rem % 360;
    int c = q / 72, k = q % 72;
    float val = (k < 64) ? g_W2[(c*64 + k)*CDEC + n] : 0.f;
    __half hi = __float2half_rn(val);
    g_W2h[idx] = prec ? __float2half_rn(val - __half2float(hi)) : hi;
}
__global__ void k_wprime(const float* __restrict__ encW, const float* __restrict__ Wih) {
    int idx = blockIdx.x * blockDim.x + threadIdx.x;
    if (idx >= 192*8) return;
    int g = idx >> 3, f = idx & 7;
    float acc = 0.f;
    for (int h = 0; h < 64; h++) acc += encW[f*64 + h] * Wih[g*64 + h];
    g_Wp[g*8 + f] = acc;
}
__global__ __launch_bounds__(192)
void k_cnode(const float* __restrict__ encB, const float* __restrict__ nodeEmb,
             const float* __restrict__ Wih,  const float* __restrict__ bih,
             const float* __restrict__ bhh) {
    __shared__ float sEB[16][68];
    int tid = threadIdx.x, n0 = blockIdx.x * 16;
    for (int i = tid; i < 16*64; i += 192) {
        int nl = i >> 6, k = i & 63;
        sEB[nl][k] = encB[k] + nodeEmb[(n0 + nl)*64 + k];
    }
    __syncthreads();
    int c = tid;
    float w[64];
    #pragma unroll
    for (int k = 0; k < 64; k++) w[k] = Wih[c*64 + k];
    float bb = bih[c] + ((c < 128) ? bhh[c] : 0.f);
    for (int nl = 0; nl < 16; nl++) {
        float acc = bb;
        #pragma unroll
        for (int k = 0; k < 64; k++) acc += sEB[nl][k] * w[k];
        g_Cnode16[(size_t)(n0 + nl)*192 + c] = __float2half_rn(acc);
    }
}
__global__ void k_prepw(const float* __restrict__ Whh) {
    int idx = blockIdx.x * blockDim.x + threadIdx.x;
    if (idx >= 33280) return;
    float val = 0.f; __half* dst;
    if (idx < 21504) {
        int rem = idx % 10752;
        int n = rem / 84, k = rem % 84;
        if (k < 64)      val = Whh[n*64 + k];
        else if (k < 72) val = g_Wp[n*8 + (k - 64)];
        dst = &g_B1Img[idx];
        int prec = idx / 10752;
        __half hi = __float2half_rn(val);
        *dst = prec ? __float2half_rn(val - __half2float(hi)) : hi;
        return;
    }
    if (idx < 24576) {
        int q = idx - 21504;
        int prec = q / 1536; int rem = q % 1536;
        int n = rem / 24, k = rem % 24;
        if (k < 8) val = g_Wp[(128 + n)*8 + k];
        dst = &g_B2aImg[q];
        __half hi = __float2half_rn(val);
        *dst = prec ? __float2half_rn(val - __half2float(hi)) : hi;
        return;
    }
    {
        int q = idx - 24576;
        int prec = q / 4352; int rem = q % 4352;
        int n = rem / 68, k = rem % 68;
        if (k < 64) val = Whh[(128 + n)*64 + k];
        dst = &g_B2bImg[q];
        __half hi = __float2half_rn(val);
        *dst = prec ? __float2half_rn(val - __half2float(hi)) : hi;
    }
}

// ================= fused 12-step GRU (unchanged from R10 winner) =================
#define GA_HI  0
#define GA_LO  18432
#define GB1    36864
#define GB2A   79872
#define GB2B   86016
#define GSE    103424
#define GC16   169984
#define GXR    221184
#define GBIAS  229376
#define GRU_SMEM 230144

__global__ __launch_bounds__(512, 1)
void k_gru(const float* __restrict__ x, const float* __restrict__ bhh)
{
    extern __shared__ __align__(16) char sm[];
    __half* Ahi = (__half*)(sm + GA_HI);
    __half* Alo = (__half*)(sm + GA_LO);
    float*  SE  = (float*)(sm + GSE);       // [128][130]
    __half* sC  = (__half*)(sm + GC16);     // [128][200] (192 used)
    float*  sXr = (float*)(sm + GXR);
    float*  sBh = (float*)(sm + GBIAS);

    int tid = threadIdx.x, lane = tid & 31, wid = tid >> 5;
    int mw = wid & 3, nw = wid >> 2;
    int m0 = blockIdx.x * 128;

    {
        const uint4* s1 = (const uint4*)g_B1Img;  uint4* d1 = (uint4*)(sm + GB1);
        for (int i = tid; i < 43008/16; i += 512) d1[i] = s1[i];
        const uint4* s2 = (const uint4*)g_B2aImg; uint4* d2 = (uint4*)(sm + GB2A);
        if (tid < 6144/16) d2[tid] = s2[tid];
        const uint4* s3 = (const uint4*)g_B2bImg; uint4* d3 = (uint4*)(sm + GB2B);
        for (int i = tid; i < 17408/16; i += 512) d3[i] = s3[i];
        float4* a4 = (float4*)(sm + GA_HI);
        for (int i = tid; i < 36864/16; i += 512) a4[i] = make_float4(0.f,0.f,0.f,0.f);
        for (int i = tid; i < 3072; i += 512) {
            int row = i / 24, ch = i % 24;
            int node = (m0 + row) % Nn;
            const uint4* srcc = (const uint4*)(g_Cnode16 + (size_t)node*192) + ch;
            *((uint4*)(sC + row*200) + ch) = *srcc;
        }
    }
    if (tid < 192) sBh[tid] = bhh[tid];

    int r  = tid >> 2;
    int kq = (tid & 3) * 16;
    int m  = m0 + r;
    uint32_t sb = smem_u32(sm);

    if (tid < 256) {
        int row = tid >> 1, ch = tid & 1;
        int mm = m0 + row, b2 = mm / Nn, n2 = mm - b2 * Nn;
        CPA16(sb + GXR + (row*8 + ch*4)*4, &x[(((size_t)b2*Tt + 0)*Nn + n2)*Ff + ch*4]);
    }
    CPA_WAIT();
    __syncthreads();

    float h[16];
    #pragma unroll
    for (int i = 0; i < 16; i++) h[i] = 0.f;

    int arow = lane & 15, acol8 = (lane >> 4) * 8;
    int bn = lane >> 2, bc2 = 2 * (lane & 3);
    int g = lane >> 2, c2 = 2 * (lane & 3);

    for (int t = 0; t < Tt; t++) {
        int cur = t & 1;
        if (t > 0) {
            #pragma unroll
            for (int jj = 0; jj < 16; jj += 2)
                h2split(h[jj], h[jj+1],
                        (__half2*)(Ahi + r*72 + kq + jj), (__half2*)(Alo + r*72 + kq + jj));
        }
        if (kq == 0) {
            #pragma unroll
            for (int f2 = 0; f2 < 8; f2 += 2)
                h2split(sXr[cur*1024 + r*8 + f2], sXr[cur*1024 + r*8 + f2 + 1],
                        (__half2*)(Ahi + r*72 + 64 + f2), (__half2*)(Alo + r*72 + 64 + f2));
        }
        __syncthreads();   // S1

        if (t + 1 < Tt && tid < 256) {
            int row = tid >> 1, ch = tid & 1;
            int mm = m0 + row, b2 = mm / Nn, n2 = mm - b2 * Nn;
            CPA16(sb + GXR + ((1-cur)*1024 + row*8 + ch*4)*4,
                  &x[(((size_t)b2*Tt + (t+1))*Nn + n2)*Ff + ch*4]);
        }

        float acc1[2][4][4], acc2a[2][2][4], acc2b[2][2][4];
        #pragma unroll
        for (int i = 0; i < 2; i++) {
            #pragma unroll
            for (int j = 0; j < 4; j++)
                #pragma unroll
                for (int q = 0; q < 4; q++) acc1[i][j][q] = 0.f;
            #pragma unroll
            for (int j = 0; j < 2; j++)
                #pragma unroll
                for (int q = 0; q < 4; q++) { acc2a[i][j][q] = 0.f; acc2b[i][j][q] = 0.f; }
        }
        #pragma unroll
        for (int p = 0; p < 3; p++) {
            uint32_t aB  = sb + ((p == 1) ? GA_LO : GA_HI);
            uint32_t b1B = sb + GB1  + ((p == 2) ? 21504 : 0);
            uint32_t b2aB= sb + GB2A + ((p == 2) ? 3072  : 0);
            uint32_t b2bB= sb + GB2B + ((p == 2) ? 8704  : 0);
            #pragma unroll
            for (int ks = 0; ks < 5; ks++) {
                uint32_t afr[2][4];
                #pragma unroll
                for (int mt = 0; mt < 2; mt++)
                    ldmat4(afr[mt], aB + ((mw*32 + mt*16 + arow)*72 + ks*16 + acol8) * 2);
                #pragma unroll
                for (int nt = 0; nt < 4; nt++) {
                    int n = nw*32 + nt*8 + bn;
                    uint32_t bo = (b1B - sb) + (n*84 + ks*16 + bc2) * 2;
                    uint32_t b0 = *(const uint32_t*)(sm + bo);
                    uint32_t b1 = *(const uint32_t*)(sm + bo + 16);
                    mma16816(acc1[0][nt], afr[0], b0, b1);
                    mma16816(acc1[1][nt], afr[1], b0, b1);
                }
                if (ks == 4) {
                    #pragma unroll
                    for (int nt2 = 0; nt2 < 2; nt2++) {
                        int n2 = nw*16 + nt2*8 + bn;
                        uint32_t bo = (b2aB - sb) + (n2*24 + bc2) * 2;
                        uint32_t b0 = *(const uint32_t*)(sm + bo);
                        uint32_t b1 = *(const uint32_t*)(sm + bo + 16);
                        mma16816(acc2a[0][nt2], afr[0], b0, b1);
                        mma16816(acc2a[1][nt2], afr[1], b0, b1);
                    }
                } else {
                    #pragma unroll
                    for (int nt2 = 0; nt2 < 2; nt2++) {
                        int n2 = nw*16 + nt2*8 + bn;
                        uint32_t bo = (b2bB - sb) + (n2*68 + ks*16 + bc2) * 2;
                        uint32_t b0 = *(const uint32_t*)(sm + bo);
                        uint32_t b1 = *(const uint32_t*)(sm + bo + 16);
                        mma16816(acc2b[0][nt2], afr[0], b0, b1);
                        mma16816(acc2b[1][nt2], afr[1], b0, b1);
                    }
                }
            }
        }

        #pragma unroll
        for (int mt = 0; mt < 2; mt++)
            #pragma unroll
            for (int q2 = 0; q2 < 2; q2++) {
                int row = mw*32 + mt*16 + g + q2*8;
                #pragma unroll
                for (int nt = 0; nt < 4; nt++) {
                    int col = nw*32 + nt*8 + c2;
                    *(float2*)&SE[row*130 + col] =
                        make_float2(acc1[mt][nt][q2*2], acc1[mt][nt][q2*2 + 1]);
                }
            }
        __syncthreads();   // S2

        float rg[16], zg[16];
        #pragma unroll
        for (int jj = 0; jj < 16; jj++) {
            int j = kq + jj;
            rg[jj] = sigf(SE[r*130 + j]      + __half2float(sC[r*200 + j]));
            zg[jj] = sigf(SE[r*130 + 64 + j] + __half2float(sC[r*200 + 64 + j]));
        }
        __syncthreads();   // S3

        #pragma unroll
        for (int mt = 0; mt < 2; mt++)
            #pragma unroll
            for (int q2 = 0; q2 < 2; q2++) {
                int row = mw*32 + mt*16 + g + q2*8;
                #pragma unroll
                for (int nt2 = 0; nt2 < 2; nt2++) {
                    int col = nw*16 + nt2*8 + c2;
                    *(float2*)&SE[row*130 + col] =
                        make_float2(acc2a[mt][nt2][q2*2], acc2a[mt][nt2][q2*2 + 1]);
                    *(float2*)&SE[row*130 + 64 + col] =
                        make_float2(acc2b[mt][nt2][q2*2], acc2b[mt][nt2][q2*2 + 1]);
                }
            }
        CPA_WAIT();
        __syncthreads();   // S4

        #pragma unroll
        for (int jj = 0; jj < 16; jj++) {
            int j = kq + jj;
            float xn = SE[r*130 + j]      + __half2float(sC[r*200 + 128 + j]);
            float hn = SE[r*130 + 64 + j] + sBh[128 + j];
            float ng = tanhff(xn + rg[jj] * hn);
            h[jj] = (1.f - zg[jj]) * ng + zg[jj] * h[jj];
        }
    }

    {
        float4* dst = (float4*)(g_h0 + (size_t)m*Hh + kq);
        __half2* d16 = (__half2*)(g_h16 + (size_t)m*Hh + kq);
        #pragma unroll
        for (int q = 0; q < 4; q++) {
            dst[q] = make_float4(h[q*4], h[q*4+1], h[q*4+2], h[q*4+3]);
            d16[q*2]   = __halves2half2(__float2half_rn(h[q*4]),   __float2half_rn(h[q*4+1]));
            d16[q*2+1] = __halves2half2(__float2half_rn(h[q*4+2]), __float2half_rn(h[q*4+3]));
        }
    }
}

// ---------------- CSR build ----------------
__global__ void k_count(const float* __restrict__ ew) {
    int e = blockIdx.x * blockDim.x + threadIdx.x;
    if (e >= Ee) return;
    int s = g_src[e], t = g_tgt[e];
    float w = ew[e];
    atomicAdd(&g_cnt_f[t], 1);  atomicAdd(&g_deg_f[t], w);
    atomicAdd(&g_cnt_b[s], 1);  atomicAdd(&g_deg_b[s], w);
}
__global__ void k_scan() {
    __shared__ int sbuf[1024];
    __shared__ int sOff;
    int tid = threadIdx.x;
    for (int which = 0; which < 2; ++which) {
        const int* cnt = which ? g_cnt_b : g_cnt_f;
        int* rp        = which ? g_rowptr_b : g_rowptr_f;
        if (tid == 0) { sOff = 0; rp[0] = 0; }
        __syncthreads();
        for (int base = 0; base < Nn; base += 1024) {
            int i = base + tid;
            int v = (i < Nn) ? cnt[i] : 0;
            sbuf[tid] = v;
            __syncthreads();
            for (int d = 1; d < 1024; d <<= 1) {
                int add = (tid >= d) ? sbuf[tid - d] : 0;
                __syncthreads();
                sbuf[tid] += add;
                __syncthreads();
            }
            if (i < Nn) rp[i + 1] = sOff + sbuf[tid];
            __syncthreads();
            if (tid == 0) sOff += sbuf[1023];
            __syncthreads();
        }
        __syncthreads();
    }
}
__global__ void k_fill(const float* __restrict__ ew) {
    int e = blockIdx.x * blockDim.x + threadIdx.x;
    if (e >= Ee) return;
    int s = g_src[e], t = g_tgt[e];
    float w = ew[e];
    float df = g_deg_f[t]; df = (df == 0.f) ? 1.f : df;
    int pf = g_rowptr_f[t] + atomicAdd(&g_cur_f[t], 1);
    g_adjn_f[pf] = s;  g_adjw_f[pf] = w / df;
    float db = g_deg_b[s]; db = (db == 0.f) ? 1.f : db;
    int pb = g_rowptr_b[s] + atomicAdd(&g_cur_b[s], 1);
    g_adjn_b[pb] = t;  g_adjw_b[pb] = w / db;
}

// ---------------- diffusion props (fp16 gather, fp32 accumulate) ----------------
__device__ __forceinline__ void prop16(const __half* __restrict__ hin,
                                       float* __restrict__ outF, __half* __restrict__ outH,
                                       const int* __restrict__ rowptr,
                                       const int* __restrict__ adjn,
                                       const float* __restrict__ adjw,
                                       int node, int lane) {
    int beg = rowptr[node], end = rowptr[node + 1];
    float acc[Bb][2];
    #pragma unroll
    for (int b = 0; b < Bb; b++) { acc[b][0] = 0.f; acc[b][1] = 0.f; }
    for (int e = beg; e < end; e++) {
        int s = adjn[e];
        float w = adjw[e];
        #pragma unroll
        for (int b = 0; b < Bb; b++) {
            __half2 hv = ((const __half2*)(hin + ((size_t)b * Nn + s) * Hh))[lane];
            float2 f = __half22float2(hv);
            acc[b][0] += f.x * w;
            acc[b][1] += f.y * w;
        }
    }
    #pragma unroll
    for (int b = 0; b < Bb; b++) {
        size_t o = ((size_t)b * Nn + node) * Hh + 2*lane;
        *(float2*)&outF[o] = make_float2(acc[b][0], acc[b][1]);
        if (outH)
            *(__half2*)&outH[o] = __halves2half2(__float2half_rn(acc[b][0]),
                                                 __float2half_rn(acc[b][1]));
    }
}
__global__ void k_prop_h1() {
    int gw = (blockIdx.x * blockDim.x + threadIdx.x) >> 5;
    int lane = threadIdx.x & 31;
    if (gw >= 2*Nn) return;
    if (gw < Nn) prop16(g_h16, g_z0, g_z016, g_rowptr_f, g_adjn_f, g_adjw_f, gw, lane);
    else         prop16(g_h16, g_z2, g_z216, g_rowptr_b, g_adjn_b, g_adjw_b, gw - Nn, lane);
}
__global__ void k_prop_h2() {
    int gw = (blockIdx.x * blockDim.x + threadIdx.x) >> 5;
    int lane = threadIdx.x & 31;
    if (gw >= 2*Nn) return;
    if (gw < Nn) prop16(g_z016, g_z1, (__half*)0, g_rowptr_f, g_adjn_f, g_adjw_f, gw, lane);
    else         prop16(g_z216, g_z3, (__half*)0, g_rowptr_b, g_adjn_b, g_adjw_b, gw - Nn, lane);
}

// ---------------- k_final: HMMA 3-pass hi/lo, M=64/block, K=320 (5 chunks), N=96 ----------------
// smem: W img [prec][96][360]h @0 (138240B), A hi/lo [64][72]h @138240 (18432B)
#define FB_A     138240
#define FIN_SMEM 156672

__global__ __launch_bounds__(256, 1)
void k_final(float* __restrict__ out) {
    extern __shared__ __align__(16) char sm[];
    __half* Ahi = (__half*)(sm + FB_A);
    __half* Alo = Ahi + 64*72;

    int tid = threadIdx.x, lane = tid & 31, wid = tid >> 5;
    int mw = wid & 1, nw = wid >> 1;
    int m0 = blockIdx.x * 64;

    {
        const uint4* sw = (const uint4*)g_W2h;
        uint4* dw = (uint4*)sm;
        for (int i = tid; i < 138240/16; i += 256) dw[i] = sw[i];
    }

    int r = tid >> 2, kq = (tid & 3) * 16;
    int arow = lane & 15, acol8 = (lane >> 4) * 8;
    int bn = lane >> 2, bc2 = 2 * (lane & 3);

    float acc[2][3][4];
    #pragma unroll
    for (int i = 0; i < 2; i++)
        #pragma unroll
        for (int j = 0; j < 3; j++)
            #pragma unroll
            for (int q = 0; q < 4; q++) acc[i][j][q] = 0.f;

    uint32_t sb = smem_u32(sm);
    const float* srcs[5] = { g_h0, g_z0, g_z1, g_z2, g_z3 };

    for (int c = 0; c < 5; c++) {
        __syncthreads();   // protect A buf (and W load on first iter)
        const float* S = srcs[c] + (size_t)(m0 + r)*64 + kq;
        #pragma unroll
        for (int j = 0; j < 16; j += 2)
            h2split(S[j], S[j+1],
                    (__half2*)(Ahi + r*72 + kq + j), (__half2*)(Alo + r*72 + kq + j));
        __syncthreads();

        #pragma unroll
        for (int p = 0; p < 3; p++) {
            uint32_t aB = sb + FB_A + ((p == 1) ? 64*72*2 : 0);
            uint32_t wB = (p == 2) ? (uint32_t)(34560*2) : 0u;   // byte offset into W img
            #pragma unroll
            for (int ks = 0; ks < 4; ks++) {
                uint32_t afr[2][4];
                #pragma unroll
                for (int mt = 0; mt < 2; mt++)
                    ldmat4(afr[mt], aB + ((mw*32 + mt*16 + arow)*72 + ks*16 + acol8) * 2);
                #pragma unroll
                for (int nt = 0; nt < 3; nt++) {
                    int n = nw*24 + nt*8 + bn;
                    uint32_t bo = wB + ((n*360 + c*72 + ks*16 + bc2) * 2);
                    uint32_t b0 = *(const uint32_t*)(sm + bo);
                    uint32_t b1 = *(const uint32_t*)(sm + bo + 16);
                    mma16816(acc[0][nt], afr[0], b0, b1);
                    mma16816(acc[1][nt], afr[1], b0, b1);
                }
            }
        }
    }

    // epilogue: direct permuted store + bias
    int g = lane >> 2, c2 = 2 * (lane & 3);
    #pragma unroll
    for (int mt = 0; mt < 2; mt++)
        #pragma unroll
        for (int q2 = 0; q2 < 2; q2++) {
            int row = mw*32 + mt*16 + g + q2*8;
            int m = m0 + row, b = m / Nn, n = m - b * Nn;
            #pragma unroll
            for (int nt = 0; nt < 3; nt++) {
                int col = nw*24 + nt*8 + c2;
                int tt = col >> 3, f = col & 7;
                float2 v = make_float2(acc[mt][nt][q2*2]     + __ldg(&g_b2[col]),
                                       acc[mt][nt][q2*2 + 1] + __ldg(&g_b2[col + 1]));
                *(float2*)&out[(((size_t)b * HOR + tt) * Nn + n) * Ff + f] = v;
            }
        }
}

// ---------------- launch (k_gru at index 3 for ncu capture) ----------------
extern "C" void kernel_launch(void* const* d_in, const int* in_sizes, int n_in,
                              void* d_out, int out_size) {
    const float* x     = (const float*)d_in[0];
    const void*  ei    = d_in[1];
    const float* ew    = (const float*)d_in[2];
    const float* encW  = (const float*)d_in[3];
    const float* encB  = (const float*)d_in[4];
    const float* nemb  = (const float*)d_in[5];
    const float* Wih   = (const float*)d_in[6];
    const float* Whh   = (const float*)d_in[7];
    const float* bih   = (const float*)d_in[8];
    const float* bhh   = (const float*)d_in[9];
    const float* filtW = (const float*)d_in[10];
    const float* filtB = (const float*)d_in[11];
    const float* decW  = (const float*)d_in[12];
    const float* decB  = (const float*)d_in[13];
    float* out = (float*)d_out;

    cudaFuncSetAttribute(k_gru,   cudaFuncAttributeMaxDynamicSharedMemorySize, GRU_SMEM);
    cudaFuncSetAttribute(k_final, cudaFuncAttributeMaxDynamicSharedMemorySize, FIN_SMEM);

    k_wprime<<<6, 256>>>(encW, Wih);                       // 0
    k_cnode<<<Nn/16, 192>>>(encB, nemb, Wih, bih, bhh);    // 1
    k_prepw<<<(33280 + 255) / 256, 256>>>(Whh);            // 2
    k_gru<<<Mm / 128, 512, GRU_SMEM>>>(x, bhh);            // 3  <- ncu captures this
    k_detect<<<1, 1>>>((const unsigned int*)ei);           // 4
    k_convert<<<(Ee + 255) / 256, 256>>>(ei);              // 5
    k_zero<<<(Nn + 255) / 256, 256>>>();                   // 6
    k_w2<<<KCAT + 1, CDEC>>>(filtW, filtB, decW, decB);    // 7
    k_w2img<<<(2*96*360 + 255) / 256, 256>>>();            // 8
    k_count<<<(Ee + 255) / 256, 256>>>(ew);                // 9
    k_scan<<<1, 1024>>>();                                 // 10
    k_fill<<<(Ee + 255) / 256, 256>>>(ew);                 // 11
    k_prop_h1<<<(2*Nn*32 + 255) / 256, 256>>>();           // 12
    k_prop_h2<<<(2*Nn*32 + 255) / 256, 256>>>();           // 13
    k_final<<<Mm / 64, 256, FIN_SMEM>>>(out);              // 14
}

// round 12
// speedup vs baseline: 2.0236x; 1.2233x over previous
#include <cuda_runtime.h>
#include <cuda_fp16.h>
#include <math.h>
#include <stdint.h>

#define Nn   10000
#define Bb   8
#define Tt   12
#define Ff   8
#define Hh   64
#define Ee   320000
#define HOR  12
#define Mm   (Bb*Nn)
#define KCAT 320
#define CDEC 96

// ---------------- device scratch ----------------
__device__ float g_h0[Mm*Hh];
__device__ float g_z0[Mm*Hh];
__device__ float g_z1[Mm*Hh];
__device__ float g_z2[Mm*Hh];
__device__ float g_z3[Mm*Hh];
__device__ __half g_h16[Mm*Hh];
__device__ __half g_z016[Mm*Hh];
__device__ __half g_z216[Mm*Hh];
__device__ int   g_src[Ee], g_tgt[Ee];
__device__ int   g_rowptr_f[Nn+1], g_rowptr_b[Nn+1];
__device__ int   g_cnt_f[Nn], g_cnt_b[Nn], g_cur_f[Nn], g_cur_b[Nn];
__device__ float g_deg_f[Nn], g_deg_b[Nn];
__device__ int   g_adjn_f[Ee]; __device__ float g_adjw_f[Ee];
__device__ int   g_adjn_b[Ee]; __device__ float g_adjw_b[Ee];
__device__ float g_W2[KCAT*CDEC];
__device__ float g_b2[CDEC];
__device__ int   g_flag64;
__device__ float g_Wp[192*8];                   // W' = encW@Wih
__device__ __half g_Cnode16[(size_t)Nn*192];    // C[n][g] fp16 (bih + bhh_rz folded)

// fp16 hi/lo weight images (zero-padded k-overhang) — unchanged layouts
__device__ __half g_B1Img [2*128*84];   // rz: rows 0..63 r, 64..127 z; k<64 Whh, 64..71 W', 72..83 zero
__device__ __half g_B2aImg[2*64*24];    // xn: k<8 W'_n, 8..23 zero
__device__ __half g_B2bImg[2*64*68];    // hn: k<64 Whh_n, 64..67 zero
__device__ __half g_W2h[2*96*360];      // k_final W2 image: [prec][96 n][5 c][72 k]

// ---------------- helpers ----------------
__device__ __forceinline__ uint32_t smem_u32(const void* p) {
    uint32_t a;
    asm("{ .reg .u64 t; cvta.to.shared.u64 t, %1; cvt.u32.u64 %0, t; }" : "=r"(a) : "l"(p));
    return a;
}
__device__ __forceinline__ void ldmat4(uint32_t* f, uint32_t addr) {
    asm volatile("ldmatrix.sync.aligned.m8n8.x4.shared.b16 {%0,%1,%2,%3}, [%4];"
        : "=r"(f[0]), "=r"(f[1]), "=r"(f[2]), "=r"(f[3]) : "r"(addr));
}
__device__ __forceinline__ void mma16816(float* c, const uint32_t* a, uint32_t b0, uint32_t b1) {
    asm volatile("mma.sync.aligned.m16n8k16.row.col.f32.f16.f16.f32 "
        "{%0,%1,%2,%3}, {%4,%5,%6,%7}, {%8,%9}, {%0,%1,%2,%3};"
        : "+f"(c[0]), "+f"(c[1]), "+f"(c[2]), "+f"(c[3])
        : "r"(a[0]), "r"(a[1]), "r"(a[2]), "r"(a[3]), "r"(b0), "r"(b1));
}
#define CPA16(sa, gp) asm volatile("cp.async.cg.shared.global [%0], [%1], 16;" :: "r"(sa), "l"(gp))
#define CPA_WAIT()    asm volatile("cp.async.wait_all;" ::: "memory")
__device__ __forceinline__ float sigf(float x)  { return 1.f / (1.f + __expf(-x)); }
__device__ __forceinline__ float tanhff(float x){ float e = __expf(2.f*x); return 1.f - 2.f/(e + 1.f); }
__device__ __forceinline__ void h2split(float v0, float v1, __half2* hi, __half2* lo) {
    __half a = __float2half_rn(v0), b = __float2half_rn(v1);
    *hi = __halves2half2(a, b);
    *lo = __halves2half2(__float2half_rn(v0 - __half2float(a)),
                         __float2half_rn(v1 - __half2float(b)));
}

// ---------------- small prep kernels (unchanged) ----------------
__global__ void k_detect(const unsigned int* ei_raw) {
    bool all0 = true;
    for (int i = 0; i < 16; i++) if (ei_raw[2*i + 1] != 0u) all0 = false;
    g_flag64 = all0 ? 1 : 0;
}
__global__ void k_convert(const void* ei) {
    int e = blockIdx.x * blockDim.x + threadIdx.x;
    if (e >= Ee) return;
    if (g_flag64) {
        const long long* p = (const long long*)ei;
        g_src[e] = (int)p[e]; g_tgt[e] = (int)p[Ee + e];
    } else {
        const int* p = (const int*)ei;
        g_src[e] = p[e]; g_tgt[e] = p[Ee + e];
    }
}
__global__ void k_zero() {
    int i = blockIdx.x * blockDim.x + threadIdx.x;
    if (i < Nn) {
        g_cnt_f[i] = 0; g_cnt_b[i] = 0; g_cur_f[i] = 0; g_cur_b[i] = 0;
        g_deg_f[i] = 0.f; g_deg_b[i] = 0.f;
    }
}
__global__ void k_w2(const float* __restrict__ filtW, const float* __restrict__ filtB,
                     const float* __restrict__ decW,  const float* __restrict__ decB) {
    int c = threadIdx.x, k = blockIdx.x;
    if (k < KCAT) {
        float acc = 0.f;
        for (int j = 0; j < Hh; j++) acc += filtW[k*Hh + j] * decW[j*CDEC + c];
        g_W2[k*CDEC + c] = acc;
    } else {
        float acc = decB[c];
        for (int j = 0; j < Hh; j++) acc += filtB[j] * decW[j*CDEC + c];
        g_b2[c] = acc;
    }
}
__global__ void k_w2img() {
    int idx = blockIdx.x * blockDim.x + threadIdx.x;
    if (idx >= 2*96*360) return;
    int prec = idx / 34560, rem = idx % 34560;
    int n = rem / 360, q = rem % 360;
    int c = q / 72, k = q % 72;
    float val = (k < 64) ? g_W2[(c*64 + k)*CDEC + n] : 0.f;
    __half hi = __float2half_rn(val);
    g_W2h[idx] = prec ? __float2half_rn(val - __half2float(hi)) : hi;
}
__global__ void k_wprime(const float* __restrict__ encW, const float* __restrict__ Wih) {
    int idx = blockIdx.x * blockDim.x + threadIdx.x;
    if (idx >= 192*8) return;
    int g = idx >> 3, f = idx & 7;
    float acc = 0.f;
    for (int h = 0; h < 64; h++) acc += encW[f*64 + h] * Wih[g*64 + h];
    g_Wp[g*8 + f] = acc;
}
__global__ __launch_bounds__(192)
void k_cnode(const float* __restrict__ encB, const float* __restrict__ nodeEmb,
             const float* __restrict__ Wih,  const float* __restrict__ bih,
             const float* __restrict__ bhh) {
    __shared__ float sEB[16][68];
    int tid = threadIdx.x, n0 = blockIdx.x * 16;
    for (int i = tid; i < 16*64; i += 192) {
        int nl = i >> 6, k = i & 63;
        sEB[nl][k] = encB[k] + nodeEmb[(n0 + nl)*64 + k];
    }
    __syncthreads();
    int c = tid;
    float w[64];
    #pragma unroll
    for (int k = 0; k < 64; k++) w[k] = Wih[c*64 + k];
    float bb = bih[c] + ((c < 128) ? bhh[c] : 0.f);
    for (int nl = 0; nl < 16; nl++) {
        float acc = bb;
        #pragma unroll
        for (int k = 0; k < 64; k++) acc += sEB[nl][k] * w[k];
        g_Cnode16[(size_t)(n0 + nl)*192 + c] = __float2half_rn(acc);
    }
}
__global__ void k_prepw(const float* __restrict__ Whh) {
    int idx = blockIdx.x * blockDim.x + threadIdx.x;
    if (idx >= 33280) return;
    float val = 0.f; __half* dst;
    if (idx < 21504) {
        int rem = idx % 10752;
        int n = rem / 84, k = rem % 84;
        if (k < 64)      val = Whh[n*64 + k];
        else if (k < 72) val = g_Wp[n*8 + (k - 64)];
        dst = &g_B1Img[idx];
        int prec = idx / 10752;
        __half hi = __float2half_rn(val);
        *dst = prec ? __float2half_rn(val - __half2float(hi)) : hi;
        return;
    }
    if (idx < 24576) {
        int q = idx - 21504;
        int prec = q / 1536; int rem = q % 1536;
        int n = rem / 24, k = rem % 24;
        if (k < 8) val = g_Wp[(128 + n)*8 + k];
        dst = &g_B2aImg[q];
        __half hi = __float2half_rn(val);
        *dst = prec ? __float2half_rn(val - __half2float(hi)) : hi;
        return;
    }
    {
        int q = idx - 24576;
        int prec = q / 4352; int rem = q % 4352;
        int n = rem / 68, k = rem % 68;
        if (k < 64) val = Whh[(128 + n)*64 + k];
        dst = &g_B2bImg[q];
        __half hi = __float2half_rn(val);
        *dst = prec ? __float2half_rn(val - __half2float(hi)) : hi;
    }
}

// ================= fused 12-step GRU v2: fragment-resident gates, no staging =================
// 128 rows/block, 512 threads, 16 warps: mw=wid&3 (32-row slabs), nw=wid>>2 (16-col gate slices).
// Each warp computes r,z,xn,hn for the SAME 16 output cols -> epilogue is register-local.
// Barriers: 2/step. smem: A hi/lo + B images + C16 + x double-buffer.
#define GA_HI  0
#define GA_LO  18432
#define GB1    36864
#define GB2A   79872
#define GB2B   86016
#define GC16   103424
#define GXR    154624
#define GRU_SMEM 162816

__global__ __launch_bounds__(512, 1)
void k_gru(const float* __restrict__ x, const float* __restrict__ bhh)
{
    extern __shared__ __align__(16) char sm[];
    __half* Ahi = (__half*)(sm + GA_HI);
    __half* Alo = (__half*)(sm + GA_LO);
    __half* sC  = (__half*)(sm + GC16);     // [128][200] (192 used)
    float*  sXr = (float*)(sm + GXR);

    int tid = threadIdx.x, lane = tid & 31, wid = tid >> 5;
    int mw = wid & 3, nw = wid >> 2;
    int m0 = blockIdx.x * 128;

    // one-time loads: B images + C16
    {
        const uint4* s1 = (const uint4*)g_B1Img;  uint4* d1 = (uint4*)(sm + GB1);
        for (int i = tid; i < 43008/16; i += 512) d1[i] = s1[i];
        const uint4* s2 = (const uint4*)g_B2aImg; uint4* d2 = (uint4*)(sm + GB2A);
        if (tid < 6144/16) d2[tid] = s2[tid];
        const uint4* s3 = (const uint4*)g_B2bImg; uint4* d3 = (uint4*)(sm + GB2B);
        for (int i = tid; i < 17408/16; i += 512) d3[i] = s3[i];
        for (int i = tid; i < 3072; i += 512) {
            int row = i / 24, ch = i % 24;
            int node = (m0 + row) % Nn;
            const uint4* srcc = (const uint4*)(g_Cnode16 + (size_t)node*192) + ch;
            *((uint4*)(sC + row*200) + ch) = *srcc;
        }
    }

    uint32_t sb = smem_u32(sm);

    // prefetch x[0]
    if (tid < 256) {
        int row = tid >> 1, ch = tid & 1;
        int mm = m0 + row, b2 = mm / Nn, n2 = mm - b2 * Nn;
        CPA16(sb + GXR + (row*8 + ch*4)*4, &x[(((size_t)b2*Tt + 0)*Nn + n2)*Ff + ch*4]);
    }
    CPA_WAIT();
    __syncthreads();

    // fragment indices
    int g  = lane >> 2;            // row within 8-group
    int c2 = 2 * (lane & 3);       // col pair
    int arow = lane & 15, acol8 = (lane >> 4) * 8;
    int bn = lane >> 2, bc2 = c2;

    // preload bhh_n for this thread's 4 cols
    float bhn[2][2];
    #pragma unroll
    for (int nt = 0; nt < 2; nt++)
        #pragma unroll
        for (int c = 0; c < 2; c++)
            bhn[nt][c] = __ldg(&bhh[128 + nw*16 + nt*8 + c2 + c]);

    // h fragments: [mt][q2][nt][c] flattened
    float h[16];
    #pragma unroll
    for (int i = 0; i < 16; i++) h[i] = 0.f;

    int xrow = tid >> 2, xp = (tid & 3) * 2;   // x write ownership

    for (int t = 0; t < Tt; t++) {
        int cur = t & 1;

        // ---- A-build: h frags (register->smem) + x pair ----
        #pragma unroll
        for (int mt = 0; mt < 2; mt++)
            #pragma unroll
            for (int q2 = 0; q2 < 2; q2++) {
                int row = mw*32 + mt*16 + g + q2*8;
                #pragma unroll
                for (int nt = 0; nt < 2; nt++) {
                    int j0 = nw*16 + nt*8 + c2;
                    int hi = mt*8 + q2*4 + nt*2;
                    h2split(h[hi], h[hi+1],
                            (__half2*)(Ahi + row*72 + j0), (__half2*)(Alo + row*72 + j0));
                }
            }
        h2split(sXr[cur*1024 + xrow*8 + xp], sXr[cur*1024 + xrow*8 + xp + 1],
                (__half2*)(Ahi + xrow*72 + 64 + xp), (__half2*)(Alo + xrow*72 + 64 + xp));
        __syncthreads();   // S1: A complete

        // prefetch x[t+1]
        if (t + 1 < Tt && tid < 256) {
            int row = tid >> 1, ch = tid & 1;
            int mm = m0 + row, b2 = mm / Nn, n2 = mm - b2 * Nn;
            CPA16(sb + GXR + ((1-cur)*1024 + row*8 + ch*4)*4,
                  &x[(((size_t)b2*Tt + (t+1))*Nn + n2)*Ff + ch*4]);
        }

        // ---- 3-pass hi/lo mma: per warp 16 cols of each gate ----
        float aR[2][2][4], aZ[2][2][4], aN[2][2][4], aH[2][2][4];
        #pragma unroll
        for (int i = 0; i < 2; i++)
            #pragma unroll
            for (int j = 0; j < 2; j++)
                #pragma unroll
                for (int q = 0; q < 4; q++) {
                    aR[i][j][q] = 0.f; aZ[i][j][q] = 0.f;
                    aN[i][j][q] = 0.f; aH[i][j][q] = 0.f;
                }

        #pragma unroll
        for (int p = 0; p < 3; p++) {
            uint32_t aB  = sb + ((p == 1) ? GA_LO : GA_HI);
            uint32_t b1B = (uint32_t)GB1  + ((p == 2) ? 21504u : 0u);
            uint32_t b2aB= (uint32_t)GB2A + ((p == 2) ? 3072u  : 0u);
            uint32_t b2bB= (uint32_t)GB2B + ((p == 2) ? 8704u  : 0u);
            #pragma unroll
            for (int ks = 0; ks < 5; ks++) {
                uint32_t afr[2][4];
                #pragma unroll
                for (int mt = 0; mt < 2; mt++)
                    ldmat4(afr[mt], aB + ((mw*32 + mt*16 + arow)*72 + ks*16 + acol8) * 2);
                #pragma unroll
                for (int nt = 0; nt < 2; nt++) {
                    int nn = nw*16 + nt*8 + bn;
                    uint32_t bor = b1B + (nn*84 + ks*16 + bc2) * 2;
                    uint32_t r0 = *(const uint32_t*)(sm + bor);
                    uint32_t r1 = *(const uint32_t*)(sm + bor + 16);
                    mma16816(aR[0][nt], afr[0], r0, r1);
                    mma16816(aR[1][nt], afr[1], r0, r1);
                    uint32_t boz = b1B + ((64 + nn)*84 + ks*16 + bc2) * 2;
                    uint32_t z0 = *(const uint32_t*)(sm + boz);
                    uint32_t z1 = *(const uint32_t*)(sm + boz + 16);
                    mma16816(aZ[0][nt], afr[0], z0, z1);
                    mma16816(aZ[1][nt], afr[1], z0, z1);
                    if (ks == 4) {
                        uint32_t bon = b2aB + (nn*24 + bc2) * 2;
                        uint32_t n0 = *(const uint32_t*)(sm + bon);
                        uint32_t n1 = *(const uint32_t*)(sm + bon + 16);
                        mma16816(aN[0][nt], afr[0], n0, n1);
                        mma16816(aN[1][nt], afr[1], n0, n1);
                    } else {
                        uint32_t boh = b2bB + (nn*68 + ks*16 + bc2) * 2;
                        uint32_t h0 = *(const uint32_t*)(sm + boh);
                        uint32_t h1 = *(const uint32_t*)(sm + boh + 16);
                        mma16816(aH[0][nt], afr[0], h0, h1);
                        mma16816(aH[1][nt], afr[1], h0, h1);
                    }
                }
            }
        }

        // ---- gates: pure register math + conflict-free C reads ----
        #pragma unroll
        for (int mt = 0; mt < 2; mt++)
            #pragma unroll
            for (int q2 = 0; q2 < 2; q2++) {
                int row = mw*32 + mt*16 + g + q2*8;
                #pragma unroll
                for (int nt = 0; nt < 2; nt++) {
                    int j0 = nw*16 + nt*8 + c2;
                    float2 fr = __half22float2(*(__half2*)&sC[row*200 + j0]);
                    float2 fz = __half22float2(*(__half2*)&sC[row*200 + 64 + j0]);
                    float2 fn = __half22float2(*(__half2*)&sC[row*200 + 128 + j0]);
                    #pragma unroll
                    for (int c = 0; c < 2; c++) {
                        int ai = q2*2 + c;
                        float rv  = aR[mt][nt][ai] + (c ? fr.y : fr.x);
                        float zv  = aZ[mt][nt][ai] + (c ? fz.y : fz.x);
                        float xnv = aN[mt][nt][ai] + (c ? fn.y : fn.x);
                        float hnv = aH[mt][nt][ai] + bhn[nt][c];
                        float rg = sigf(rv), zg = sigf(zv);
                        float ng = tanhff(xnv + rg * hnv);
                        int hi = mt*8 + q2*4 + nt*2 + c;
                        h[hi] = (1.f - zg) * ng + zg * h[hi];
                    }
                }
            }

        CPA_WAIT();
        __syncthreads();   // S2: all mma done (A free), x[t+1] landed
    }

    // ---- final h -> gmem (fragment-scattered float2/half2) ----
    #pragma unroll
    for (int mt = 0; mt < 2; mt++)
        #pragma unroll
        for (int q2 = 0; q2 < 2; q2++) {
            int row = mw*32 + mt*16 + g + q2*8;
            #pragma unroll
            for (int nt = 0; nt < 2; nt++) {
                int j0 = nw*16 + nt*8 + c2;
                int hi = mt*8 + q2*4 + nt*2;
                size_t o = (size_t)(m0 + row)*Hh + j0;
                *(float2*)&g_h0[o] = make_float2(h[hi], h[hi+1]);
                *(__half2*)&g_h16[o] = __halves2half2(__float2half_rn(h[hi]),
                                                      __float2half_rn(h[hi+1]));
            }
        }
}

// ---------------- CSR build ----------------
__global__ void k_count(const float* __restrict__ ew) {
    int e = blockIdx.x * blockDim.x + threadIdx.x;
    if (e >= Ee) return;
    int s = g_src[e], t = g_tgt[e];
    float w = ew[e];
    atomicAdd(&g_cnt_f[t], 1);  atomicAdd(&g_deg_f[t], w);
    atomicAdd(&g_cnt_b[s], 1);  atomicAdd(&g_deg_b[s], w);
}
__global__ void k_scan() {
    __shared__ int sbuf[1024];
    __shared__ int sOff;
    int tid = threadIdx.x;
    for (int which = 0; which < 2; ++which) {
        const int* cnt = which ? g_cnt_b : g_cnt_f;
        int* rp        = which ? g_rowptr_b : g_rowptr_f;
        if (tid == 0) { sOff = 0; rp[0] = 0; }
        __syncthreads();
        for (int base = 0; base < Nn; base += 1024) {
            int i = base + tid;
            int v = (i < Nn) ? cnt[i] : 0;
            sbuf[tid] = v;
            __syncthreads();
            for (int d = 1; d < 1024; d <<= 1) {
                int add = (tid >= d) ? sbuf[tid - d] : 0;
                __syncthreads();
                sbuf[tid] += add;
                __syncthreads();
            }
            if (i < Nn) rp[i + 1] = sOff + sbuf[tid];
            __syncthreads();
            if (tid == 0) sOff += sbuf[1023];
            __syncthreads();
        }
        __syncthreads();
    }
}
__global__ void k_fill(const float* __restrict__ ew) {
    int e = blockIdx.x * blockDim.x + threadIdx.x;
    if (e >= Ee) return;
    int s = g_src[e], t = g_tgt[e];
    float w = ew[e];
    float df = g_deg_f[t]; df = (df == 0.f) ? 1.f : df;
    int pf = g_rowptr_f[t] + atomicAdd(&g_cur_f[t], 1);
    g_adjn_f[pf] = s;  g_adjw_f[pf] = w / df;
    float db = g_deg_b[s]; db = (db == 0.f) ? 1.f : db;
    int pb = g_rowptr_b[s] + atomicAdd(&g_cur_b[s], 1);
    g_adjn_b[pb] = t;  g_adjw_b[pb] = w / db;
}

// ---------------- diffusion props (fp16 gather, fp32 accumulate) ----------------
__device__ __forceinline__ void prop16(const __half* __restrict__ hin,
                                       float* __restrict__ outF, __half* __restrict__ outH,
                                       const int* __restrict__ rowptr,
                                       const int* __restrict__ adjn,
                                       const float* __restrict__ adjw,
                                       int node, int lane) {
    int beg = rowptr[node], end = rowptr[node + 1];
    float acc[Bb][2];
    #pragma unroll
    for (int b = 0; b < Bb; b++) { acc[b][0] = 0.f; acc[b][1] = 0.f; }
    for (int e = beg; e < end; e++) {
        int s = adjn[e];
        float w = adjw[e];
        #pragma unroll
        for (int b = 0; b < Bb; b++) {
            __half2 hv = ((const __half2*)(hin + ((size_t)b * Nn + s) * Hh))[lane];
            float2 f = __half22float2(hv);
            acc[b][0] += f.x * w;
            acc[b][1] += f.y * w;
        }
    }
    #pragma unroll
    for (int b = 0; b < Bb; b++) {
        size_t o = ((size_t)b * Nn + node) * Hh + 2*lane;
        *(float2*)&outF[o] = make_float2(acc[b][0], acc[b][1]);
        if (outH)
            *(__half2*)&outH[o] = __halves2half2(__float2half_rn(acc[b][0]),
                                                 __float2half_rn(acc[b][1]));
    }
}
__global__ void k_prop_h1() {
    int gw = (blockIdx.x * blockDim.x + threadIdx.x) >> 5;
    int lane = threadIdx.x & 31;
    if (gw >= 2*Nn) return;
    if (gw < Nn) prop16(g_h16, g_z0, g_z016, g_rowptr_f, g_adjn_f, g_adjw_f, gw, lane);
    else         prop16(g_h16, g_z2, g_z216, g_rowptr_b, g_adjn_b, g_adjw_b, gw - Nn, lane);
}
__global__ void k_prop_h2() {
    int gw = (blockIdx.x * blockDim.x + threadIdx.x) >> 5;
    int lane = threadIdx.x & 31;
    if (gw >= 2*Nn) return;
    if (gw < Nn) prop16(g_z016, g_z1, (__half*)0, g_rowptr_f, g_adjn_f, g_adjw_f, gw, lane);
    else         prop16(g_z216, g_z3, (__half*)0, g_rowptr_b, g_adjn_b, g_adjw_b, gw - Nn, lane);
}

// ---------------- k_final: HMMA 3-pass hi/lo (unchanged from R11) ----------------
#define FB_A     138240
#define FIN_SMEM 156672

__global__ __launch_bounds__(256, 1)
void k_final(float* __restrict__ out) {
    extern __shared__ __align__(16) char sm[];
    __half* Ahi = (__half*)(sm + FB_A);
    __half* Alo = Ahi + 64*72;

    int tid = threadIdx.x, lane = tid & 31, wid = tid >> 5;
    int mw = wid & 1, nw = wid >> 1;
    int m0 = blockIdx.x * 64;

    {
        const uint4* sw = (const uint4*)g_W2h;
        uint4* dw = (uint4*)sm;
        for (int i = tid; i < 138240/16; i += 256) dw[i] = sw[i];
    }

    int r = tid >> 2, kq = (tid & 3) * 16;
    int arow = lane & 15, acol8 = (lane >> 4) * 8;
    int bn = lane >> 2, bc2 = 2 * (lane & 3);

    float acc[2][3][4];
    #pragma unroll
    for (int i = 0; i < 2; i++)
        #pragma unroll
        for (int j = 0; j < 3; j++)
            #pragma unroll
            for (int q = 0; q < 4; q++) acc[i][j][q] = 0.f;

    uint32_t sb = smem_u32(sm);
    const float* srcs[5] = { g_h0, g_z0, g_z1, g_z2, g_z3 };

    for (int c = 0; c < 5; c++) {
        __syncthreads();
        const float* S = srcs[c] + (size_t)(m0 + r)*64 + kq;
        #pragma unroll
        for (int j = 0; j < 16; j += 2)
            h2split(S[j], S[j+1],
                    (__half2*)(Ahi + r*72 + kq + j), (__half2*)(Alo + r*72 + kq + j));
        __syncthreads();

        #pragma unroll
        for (int p = 0; p < 3; p++) {
            uint32_t aB = sb + FB_A + ((p == 1) ? 64*72*2 : 0);
            uint32_t wB = (p == 2) ? (uint32_t)(34560*2) : 0u;
            #pragma unroll
            for (int ks = 0; ks < 4; ks++) {
                uint32_t afr[2][4];
                #pragma unroll
                for (int mt = 0; mt < 2; mt++)
                    ldmat4(afr[mt], aB + ((mw*32 + mt*16 + arow)*72 + ks*16 + acol8) * 2);
                #pragma unroll
                for (int nt = 0; nt < 3; nt++) {
                    int n = nw*24 + nt*8 + bn;
                    uint32_t bo = wB + ((n*360 + c*72 + ks*16 + bc2) * 2);
                    uint32_t b0 = *(const uint32_t*)(sm + bo);
                    uint32_t b1 = *(const uint32_t*)(sm + bo + 16);
                    mma16816(acc[0][nt], afr[0], b0, b1);
                    mma16816(acc[1][nt], afr[1], b0, b1);
                }
            }
        }
    }

    int g = lane >> 2, c2 = 2 * (lane & 3);
    #pragma unroll
    for (int mt = 0; mt < 2; mt++)
        #pragma unroll
        for (int q2 = 0; q2 < 2; q2++) {
            int row = mw*32 + mt*16 + g + q2*8;
            int m = m0 + row, b = m / Nn, n = m - b * Nn;
            #pragma unroll
            for (int nt = 0; nt < 3; nt++) {
                int col = nw*24 + nt*8 + c2;
                int tt = col >> 3, f = col & 7;
                float2 v = make_float2(acc[mt][nt][q2*2]     + __ldg(&g_b2[col]),
                                       acc[mt][nt][q2*2 + 1] + __ldg(&g_b2[col + 1]));
                *(float2*)&out[(((size_t)b * HOR + tt) * Nn + n) * Ff + f] = v;
            }
        }
}

// ---------------- launch (k_gru at index 3 for ncu capture) ----------------
extern "C" void kernel_launch(void* const* d_in, const int* in_sizes, int n_in,
                              void* d_out, int out_size) {
    const float* x     = (const float*)d_in[0];
    const void*  ei    = d_in[1];
    const float* ew    = (const float*)d_in[2];
    const float* encW  = (const float*)d_in[3];
    const float* encB  = (const float*)d_in[4];
    const float* nemb  = (const float*)d_in[5];
    const float* Wih   = (const float*)d_in[6];
    const float* Whh   = (const float*)d_in[7];
    const float* bih   = (const float*)d_in[8];
    const float* bhh   = (const float*)d_in[9];
    const float* filtW = (const float*)d_in[10];
    const float* filtB = (const float*)d_in[11];
    const float* decW  = (const float*)d_in[12];
    const float* decB  = (const float*)d_in[13];
    float* out = (float*)d_out;

    cudaFuncSetAttribute(k_gru,   cudaFuncAttributeMaxDynamicSharedMemorySize, GRU_SMEM);
    cudaFuncSetAttribute(k_final, cudaFuncAttributeMaxDynamicSharedMemorySize, FIN_SMEM);

    k_wprime<<<6, 256>>>(encW, Wih);                       // 0
    k_cnode<<<Nn/16, 192>>>(encB, nemb, Wih, bih, bhh);    // 1
    k_prepw<<<(33280 + 255) / 256, 256>>>(Whh);            // 2
    k_gru<<<Mm / 128, 512, GRU_SMEM>>>(x, bhh);            // 3  <- ncu captures this
    k_detect<<<1, 1>>>((const unsigned int*)ei);           // 4
    k_convert<<<(Ee + 255) / 256, 256>>>(ei);              // 5
    k_zero<<<(Nn + 255) / 256, 256>>>();                   // 6
    k_w2<<<KCAT + 1, CDEC>>>(filtW, filtB, decW, decB);    // 7
    k_w2img<<<(2*96*360 + 255) / 256, 256>>>();            // 8
    k_count<<<(Ee + 255) / 256, 256>>>(ew);                // 9
    k_scan<<<1, 1024>>>();                                 // 10
    k_fill<<<(Ee + 255) / 256, 256>>>(ew);                 // 11
    k_prop_h1<<<(2*Nn*32 + 255) / 256, 256>>>();           // 12
    k_prop_h2<<<(2*Nn*32 + 255) / 256, 256>>>();           // 13
    k_final<<<Mm / 64, 256, FIN_SMEM>>>(out);              // 14
}

// round 13
// speedup vs baseline: 2.1377x; 1.0564x over previous
#include <cuda_runtime.h>
#include <cuda_fp16.h>
#include <math.h>
#include <stdint.h>

#define Nn   10000
#define Bb   8
#define Tt   12
#define Ff   8
#define Hh   64
#define Ee   320000
#define HOR  12
#define Mm   (Bb*Nn)
#define KCAT 320
#define CDEC 96

// ---------------- device scratch ----------------
__device__ float g_h0[Mm*Hh];
__device__ float g_z0[Mm*Hh];
__device__ float g_z1[Mm*Hh];
__device__ float g_z2[Mm*Hh];
__device__ float g_z3[Mm*Hh];
__device__ __half g_h16[Mm*Hh];
__device__ __half g_z016[Mm*Hh];
__device__ __half g_z216[Mm*Hh];
__device__ int   g_src[Ee], g_tgt[Ee];
__device__ int   g_rowptr_f[Nn+1], g_rowptr_b[Nn+1];
__device__ int   g_cnt_f[Nn], g_cnt_b[Nn], g_cur_f[Nn], g_cur_b[Nn];
__device__ float g_deg_f[Nn], g_deg_b[Nn];
__device__ int   g_adjn_f[Ee]; __device__ float g_adjw_f[Ee];
__device__ int   g_adjn_b[Ee]; __device__ float g_adjw_b[Ee];
__device__ float g_W2[KCAT*CDEC];
__device__ float g_b2[CDEC];
__device__ int   g_flag64;
__device__ float g_Wp[192*8];                   // W' = encW@Wih
__device__ __half g_Cnode16[(size_t)Nn*192];    // C[n][g] fp16 (bih + bhh_rz folded)

// fp16 hi/lo weight images (zero-padded k-overhang)
__device__ __half g_B1Img [2*128*84];   // rz: rows 0..63 r, 64..127 z
__device__ __half g_B2aImg[2*64*24];    // xn
__device__ __half g_B2bImg[2*64*68];    // hn
__device__ __half g_W2h[2*96*360];      // k_final W2 image

// ---------------- helpers ----------------
__device__ __forceinline__ uint32_t smem_u32(const void* p) {
    uint32_t a;
    asm("{ .reg .u64 t; cvta.to.shared.u64 t, %1; cvt.u32.u64 %0, t; }" : "=r"(a) : "l"(p));
    return a;
}
__device__ __forceinline__ void ldmat4(uint32_t* f, uint32_t addr) {
    asm volatile("ldmatrix.sync.aligned.m8n8.x4.shared.b16 {%0,%1,%2,%3}, [%4];"
        : "=r"(f[0]), "=r"(f[1]), "=r"(f[2]), "=r"(f[3]) : "r"(addr));
}
__device__ __forceinline__ void mma16816(float* c, const uint32_t* a, uint32_t b0, uint32_t b1) {
    asm volatile("mma.sync.aligned.m16n8k16.row.col.f32.f16.f16.f32 "
        "{%0,%1,%2,%3}, {%4,%5,%6,%7}, {%8,%9}, {%0,%1,%2,%3};"
        : "+f"(c[0]), "+f"(c[1]), "+f"(c[2]), "+f"(c[3])
        : "r"(a[0]), "r"(a[1]), "r"(a[2]), "r"(a[3]), "r"(b0), "r"(b1));
}
#define CPA16(sa, gp) asm volatile("cp.async.cg.shared.global [%0], [%1], 16;" :: "r"(sa), "l"(gp))
#define CPA_WAIT()    asm volatile("cp.async.wait_all;" ::: "memory")
__device__ __forceinline__ float sigf(float x)  { return 1.f / (1.f + __expf(-x)); }
__device__ __forceinline__ float tanhff(float x){ float e = __expf(2.f*x); return 1.f - 2.f/(e + 1.f); }
__device__ __forceinline__ void h2split(float v0, float v1, __half2* hi, __half2* lo) {
    __half a = __float2half_rn(v0), b = __float2half_rn(v1);
    *hi = __halves2half2(a, b);
    *lo = __halves2half2(__float2half_rn(v0 - __half2float(a)),
                         __float2half_rn(v1 - __half2float(b)));
}

// ---------------- small prep kernels ----------------
__global__ void k_detect(const unsigned int* ei_raw) {
    bool all0 = true;
    for (int i = 0; i < 16; i++) if (ei_raw[2*i + 1] != 0u) all0 = false;
    g_flag64 = all0 ? 1 : 0;
}
__global__ void k_convert(const void* ei) {
    int e = blockIdx.x * blockDim.x + threadIdx.x;
    if (e >= Ee) return;
    if (g_flag64) {
        const long long* p = (const long long*)ei;
        g_src[e] = (int)p[e]; g_tgt[e] = (int)p[Ee + e];
    } else {
        const int* p = (const int*)ei;
        g_src[e] = p[e]; g_tgt[e] = p[Ee + e];
    }
}
__global__ void k_zero() {
    int i = blockIdx.x * blockDim.x + threadIdx.x;
    if (i < Nn) {
        g_cnt_f[i] = 0; g_cnt_b[i] = 0; g_cur_f[i] = 0; g_cur_b[i] = 0;
        g_deg_f[i] = 0.f; g_deg_b[i] = 0.f;
    }
}
__global__ void k_w2(const float* __restrict__ filtW, const float* __restrict__ filtB,
                     const float* __restrict__ decW,  const float* __restrict__ decB) {
    int c = threadIdx.x, k = blockIdx.x;
    if (k < KCAT) {
        float acc = 0.f;
        for (int j = 0; j < Hh; j++) acc += filtW[k*Hh + j] * decW[j*CDEC + c];
        g_W2[k*CDEC + c] = acc;
    } else {
        float acc = decB[c];
        for (int j = 0; j < Hh; j++) acc += filtB[j] * decW[j*CDEC + c];
        g_b2[c] = acc;
    }
}
__global__ void k_w2img() {
    int idx = blockIdx.x * blockDim.x + threadIdx.x;
    if (idx >= 2*96*360) return;
    int prec = idx / 34560, rem = idx % 34560;
    int n = rem / 360, q = rem % 360;
    int c = q / 72, k = q % 72;
    float val = (k < 64) ? g_W2[(c*64 + k)*CDEC + n] : 0.f;
    __half hi = __float2half_rn(val);
    g_W2h[idx] = prec ? __float2half_rn(val - __half2float(hi)) : hi;
}
__global__ void k_wprime(const float* __restrict__ encW, const float* __restrict__ Wih) {
    int idx = blockIdx.x * blockDim.x + threadIdx.x;
    if (idx >= 192*8) return;
    int g = idx >> 3, f = idx & 7;
    float acc = 0.f;
    for (int h = 0; h < 64; h++) acc += encW[f*64 + h] * Wih[g*64 + h];
    g_Wp[g*8 + f] = acc;
}
__global__ __launch_bounds__(192)
void k_cnode(const float* __restrict__ encB, const float* __restrict__ nodeEmb,
             const float* __restrict__ Wih,  const float* __restrict__ bih,
             const float* __restrict__ bhh) {
    __shared__ float sEB[16][68];
    int tid = threadIdx.x, n0 = blockIdx.x * 16;
    for (int i = tid; i < 16*64; i += 192) {
        int nl = i >> 6, k = i & 63;
        sEB[nl][k] = encB[k] + nodeEmb[(n0 + nl)*64 + k];
    }
    __syncthreads();
    int c = tid;
    float w[64];
    #pragma unroll
    for (int k = 0; k < 64; k++) w[k] = Wih[c*64 + k];
    float bb = bih[c] + ((c < 128) ? bhh[c] : 0.f);
    for (int nl = 0; nl < 16; nl++) {
        float acc = bb;
        #pragma unroll
        for (int k = 0; k < 64; k++) acc += sEB[nl][k] * w[k];
        g_Cnode16[(size_t)(n0 + nl)*192 + c] = __float2half_rn(acc);
    }
}
__global__ void k_prepw(const float* __restrict__ Whh) {
    int idx = blockIdx.x * blockDim.x + threadIdx.x;
    if (idx >= 33280) return;
    float val = 0.f; __half* dst;
    if (idx < 21504) {
        int rem = idx % 10752;
        int n = rem / 84, k = rem % 84;
        if (k < 64)      val = Whh[n*64 + k];
        else if (k < 72) val = g_Wp[n*8 + (k - 64)];
        dst = &g_B1Img[idx];
        int prec = idx / 10752;
        __half hi = __float2half_rn(val);
        *dst = prec ? __float2half_rn(val - __half2float(hi)) : hi;
        return;
    }
    if (idx < 24576) {
        int q = idx - 21504;
        int prec = q / 1536; int rem = q % 1536;
        int n = rem / 24, k = rem % 24;
        if (k < 8) val = g_Wp[(128 + n)*8 + k];
        dst = &g_B2aImg[q];
        __half hi = __float2half_rn(val);
        *dst = prec ? __float2half_rn(val - __half2float(hi)) : hi;
        return;
    }
    {
        int q = idx - 24576;
        int prec = q / 4352; int rem = q % 4352;
        int n = rem / 68, k = rem % 68;
        if (k < 64) val = Whh[(128 + n)*64 + k];
        dst = &g_B2bImg[q];
        __half hi = __float2half_rn(val);
        *dst = prec ? __float2half_rn(val - __half2float(hi)) : hi;
    }
}

// ================= fused 12-step GRU v3: 64 rows/block, 256 thr, 2 blocks/SM =================
// 8 warps: mw=wid&1 (32-row slabs), nw=wid>>1 (16-col gate slices). Fragment-resident gates.
#define GA_HI  0
#define GA_LO  9216
#define GB1    18432
#define GB2A   61440
#define GB2B   67584
#define GC16   84992
#define GXR    110592
#define GRU_SMEM 114688

__global__ __launch_bounds__(256, 2)
void k_gru(const float* __restrict__ x, const float* __restrict__ bhh)
{
    extern __shared__ __align__(16) char sm[];
    __half* Ahi = (__half*)(sm + GA_HI);
    __half* Alo = (__half*)(sm + GA_LO);
    __half* sC  = (__half*)(sm + GC16);     // [64][200] (192 used)
    float*  sXr = (float*)(sm + GXR);

    int tid = threadIdx.x, lane = tid & 31, wid = tid >> 5;
    int mw = wid & 1, nw = wid >> 1;
    int m0 = blockIdx.x * 64;

    // one-time loads: B images + C16
    {
        const uint4* s1 = (const uint4*)g_B1Img;  uint4* d1 = (uint4*)(sm + GB1);
        for (int i = tid; i < 43008/16; i += 256) d1[i] = s1[i];
        const uint4* s2 = (const uint4*)g_B2aImg; uint4* d2 = (uint4*)(sm + GB2A);
        for (int i = tid; i < 6144/16; i += 256) d2[i] = s2[i];
        const uint4* s3 = (const uint4*)g_B2bImg; uint4* d3 = (uint4*)(sm + GB2B);
        for (int i = tid; i < 17408/16; i += 256) d3[i] = s3[i];
        for (int i = tid; i < 1536; i += 256) {
            int row = i / 24, ch = i % 24;
            int node = (m0 + row) % Nn;
            const uint4* srcc = (const uint4*)(g_Cnode16 + (size_t)node*192) + ch;
            *((uint4*)(sC + row*200) + ch) = *srcc;
        }
    }

    uint32_t sb = smem_u32(sm);

    // prefetch x[0]: 64 rows x 32B = 128 chunks
    if (tid < 128) {
        int row = tid >> 1, ch = tid & 1;
        int mm = m0 + row, b2 = mm / Nn, n2 = mm - b2 * Nn;
        CPA16(sb + GXR + (row*8 + ch*4)*4, &x[(((size_t)b2*Tt + 0)*Nn + n2)*Ff + ch*4]);
    }
    CPA_WAIT();
    __syncthreads();

    // fragment indices
    int g  = lane >> 2;
    int c2 = 2 * (lane & 3);
    int arow = lane & 15, acol8 = (lane >> 4) * 8;
    int bn = lane >> 2, bc2 = c2;

    float bhn[2][2];
    #pragma unroll
    for (int nt = 0; nt < 2; nt++)
        #pragma unroll
        for (int c = 0; c < 2; c++)
            bhn[nt][c] = __ldg(&bhh[128 + nw*16 + nt*8 + c2 + c]);

    float h[16];
    #pragma unroll
    for (int i = 0; i < 16; i++) h[i] = 0.f;

    int xrow = tid >> 2, xp = (tid & 3) * 2;

    for (int t = 0; t < Tt; t++) {
        int cur = t & 1;

        // ---- A-build: h frags + x pair ----
        #pragma unroll
        for (int mt = 0; mt < 2; mt++)
            #pragma unroll
            for (int q2 = 0; q2 < 2; q2++) {
                int row = mw*32 + mt*16 + g + q2*8;
                #pragma unroll
                for (int nt = 0; nt < 2; nt++) {
                    int j0 = nw*16 + nt*8 + c2;
                    int hi = mt*8 + q2*4 + nt*2;
                    h2split(h[hi], h[hi+1],
                            (__half2*)(Ahi + row*72 + j0), (__half2*)(Alo + row*72 + j0));
                }
            }
        h2split(sXr[cur*512 + xrow*8 + xp], sXr[cur*512 + xrow*8 + xp + 1],
                (__half2*)(Ahi + xrow*72 + 64 + xp), (__half2*)(Alo + xrow*72 + 64 + xp));
        __syncthreads();   // S1: A complete

        // prefetch x[t+1]
        if (t + 1 < Tt && tid < 128) {
            int row = tid >> 1, ch = tid & 1;
            int mm = m0 + row, b2 = mm / Nn, n2 = mm - b2 * Nn;
            CPA16(sb + GXR + ((1-cur)*512 + row*8 + ch*4)*4,
                  &x[(((size_t)b2*Tt + (t+1))*Nn + n2)*Ff + ch*4]);
        }

        // ---- 3-pass hi/lo mma ----
        float aR[2][2][4], aZ[2][2][4], aN[2][2][4], aH[2][2][4];
        #pragma unroll
        for (int i = 0; i < 2; i++)
            #pragma unroll
            for (int j = 0; j < 2; j++)
                #pragma unroll
                for (int q = 0; q < 4; q++) {
                    aR[i][j][q] = 0.f; aZ[i][j][q] = 0.f;
                    aN[i][j][q] = 0.f; aH[i][j][q] = 0.f;
                }

        #pragma unroll
        for (int p = 0; p < 3; p++) {
            uint32_t aB  = sb + ((p == 1) ? GA_LO : GA_HI);
            uint32_t b1B = (uint32_t)GB1  + ((p == 2) ? 21504u : 0u);
            uint32_t b2aB= (uint32_t)GB2A + ((p == 2) ? 3072u  : 0u);
            uint32_t b2bB= (uint32_t)GB2B + ((p == 2) ? 8704u  : 0u);
            #pragma unroll
            for (int ks = 0; ks < 5; ks++) {
                uint32_t afr[2][4];
                #pragma unroll
                for (int mt = 0; mt < 2; mt++)
                    ldmat4(afr[mt], aB + ((mw*32 + mt*16 + arow)*72 + ks*16 + acol8) * 2);
                #pragma unroll
                for (int nt = 0; nt < 2; nt++) {
                    int nn = nw*16 + nt*8 + bn;
                    uint32_t bor = b1B + (nn*84 + ks*16 + bc2) * 2;
                    uint32_t r0 = *(const uint32_t*)(sm + bor);
                    uint32_t r1 = *(const uint32_t*)(sm + bor + 16);
                    mma16816(aR[0][nt], afr[0], r0, r1);
                    mma16816(aR[1][nt], afr[1], r0, r1);
                    uint32_t boz = b1B + ((64 + nn)*84 + ks*16 + bc2) * 2;
                    uint32_t z0 = *(const uint32_t*)(sm + boz);
                    uint32_t z1 = *(const uint32_t*)(sm + boz + 16);
                    mma16816(aZ[0][nt], afr[0], z0, z1);
                    mma16816(aZ[1][nt], afr[1], z0, z1);
                    if (ks == 4) {
                        uint32_t bon = b2aB + (nn*24 + bc2) * 2;
                        uint32_t n0 = *(const uint32_t*)(sm + bon);
                        uint32_t n1 = *(const uint32_t*)(sm + bon + 16);
                        mma16816(aN[0][nt], afr[0], n0, n1);
                        mma16816(aN[1][nt], afr[1], n0, n1);
                    } else {
                        uint32_t boh = b2bB + (nn*68 + ks*16 + bc2) * 2;
                        uint32_t h0 = *(const uint32_t*)(sm + boh);
                        uint32_t h1 = *(const uint32_t*)(sm + boh + 16);
                        mma16816(aH[0][nt], afr[0], h0, h1);
                        mma16816(aH[1][nt], afr[1], h0, h1);
                    }
                }
            }
        }

        // ---- gates: register math + conflict-free C reads ----
        #pragma unroll
        for (int mt = 0; mt < 2; mt++)
            #pragma unroll
            for (int q2 = 0; q2 < 2; q2++) {
                int row = mw*32 + mt*16 + g + q2*8;
                #pragma unroll
                for (int nt = 0; nt < 2; nt++) {
                    int j0 = nw*16 + nt*8 + c2;
                    float2 fr = __half22float2(*(__half2*)&sC[row*200 + j0]);
                    float2 fz = __half22float2(*(__half2*)&sC[row*200 + 64 + j0]);
                    float2 fn = __half22float2(*(__half2*)&sC[row*200 + 128 + j0]);
                    #pragma unroll
                    for (int c = 0; c < 2; c++) {
                        int ai = q2*2 + c;
                        float rv  = aR[mt][nt][ai] + (c ? fr.y : fr.x);
                        float zv  = aZ[mt][nt][ai] + (c ? fz.y : fz.x);
                        float xnv = aN[mt][nt][ai] + (c ? fn.y : fn.x);
                        float hnv = aH[mt][nt][ai] + bhn[nt][c];
                        float rg = sigf(rv), zg = sigf(zv);
                        float ng = tanhff(xnv + rg * hnv);
                        int hi = mt*8 + q2*4 + nt*2 + c;
                        h[hi] = (1.f - zg) * ng + zg * h[hi];
                    }
                }
            }

        CPA_WAIT();
        __syncthreads();   // S2: all mma done, x[t+1] landed
    }

    // ---- final h -> gmem ----
    #pragma unroll
    for (int mt = 0; mt < 2; mt++)
        #pragma unroll
        for (int q2 = 0; q2 < 2; q2++) {
            int row = mw*32 + mt*16 + g + q2*8;
            #pragma unroll
            for (int nt = 0; nt < 2; nt++) {
                int j0 = nw*16 + nt*8 + c2;
                int hi = mt*8 + q2*4 + nt*2;
                size_t o = (size_t)(m0 + row)*Hh + j0;
                *(float2*)&g_h0[o] = make_float2(h[hi], h[hi+1]);
                *(__half2*)&g_h16[o] = __halves2half2(__float2half_rn(h[hi]),
                                                      __float2half_rn(h[hi+1]));
            }
        }
}

// ---------------- CSR build ----------------
__global__ void k_count(const float* __restrict__ ew) {
    int e = blockIdx.x * blockDim.x + threadIdx.x;
    if (e >= Ee) return;
    int s = g_src[e], t = g_tgt[e];
    float w = ew[e];
    atomicAdd(&g_cnt_f[t], 1);  atomicAdd(&g_deg_f[t], w);
    atomicAdd(&g_cnt_b[s], 1);  atomicAdd(&g_deg_b[s], w);
}
__global__ void k_scan() {
    __shared__ int sbuf[1024];
    __shared__ int sOff;
    int tid = threadIdx.x;
    for (int which = 0; which < 2; ++which) {
        const int* cnt = which ? g_cnt_b : g_cnt_f;
        int* rp        = which ? g_rowptr_b : g_rowptr_f;
        if (tid == 0) { sOff = 0; rp[0] = 0; }
        __syncthreads();
        for (int base = 0; base < Nn; base += 1024) {
            int i = base + tid;
            int v = (i < Nn) ? cnt[i] : 0;
            sbuf[tid] = v;
            __syncthreads();
            for (int d = 1; d < 1024; d <<= 1) {
                int add = (tid >= d) ? sbuf[tid - d] : 0;
                __syncthreads();
                sbuf[tid] += add;
                __syncthreads();
            }
            if (i < Nn) rp[i + 1] = sOff + sbuf[tid];
            __syncthreads();
            if (tid == 0) sOff += sbuf[1023];
            __syncthreads();
        }
        __syncthreads();
    }
}
__global__ void k_fill(const float* __restrict__ ew) {
    int e = blockIdx.x * blockDim.x + threadIdx.x;
    if (e >= Ee) return;
    int s = g_src[e], t = g_tgt[e];
    float w = ew[e];
    float df = g_deg_f[t]; df = (df == 0.f) ? 1.f : df;
    int pf = g_rowptr_f[t] + atomicAdd(&g_cur_f[t], 1);
    g_adjn_f[pf] = s;  g_adjw_f[pf] = w / df;
    float db = g_deg_b[s]; db = (db == 0.f) ? 1.f : db;
    int pb = g_rowptr_b[s] + atomicAdd(&g_cur_b[s], 1);
    g_adjn_b[pb] = t;  g_adjw_b[pb] = w / db;
}

// ---------------- diffusion props (fp16 gather, fp32 accumulate) ----------------
__device__ __forceinline__ void prop16(const __half* __restrict__ hin,
                                       float* __restrict__ outF, __half* __restrict__ outH,
                                       const int* __restrict__ rowptr,
                                       const int* __restrict__ adjn,
                                       const float* __restrict__ adjw,
                                       int node, int lane) {
    int beg = rowptr[node], end = rowptr[node + 1];
    float acc[Bb][2];
    #pragma unroll
    for (int b = 0; b < Bb; b++) { acc[b][0] = 0.f; acc[b][1] = 0.f; }
    for (int e = beg; e < end; e++) {
        int s = adjn[e];
        float w = adjw[e];
        #pragma unroll
        for (int b = 0; b < Bb; b++) {
            __half2 hv = ((const __half2*)(hin + ((size_t)b * Nn + s) * Hh))[lane];
            float2 f = __half22float2(hv);
            acc[b][0] += f.x * w;
            acc[b][1] += f.y * w;
        }
    }
    #pragma unroll
    for (int b = 0; b < Bb; b++) {
        size_t o = ((size_t)b * Nn + node) * Hh + 2*lane;
        *(float2*)&outF[o] = make_float2(acc[b][0], acc[b][1]);
        if (outH)
            *(__half2*)&outH[o] = __halves2half2(__float2half_rn(acc[b][0]),
                                                 __float2half_rn(acc[b][1]));
    }
}
__global__ void k_prop_h1() {
    int gw = (blockIdx.x * blockDim.x + threadIdx.x) >> 5;
    int lane = threadIdx.x & 31;
    if (gw >= 2*Nn) return;
    if (gw < Nn) prop16(g_h16, g_z0, g_z016, g_rowptr_f, g_adjn_f, g_adjw_f, gw, lane);
    else         prop16(g_h16, g_z2, g_z216, g_rowptr_b, g_adjn_b, g_adjw_b, gw - Nn, lane);
}
__global__ void k_prop_h2() {
    int gw = (blockIdx.x * blockDim.x + threadIdx.x) >> 5;
    int lane = threadIdx.x & 31;
    if (gw >= 2*Nn) return;
    if (gw < Nn) prop16(g_z016, g_z1, (__half*)0, g_rowptr_f, g_adjn_f, g_adjw_f, gw, lane);
    else         prop16(g_z216, g_z3, (__half*)0, g_rowptr_b, g_adjn_b, g_adjw_b, gw - Nn, lane);
}

// ---------------- k_final: HMMA 3-pass hi/lo ----------------
#define FB_A     138240
#define FIN_SMEM 156672

__global__ __launch_bounds__(256, 1)
void k_final(float* __restrict__ out) {
    extern __shared__ __align__(16) char sm[];
    __half* Ahi = (__half*)(sm + FB_A);
    __half* Alo = Ahi + 64*72;

    int tid = threadIdx.x, lane = tid & 31, wid = tid >> 5;
    int mw = wid & 1, nw = wid >> 1;
    int m0 = blockIdx.x * 64;

    {
        const uint4* sw = (const uint4*)g_W2h;
        uint4* dw = (uint4*)sm;
        for (int i = tid; i < 138240/16; i += 256) dw[i] = sw[i];
    }

    int r = tid >> 2, kq = (tid & 3) * 16;
    int arow = lane & 15, acol8 = (lane >> 4) * 8;
    int bn = lane >> 2, bc2 = 2 * (lane & 3);

    float acc[2][3][4];
    #pragma unroll
    for (int i = 0; i < 2; i++)
        #pragma unroll
        for (int j = 0; j < 3; j++)
            #pragma unroll
            for (int q = 0; q < 4; q++) acc[i][j][q] = 0.f;

    uint32_t sb = smem_u32(sm);
    const float* srcs[5] = { g_h0, g_z0, g_z1, g_z2, g_z3 };

    for (int c = 0; c < 5; c++) {
        __syncthreads();
        const float* S = srcs[c] + (size_t)(m0 + r)*64 + kq;
        #pragma unroll
        for (int j = 0; j < 16; j += 2)
            h2split(S[j], S[j+1],
                    (__half2*)(Ahi + r*72 + kq + j), (__half2*)(Alo + r*72 + kq + j));
        __syncthreads();

        #pragma unroll
        for (int p = 0; p < 3; p++) {
            uint32_t aB = sb + FB_A + ((p == 1) ? 64*72*2 : 0);
            uint32_t wB = (p == 2) ? (uint32_t)(34560*2) : 0u;
            #pragma unroll
            for (int ks = 0; ks < 4; ks++) {
                uint32_t afr[2][4];
                #pragma unroll
                for (int mt = 0; mt < 2; mt++)
                    ldmat4(afr[mt], aB + ((mw*32 + mt*16 + arow)*72 + ks*16 + acol8) * 2);
                #pragma unroll
                for (int nt = 0; nt < 3; nt++) {
                    int n = nw*24 + nt*8 + bn;
                    uint32_t bo = wB + ((n*360 + c*72 + ks*16 + bc2) * 2);
                    uint32_t b0 = *(const uint32_t*)(sm + bo);
                    uint32_t b1 = *(const uint32_t*)(sm + bo + 16);
                    mma16816(acc[0][nt], afr[0], b0, b1);
                    mma16816(acc[1][nt], afr[1], b0, b1);
                }
            }
        }
    }

    int g = lane >> 2, c2 = 2 * (lane & 3);
    #pragma unroll
    for (int mt = 0; mt < 2; mt++)
        #pragma unroll
        for (int q2 = 0; q2 < 2; q2++) {
            int row = mw*32 + mt*16 + g + q2*8;
            int m = m0 + row, b = m / Nn, n = m - b * Nn;
            #pragma unroll
            for (int nt = 0; nt < 3; nt++) {
                int col = nw*24 + nt*8 + c2;
                int tt = col >> 3, f = col & 7;
                float2 v = make_float2(acc[mt][nt][q2*2]     + __ldg(&g_b2[col]),
                                       acc[mt][nt][q2*2 + 1] + __ldg(&g_b2[col + 1]));
                *(float2*)&out[(((size_t)b * HOR + tt) * Nn + n) * Ff + f] = v;
            }
        }
}

// ---------------- launch (k_gru at index 3 for ncu capture) ----------------
extern "C" void kernel_launch(void* const* d_in, const int* in_sizes, int n_in,
                              void* d_out, int out_size) {
    const float* x     = (const float*)d_in[0];
    const void*  ei    = d_in[1];
    const float* ew    = (const float*)d_in[2];
    const float* encW  = (const float*)d_in[3];
    const float* encB  = (const float*)d_in[4];
    const float* nemb  = (const float*)d_in[5];
    const float* Wih   = (const float*)d_in[6];
    const float* Whh   = (const float*)d_in[7];
    const float* bih   = (const float*)d_in[8];
    const float* bhh   = (const float*)d_in[9];
    const float* filtW = (const float*)d_in[10];
    const float* filtB = (const float*)d_in[11];
    const float* decW  = (const float*)d_in[12];
    const float* decB  = (const float*)d_in[13];
    float* out = (float*)d_out;

    cudaFuncSetAttribute(k_gru,   cudaFuncAttributeMaxDynamicSharedMemorySize, GRU_SMEM);
    cudaFuncSetAttribute(k_final, cudaFuncAttributeMaxDynamicSharedMemorySize, FIN_SMEM);

    k_wprime<<<6, 256>>>(encW, Wih);                       // 0
    k_cnode<<<Nn/16, 192>>>(encB, nemb, Wih, bih, bhh);    // 1
    k_prepw<<<(33280 + 255) / 256, 256>>>(Whh);            // 2
    k_gru<<<Mm / 64, 256, GRU_SMEM>>>(x, bhh);             // 3  <- ncu captures this
    k_detect<<<1, 1>>>((const unsigned int*)ei);           // 4
    k_convert<<<(Ee + 255) / 256, 256>>>(ei);              // 5
    k_zero<<<(Nn + 255) / 256, 256>>>();                   // 6
    k_w2<<<KCAT + 1, CDEC>>>(filtW, filtB, decW, decB);    // 7
    k_w2img<<<(2*96*360 + 255) / 256, 256>>>();            // 8
    k_count<<<(Ee + 255) / 256, 256>>>(ew);                // 9
    k_scan<<<1, 1024>>>();                                 // 10
    k_fill<<<(Ee + 255) / 256, 256>>>(ew);                 // 11
    k_prop_h1<<<(2*Nn*32 + 255) / 256, 256>>>();           // 12
    k_prop_h2<<<(2*Nn*32 + 255) / 256, 256>>>();           // 13
    k_final<<<Mm / 64, 256, FIN_SMEM>>>(out);              // 14
}

// round 14
// speedup vs baseline: 2.1770x; 1.0184x over previous
#include <cuda_runtime.h>
#include <cuda_fp16.h>
#include <math.h>
#include <stdint.h>

#define Nn   10000
#define Bb   8
#define Tt   12
#define Ff   8
#define Hh   64
#define Ee   320000
#define HOR  12
#define Mm   (Bb*Nn)
#define KCAT 320
#define CDEC 96

// ---------------- device scratch ----------------
__device__ float g_h0[Mm*Hh];
__device__ float g_z0[Mm*Hh];
__device__ float g_z1[Mm*Hh];
__device__ float g_z2[Mm*Hh];
__device__ float g_z3[Mm*Hh];
__device__ __half g_h16[Mm*Hh];
__device__ __half g_z016[Mm*Hh];
__device__ __half g_z216[Mm*Hh];
__device__ int   g_src[Ee], g_tgt[Ee];
__device__ int   g_rowptr_f[Nn+1], g_rowptr_b[Nn+1];
__device__ int   g_cnt_f[Nn], g_cnt_b[Nn], g_cur_f[Nn], g_cur_b[Nn];
__device__ float g_deg_f[Nn], g_deg_b[Nn];
__device__ int   g_adjn_f[Ee]; __device__ float g_adjw_f[Ee];
__device__ int   g_adjn_b[Ee]; __device__ float g_adjw_b[Ee];
__device__ float g_W2[KCAT*CDEC];
__device__ float g_b2[CDEC];
__device__ int   g_flag64;
__device__ float g_Wp[192*8];                   // W' = encW@Wih
__device__ __half g_Cnode16[(size_t)Nn*192];    // C[n][g] fp16 (bih + bhh_rz folded)

// fp16 hi/lo weight images, 16B-aligned row strides for ldmatrix
__device__ __half g_B1Img [2*128*88];   // rz: rows 0..63 r, 64..127 z; k<64 Whh, 64..71 W', 72..87 zero
__device__ __half g_B2aImg[2*64*16];    // xn: k<8 W'_n, 8..15 zero
__device__ __half g_B2bImg[2*64*72];    // hn: k<64 Whh_n, 64..71 zero
__device__ __half g_W2h[2*96*360];      // k_final W2 image

// ---------------- helpers ----------------
__device__ __forceinline__ uint32_t smem_u32(const void* p) {
    uint32_t a;
    asm("{ .reg .u64 t; cvta.to.shared.u64 t, %1; cvt.u32.u64 %0, t; }" : "=r"(a) : "l"(p));
    return a;
}
__device__ __forceinline__ void ldmat4(uint32_t* f, uint32_t addr) {
    asm volatile("ldmatrix.sync.aligned.m8n8.x4.shared.b16 {%0,%1,%2,%3}, [%4];"
        : "=r"(f[0]), "=r"(f[1]), "=r"(f[2]), "=r"(f[3]) : "r"(addr));
}
__device__ __forceinline__ void mma16816(float* c, const uint32_t* a, uint32_t b0, uint32_t b1) {
    asm volatile("mma.sync.aligned.m16n8k16.row.col.f32.f16.f16.f32 "
        "{%0,%1,%2,%3}, {%4,%5,%6,%7}, {%8,%9}, {%0,%1,%2,%3};"
        : "+f"(c[0]), "+f"(c[1]), "+f"(c[2]), "+f"(c[3])
        : "r"(a[0]), "r"(a[1]), "r"(a[2]), "r"(a[3]), "r"(b0), "r"(b1));
}
#define CPA16(sa, gp) asm volatile("cp.async.cg.shared.global [%0], [%1], 16;" :: "r"(sa), "l"(gp))
#define CPA_WAIT()    asm volatile("cp.async.wait_all;" ::: "memory")
__device__ __forceinline__ float sigf(float x)  { return 1.f / (1.f + __expf(-x)); }
__device__ __forceinline__ float tanhff(float x){ float e = __expf(2.f*x); return 1.f - 2.f/(e + 1.f); }
__device__ __forceinline__ void h2split(float v0, float v1, __half2* hi, __half2* lo) {
    __half a = __float2half_rn(v0), b = __float2half_rn(v1);
    *hi = __halves2half2(a, b);
    *lo = __halves2half2(__float2half_rn(v0 - __half2float(a)),
                         __float2half_rn(v1 - __half2float(b)));
}

// ---------------- small prep kernels ----------------
__global__ void k_detect(const unsigned int* ei_raw) {
    bool all0 = true;
    for (int i = 0; i < 16; i++) if (ei_raw[2*i + 1] != 0u) all0 = false;
    g_flag64 = all0 ? 1 : 0;
}
__global__ void k_convert(const void* ei) {
    int e = blockIdx.x * blockDim.x + threadIdx.x;
    if (e >= Ee) return;
    if (g_flag64) {
        const long long* p = (const long long*)ei;
        g_src[e] = (int)p[e]; g_tgt[e] = (int)p[Ee + e];
    } else {
        const int* p = (const int*)ei;
        g_src[e] = p[e]; g_tgt[e] = p[Ee + e];
    }
}
__global__ void k_zero() {
    int i = blockIdx.x * blockDim.x + threadIdx.x;
    if (i < Nn) {
        g_cnt_f[i] = 0; g_cnt_b[i] = 0; g_cur_f[i] = 0; g_cur_b[i] = 0;
        g_deg_f[i] = 0.f; g_deg_b[i] = 0.f;
    }
}
__global__ void k_w2(const float* __restrict__ filtW, const float* __restrict__ filtB,
                     const float* __restrict__ decW,  const float* __restrict__ decB) {
    int c = threadIdx.x, k = blockIdx.x;
    if (k < KCAT) {
        float acc = 0.f;
        for (int j = 0; j < Hh; j++) acc += filtW[k*Hh + j] * decW[j*CDEC + c];
        g_W2[k*CDEC + c] = acc;
    } else {
        float acc = decB[c];
        for (int j = 0; j < Hh; j++) acc += filtB[j] * decW[j*CDEC + c];
        g_b2[c] = acc;
    }
}
__global__ void k_w2img() {
    int idx = blockIdx.x * blockDim.x + threadIdx.x;
    if (idx >= 2*96*360) return;
    int prec = idx / 34560, rem = idx % 34560;
    int n = rem / 360, q = rem % 360;
    int c = q / 72, k = q % 72;
    float val = (k < 64) ? g_W2[(c*64 + k)*CDEC + n] : 0.f;
    __half hi = __float2half_rn(val);
    g_W2h[idx] = prec ? __float2half_rn(val - __half2float(hi)) : hi;
}
__global__ void k_wprime(const float* __restrict__ encW, const float* __restrict__ Wih) {
    int idx = blockIdx.x * blockDim.x + threadIdx.x;
    if (idx >= 192*8) return;
    int g = idx >> 3, f = idx & 7;
    float acc = 0.f;
    for (int h = 0; h < 64; h++) acc += encW[f*64 + h] * Wih[g*64 + h];
    g_Wp[g*8 + f] = acc;
}
__global__ __launch_bounds__(192)
void k_cnode(const float* __restrict__ encB, const float* __restrict__ nodeEmb,
             const float* __restrict__ Wih,  const float* __restrict__ bih,
             const float* __restrict__ bhh) {
    __shared__ float sEB[16][68];
    int tid = threadIdx.x, n0 = blockIdx.x * 16;
    for (int i = tid; i < 16*64; i += 192) {
        int nl = i >> 6, k = i & 63;
        sEB[nl][k] = encB[k] + nodeEmb[(n0 + nl)*64 + k];
    }
    __syncthreads();
    int c = tid;
    float w[64];
    #pragma unroll
    for (int k = 0; k < 64; k++) w[k] = Wih[c*64 + k];
    float bb = bih[c] + ((c < 128) ? bhh[c] : 0.f);
    for (int nl = 0; nl < 16; nl++) {
        float acc = bb;
        #pragma unroll
        for (int k = 0; k < 64; k++) acc += sEB[nl][k] * w[k];
        g_Cnode16[(size_t)(n0 + nl)*192 + c] = __float2half_rn(acc);
    }
}
// new strides: B1 [prec][128][88], B2a [prec][64][16], B2b [prec][64][72]
__global__ void k_prepw(const float* __restrict__ Whh) {
    int idx = blockIdx.x * blockDim.x + threadIdx.x;
    if (idx >= 33792) return;
    float val = 0.f;
    if (idx < 22528) {
        int prec = idx / 11264, rem = idx % 11264;
        int n = rem / 88, k = rem % 88;
        if (k < 64)      val = Whh[n*64 + k];
        else if (k < 72) val = g_Wp[n*8 + (k - 64)];
        __half hi = __float2half_rn(val);
        g_B1Img[idx] = prec ? __float2half_rn(val - __half2float(hi)) : hi;
        return;
    }
    if (idx < 24576) {
        int q = idx - 22528;
        int prec = q / 1024, rem = q % 1024;
        int n = rem / 16, k = rem % 16;
        if (k < 8) val = g_Wp[(128 + n)*8 + k];
        __half hi = __float2half_rn(val);
        g_B2aImg[q] = prec ? __float2half_rn(val - __half2float(hi)) : hi;
        return;
    }
    {
        int q = idx - 24576;
        int prec = q / 4608, rem = q % 4608;
        int n = rem / 72, k = rem % 72;
        if (k < 64) val = Whh[(128 + n)*64 + k];
        __half hi = __float2half_rn(val);
        g_B2bImg[q] = prec ? __float2half_rn(val - __half2float(hi)) : hi;
    }
}

// ================= fused 12-step GRU v4: ldmatrix-B operands =================
// 64 rows/block, 256 thr, 2 blocks/SM. 8 warps: mw=wid&1, nw=wid>>1.
#define GA_HI  0
#define GA_LO  9216
#define GB1    18432
#define GB2A   63488
#define GB2B   67584
#define GC16   86016
#define GXR    111104
#define GRU_SMEM 115200

__global__ __launch_bounds__(256, 2)
void k_gru(const float* __restrict__ x, const float* __restrict__ bhh)
{
    extern __shared__ __align__(16) char sm[];
    __half* Ahi = (__half*)(sm + GA_HI);
    __half* Alo = (__half*)(sm + GA_LO);
    __half* sC  = (__half*)(sm + GC16);     // [64][196] (192 used)
    float*  sXr = (float*)(sm + GXR);

    int tid = threadIdx.x, lane = tid & 31, wid = tid >> 5;
    int mw = wid & 1, nw = wid >> 1;
    int m0 = blockIdx.x * 64;

    // one-time loads: B images + C16
    {
        const uint4* s1 = (const uint4*)g_B1Img;  uint4* d1 = (uint4*)(sm + GB1);
        for (int i = tid; i < 45056/16; i += 256) d1[i] = s1[i];
        const uint4* s2 = (const uint4*)g_B2aImg; uint4* d2 = (uint4*)(sm + GB2A);
        if (tid < 4096/16) d2[tid] = s2[tid];
        const uint4* s3 = (const uint4*)g_B2bImg; uint4* d3 = (uint4*)(sm + GB2B);
        for (int i = tid; i < 18432/16; i += 256) d3[i] = s3[i];
        // C16: 64 rows x 192 halves, smem stride 196 halves (392B, 8B-aligned) via uint2
        for (int i = tid; i < 3072; i += 256) {
            int row = i / 48, ch = i % 48;
            int node = (m0 + row) % Nn;
            const uint2* srcc = (const uint2*)(g_Cnode16 + (size_t)node*192) + ch;
            *((uint2*)(sC + row*196) + ch) = *srcc;
        }
    }

    uint32_t sb = smem_u32(sm);

    // prefetch x[0]
    if (tid < 128) {
        int row = tid >> 1, ch = tid & 1;
        int mm = m0 + row, b2 = mm / Nn, n2 = mm - b2 * Nn;
        CPA16(sb + GXR + (row*8 + ch*4)*4, &x[(((size_t)b2*Tt + 0)*Nn + n2)*Ff + ch*4]);
    }
    CPA_WAIT();
    __syncthreads();

    // fragment indices
    int g  = lane >> 2;
    int c2 = 2 * (lane & 3);
    int arow = lane & 15, acol8 = (lane >> 4) * 8;

    // ldmatrix-B per-lane row addressing: matq = lane>>3 -> (ntp, khalf)
    int ntp   = (lane >> 4) & 1;
    int khalf = (lane >> 3) & 1;
    int nnB   = nw*16 + ntp*8 + (lane & 7);
    uint32_t offR = (uint32_t)((nnB*88 + khalf*8) * 2);
    uint32_t offZ = offR + 64*88*2;
    uint32_t offN = (uint32_t)((nnB*16 + khalf*8) * 2);
    uint32_t offH = (uint32_t)((nnB*72 + khalf*8) * 2);

    float bhn[2][2];
    #pragma unroll
    for (int nt = 0; nt < 2; nt++)
        #pragma unroll
        for (int c = 0; c < 2; c++)
            bhn[nt][c] = __ldg(&bhh[128 + nw*16 + nt*8 + c2 + c]);

    float h[16];
    #pragma unroll
    for (int i = 0; i < 16; i++) h[i] = 0.f;

    int xrow = tid >> 2, xp = (tid & 3) * 2;

    for (int t = 0; t < Tt; t++) {
        int cur = t & 1;

        // ---- A-build: h frags + x pair ----
        #pragma unroll
        for (int mt = 0; mt < 2; mt++)
            #pragma unroll
            for (int q2 = 0; q2 < 2; q2++) {
                int row = mw*32 + mt*16 + g + q2*8;
                #pragma unroll
                for (int nt = 0; nt < 2; nt++) {
                    int j0 = nw*16 + nt*8 + c2;
                    int hi = mt*8 + q2*4 + nt*2;
                    h2split(h[hi], h[hi+1],
                            (__half2*)(Ahi + row*72 + j0), (__half2*)(Alo + row*72 + j0));
                }
            }
        h2split(sXr[cur*512 + xrow*8 + xp], sXr[cur*512 + xrow*8 + xp + 1],
                (__half2*)(Ahi + xrow*72 + 64 + xp), (__half2*)(Alo + xrow*72 + 64 + xp));
        __syncthreads();   // S1: A complete

        // prefetch x[t+1]
        if (t + 1 < Tt && tid < 128) {
            int row = tid >> 1, ch = tid & 1;
            int mm = m0 + row, b2 = mm / Nn, n2 = mm - b2 * Nn;
            CPA16(sb + GXR + ((1-cur)*512 + row*8 + ch*4)*4,
                  &x[(((size_t)b2*Tt + (t+1))*Nn + n2)*Ff + ch*4]);
        }

        // ---- 3-pass hi/lo mma with ldmatrix-B ----
        float aR[2][2][4], aZ[2][2][4], aN[2][2][4], aH[2][2][4];
        #pragma unroll
        for (int i = 0; i < 2; i++)
            #pragma unroll
            for (int j = 0; j < 2; j++)
                #pragma unroll
                for (int q = 0; q < 4; q++) {
                    aR[i][j][q] = 0.f; aZ[i][j][q] = 0.f;
                    aN[i][j][q] = 0.f; aH[i][j][q] = 0.f;
                }

        #pragma unroll
        for (int p = 0; p < 3; p++) {
            uint32_t aB  = sb + ((p == 1) ? GA_LO : GA_HI);
            uint32_t b1B = sb + GB1  + ((p == 2) ? 22528u : 0u);
            uint32_t b2aB= sb + GB2A + ((p == 2) ? 2048u  : 0u);
            uint32_t b2bB= sb + GB2B + ((p == 2) ? 9216u  : 0u);
            #pragma unroll
            for (int ks = 0; ks < 5; ks++) {
                uint32_t afr[2][4];
                #pragma unroll
                for (int mt = 0; mt < 2; mt++)
                    ldmat4(afr[mt], aB + ((mw*32 + mt*16 + arow)*72 + ks*16 + acol8) * 2);

                uint32_t fR[4], fZ[4];
                ldmat4(fR, b1B + offR + ks*32);
                mma16816(aR[0][0], afr[0], fR[0], fR[1]);
                mma16816(aR[1][0], afr[1], fR[0], fR[1]);
                mma16816(aR[0][1], afr[0], fR[2], fR[3]);
                mma16816(aR[1][1], afr[1], fR[2], fR[3]);
                ldmat4(fZ, b1B + offZ + ks*32);
                mma16816(aZ[0][0], afr[0], fZ[0], fZ[1]);
                mma16816(aZ[1][0], afr[1], fZ[0], fZ[1]);
                mma16816(aZ[0][1], afr[0], fZ[2], fZ[3]);
                mma16816(aZ[1][1], afr[1], fZ[2], fZ[3]);
                if (ks == 4) {
                    uint32_t fN[4];
                    ldmat4(fN, b2aB + offN);
                    mma16816(aN[0][0], afr[0], fN[0], fN[1]);
                    mma16816(aN[1][0], afr[1], fN[0], fN[1]);
                    mma16816(aN[0][1], afr[0], fN[2], fN[3]);
                    mma16816(aN[1][1], afr[1], fN[2], fN[3]);
                } else {
                    uint32_t fH[4];
                    ldmat4(fH, b2bB + offH + ks*32);
                    mma16816(aH[0][0], afr[0], fH[0], fH[1]);
                    mma16816(aH[1][0], afr[1], fH[0], fH[1]);
                    mma16816(aH[0][1], afr[0], fH[2], fH[3]);
                    mma16816(aH[1][1], afr[1], fH[2], fH[3]);
                }
            }
        }

        // ---- gates: register math + conflict-free C reads ----
        #pragma unroll
        for (int mt = 0; mt < 2; mt++)
            #pragma unroll
            for (int q2 = 0; q2 < 2; q2++) {
                int row = mw*32 + mt*16 + g + q2*8;
                #pragma unroll
                for (int nt = 0; nt < 2; nt++) {
                    int j0 = nw*16 + nt*8 + c2;
                    float2 fr = __half22float2(*(__half2*)&sC[row*196 + j0]);
                    float2 fz = __half22float2(*(__half2*)&sC[row*196 + 64 + j0]);
                    float2 fn = __half22float2(*(__half2*)&sC[row*196 + 128 + j0]);
                    #pragma unroll
                    for (int c = 0; c < 2; c++) {
                        int ai = q2*2 + c;
                        float rv  = aR[mt][nt][ai] + (c ? fr.y : fr.x);
                        float zv  = aZ[mt][nt][ai] + (c ? fz.y : fz.x);
                        float xnv = aN[mt][nt][ai] + (c ? fn.y : fn.x);
                        float hnv = aH[mt][nt][ai] + bhn[nt][c];
                        float rg = sigf(rv), zg = sigf(zv);
                        float ng = tanhff(xnv + rg * hnv);
                        int hi = mt*8 + q2*4 + nt*2 + c;
                        h[hi] = (1.f - zg) * ng + zg * h[hi];
                    }
                }
            }

        CPA_WAIT();
        __syncthreads();   // S2: all mma done, x[t+1] landed
    }

    // ---- final h -> gmem ----
    #pragma unroll
    for (int mt = 0; mt < 2; mt++)
        #pragma unroll
        for (int q2 = 0; q2 < 2; q2++) {
            int row = mw*32 + mt*16 + g + q2*8;
            #pragma unroll
            for (int nt = 0; nt < 2; nt++) {
                int j0 = nw*16 + nt*8 + c2;
                int hi = mt*8 + q2*4 + nt*2;
                size_t o = (size_t)(m0 + row)*Hh + j0;
                *(float2*)&g_h0[o] = make_float2(h[hi], h[hi+1]);
                *(__half2*)&g_h16[o] = __halves2half2(__float2half_rn(h[hi]),
                                                      __float2half_rn(h[hi+1]));
            }
        }
}

// ---------------- CSR build ----------------
__global__ void k_count(const float* __restrict__ ew) {
    int e = blockIdx.x * blockDim.x + threadIdx.x;
    if (e >= Ee) return;
    int s = g_src[e], t = g_tgt[e];
    float w = ew[e];
    atomicAdd(&g_cnt_f[t], 1);  atomicAdd(&g_deg_f[t], w);
    atomicAdd(&g_cnt_b[s], 1);  atomicAdd(&g_deg_b[s], w);
}
__global__ void k_scan() {
    __shared__ int sbuf[1024];
    __shared__ int sOff;
    int tid = threadIdx.x;
    for (int which = 0; which < 2; ++which) {
        const int* cnt = which ? g_cnt_b : g_cnt_f;
        int* rp        = which ? g_rowptr_b : g_rowptr_f;
        if (tid == 0) { sOff = 0; rp[0] = 0; }
        __syncthreads();
        for (int base = 0; base < Nn; base += 1024) {
            int i = base + tid;
            int v = (i < Nn) ? cnt[i] : 0;
            sbuf[tid] = v;
            __syncthreads();
            for (int d = 1; d < 1024; d <<= 1) {
                int add = (tid >= d) ? sbuf[tid - d] : 0;
                __syncthreads();
                sbuf[tid] += add;
                __syncthreads();
            }
            if (i < Nn) rp[i + 1] = sOff + sbuf[tid];
            __syncthreads();
            if (tid == 0) sOff += sbuf[1023];
            __syncthreads();
        }
        __syncthreads();
    }
}
__global__ void k_fill(const float* __restrict__ ew) {
    int e = blockIdx.x * blockDim.x + threadIdx.x;
    if (e >= Ee) return;
    int s = g_src[e], t = g_tgt[e];
    float w = ew[e];
    float df = g_deg_f[t]; df = (df == 0.f) ? 1.f : df;
    int pf = g_rowptr_f[t] + atomicAdd(&g_cur_f[t], 1);
    g_adjn_f[pf] = s;  g_adjw_f[pf] = w / df;
    float db = g_deg_b[s]; db = (db == 0.f) ? 1.f : db;
    int pb = g_rowptr_b[s] + atomicAdd(&g_cur_b[s], 1);
    g_adjn_b[pb] = t;  g_adjw_b[pb] = w / db;
}

// ---------------- diffusion props (fp16 gather, fp32 accumulate) ----------------
__device__ __forceinline__ void prop16(const __half* __restrict__ hin,
                                       float* __restrict__ outF, __half* __restrict__ outH,
                                       const int* __restrict__ rowptr,
                                       const int* __restrict__ adjn,
                                       const float* __restrict__ adjw,
                                       int node, int lane) {
    int beg = rowptr[node], end = rowptr[node + 1];
    float acc[Bb][2];
    #pragma unroll
    for (int b = 0; b < Bb; b++) { acc[b][0] = 0.f; acc[b][1] = 0.f; }
    for (int e = beg; e < end; e++) {
        int s = adjn[e];
        float w = adjw[e];
        #pragma unroll
        for (int b = 0; b < Bb; b++) {
            __half2 hv = ((const __half2*)(hin + ((size_t)b * Nn + s) * Hh))[lane];
            float2 f = __half22float2(hv);
            acc[b][0] += f.x * w;
            acc[b][1] += f.y * w;
        }
    }
    #pragma unroll
    for (int b = 0; b < Bb; b++) {
        size_t o = ((size_t)b * Nn + node) * Hh + 2*lane;
        *(float2*)&outF[o] = make_float2(acc[b][0], acc[b][1]);
        if (outH)
            *(__half2*)&outH[o] = __halves2half2(__float2half_rn(acc[b][0]),
                                                 __float2half_rn(acc[b][1]));
    }
}
__global__ void k_prop_h1() {
    int gw = (blockIdx.x * blockDim.x + threadIdx.x) >> 5;
    int lane = threadIdx.x & 31;
    if (gw >= 2*Nn) return;
    if (gw < Nn) prop16(g_h16, g_z0, g_z016, g_rowptr_f, g_adjn_f, g_adjw_f, gw, lane);
    else         prop16(g_h16, g_z2, g_z216, g_rowptr_b, g_adjn_b, g_adjw_b, gw - Nn, lane);
}
__global__ void k_prop_h2() {
    int gw = (blockIdx.x * blockDim.x + threadIdx.x) >> 5;
    int lane = threadIdx.x & 31;
    if (gw >= 2*Nn) return;
    if (gw < Nn) prop16(g_z016, g_z1, (__half*)0, g_rowptr_f, g_adjn_f, g_adjw_f, gw, lane);
    else         prop16(g_z216, g_z3, (__half*)0, g_rowptr_b, g_adjn_b, g_adjw_b, gw - Nn, lane);
}

// ---------------- k_final: HMMA 3-pass hi/lo ----------------
#define FB_A     138240
#define FIN_SMEM 156672

__global__ __launch_bounds__(256, 1)
void k_final(float* __restrict__ out) {
    extern __shared__ __align__(16) char sm[];
    __half* Ahi = (__half*)(sm + FB_A);
    __half* Alo = Ahi + 64*72;

    int tid = threadIdx.x, lane = tid & 31, wid = tid >> 5;
    int mw = wid & 1, nw = wid >> 1;
    int m0 = blockIdx.x * 64;

    {
        const uint4* sw = (const uint4*)g_W2h;
        uint4* dw = (uint4*)sm;
        for (int i = tid; i < 138240/16; i += 256) dw[i] = sw[i];
    }

    int r = tid >> 2, kq = (tid & 3) * 16;
    int arow = lane & 15, acol8 = (lane >> 4) * 8;
    int bn = lane >> 2, bc2 = 2 * (lane & 3);

    float acc[2][3][4];
    #pragma unroll
    for (int i = 0; i < 2; i++)
        #pragma unroll
        for (int j = 0; j < 3; j++)
            #pragma unroll
            for (int q = 0; q < 4; q++) acc[i][j][q] = 0.f;

    uint32_t sb = smem_u32(sm);
    const float* srcs[5] = { g_h0, g_z0, g_z1, g_z2, g_z3 };

    for (int c = 0; c < 5; c++) {
        __syncthreads();
        const float* S = srcs[c] + (size_t)(m0 + r)*64 + kq;
        #pragma unroll
        for (int j = 0; j < 16; j += 2)
            h2split(S[j], S[j+1],
                    (__half2*)(Ahi + r*72 + kq + j), (__half2*)(Alo + r*72 + kq + j));
        __syncthreads();

        #pragma unroll
        for (int p = 0; p < 3; p++) {
            uint32_t aB = sb + FB_A + ((p == 1) ? 64*72*2 : 0);
            uint32_t wB = (p == 2) ? (uint32_t)(34560*2) : 0u;
            #pragma unroll
            for (int ks = 0; ks < 4; ks++) {
                uint32_t afr[2][4];
                #pragma unroll
                for (int mt = 0; mt < 2; mt++)
                    ldmat4(afr[mt], aB + ((mw*32 + mt*16 + arow)*72 + ks*16 + acol8) * 2);
                #pragma unroll
                for (int nt = 0; nt < 3; nt++) {
                    int n = nw*24 + nt*8 + bn;
                    uint32_t bo = wB + ((n*360 + c*72 + ks*16 + bc2) * 2);
                    uint32_t b0 = *(const uint32_t*)(sm + bo);
                    uint32_t b1 = *(const uint32_t*)(sm + bo + 16);
                    mma16816(acc[0][nt], afr[0], b0, b1);
                    mma16816(acc[1][nt], afr[1], b0, b1);
                }
            }
        }
    }

    int g = lane >> 2, c2 = 2 * (lane & 3);
    #pragma unroll
    for (int mt = 0; mt < 2; mt++)
        #pragma unroll
        for (int q2 = 0; q2 < 2; q2++) {
            int row = mw*32 + mt*16 + g + q2*8;
            int m = m0 + row, b = m / Nn, n = m - b * Nn;
            #pragma unroll
            for (int nt = 0; nt < 3; nt++) {
                int col = nw*24 + nt*8 + c2;
                int tt = col >> 3, f = col & 7;
                float2 v = make_float2(acc[mt][nt][q2*2]     + __ldg(&g_b2[col]),
                                       acc[mt][nt][q2*2 + 1] + __ldg(&g_b2[col + 1]));
                *(float2*)&out[(((size_t)b * HOR + tt) * Nn + n) * Ff + f] = v;
            }
        }
}

// ---------------- launch (k_gru at index 3 for ncu capture) ----------------
extern "C" void kernel_launch(void* const* d_in, const int* in_sizes, int n_in,
                              void* d_out, int out_size) {
    const float* x     = (const float*)d_in[0];
    const void*  ei    = d_in[1];
    const float* ew    = (const float*)d_in[2];
    const float* encW  = (const float*)d_in[3];
    const float* encB  = (const float*)d_in[4];
    const float* nemb  = (const float*)d_in[5];
    const float* Wih   = (const float*)d_in[6];
    const float* Whh   = (const float*)d_in[7];
    const float* bih   = (const float*)d_in[8];
    const float* bhh   = (const float*)d_in[9];
    const float* filtW = (const float*)d_in[10];
    const float* filtB = (const float*)d_in[11];
    const float* decW  = (const float*)d_in[12];
    const float* decB  = (const float*)d_in[13];
    float* out = (float*)d_out;

    cudaFuncSetAttribute(k_gru,   cudaFuncAttributeMaxDynamicSharedMemorySize, GRU_SMEM);
    cudaFuncSetAttribute(k_final, cudaFuncAttributeMaxDynamicSharedMemorySize, FIN_SMEM);

    k_wprime<<<6, 256>>>(encW, Wih);                       // 0
    k_cnode<<<Nn/16, 192>>>(encB, nemb, Wih, bih, bhh);    // 1
    k_prepw<<<(33792 + 255) / 256, 256>>>(Whh);            // 2
    k_gru<<<Mm / 64, 256, GRU_SMEM>>>(x, bhh);             // 3  <- ncu captures this
    k_detect<<<1, 1>>>((const unsigned int*)ei);           // 4
    k_convert<<<(Ee + 255) / 256, 256>>>(ei);              // 5
    k_zero<<<(Nn + 255) / 256, 256>>>();                   // 6
    k_w2<<<KCAT + 1, CDEC>>>(filtW, filtB, decW, decB);    // 7
    k_w2img<<<(2*96*360 + 255) / 256, 256>>>();            // 8
    k_count<<<(Ee + 255) / 256, 256>>>(ew);                // 9
    k_scan<<<1, 1024>>>();                                 // 10
    k_fill<<<(Ee + 255) / 256, 256>>>(ew);                 // 11
    k_prop_h1<<<(2*Nn*32 + 255) / 256, 256>>>();           // 12
    k_prop_h2<<<(2*Nn*32 + 255) / 256, 256>>>();           // 13
    k_final<<<Mm / 64, 256, FIN_SMEM>>>(out);              // 14
}

// round 15
// speedup vs baseline: 2.7723x; 1.2734x over previous
#include <cuda_runtime.h>
#include <cuda_fp16.h>
#include <math.h>
#include <stdint.h>

#define Nn   10000
#define Bb   8
#define Tt   12
#define Ff   8
#define Hh   64
#define Ee   320000
#define HOR  12
#define Mm   (Bb*Nn)
#define KCAT 320
#define CDEC 96

// ---------------- device scratch ----------------
__device__ float g_h0[Mm*Hh];
__device__ float g_z0[Mm*Hh];
__device__ float g_z1[Mm*Hh];
__device__ float g_z2[Mm*Hh];
__device__ float g_z3[Mm*Hh];
__device__ __half g_h16[Mm*Hh];
__device__ __half g_z016[Mm*Hh];
__device__ __half g_z216[Mm*Hh];
__device__ int   g_src[Ee], g_tgt[Ee];
__device__ int   g_rowptr_f[Nn+1], g_rowptr_b[Nn+1];
__device__ int   g_cnt_f[Nn], g_cnt_b[Nn], g_cur_f[Nn], g_cur_b[Nn];
__device__ float g_deg_f[Nn], g_deg_b[Nn];
__device__ int   g_adjn_f[Ee]; __device__ float g_adjw_f[Ee];
__device__ int   g_adjn_b[Ee]; __device__ float g_adjw_b[Ee];
__device__ float g_W2[KCAT*CDEC];
__device__ float g_b2[CDEC];
__device__ int   g_flag64;
__device__ float g_Wp[192*8];                   // W' = encW@Wih
__device__ __half g_Cnode16[(size_t)Nn*192];    // C[n][g] fp16 (bih + bhh_rz folded)

// fp16 hi/lo weight images, 16B-aligned row strides for ldmatrix
__device__ __half g_B1Img [2*128*88];   // rz: rows 0..63 r, 64..127 z
__device__ __half g_B2aImg[2*64*16];    // xn
__device__ __half g_B2bImg[2*64*72];    // hn
__device__ __half g_W2h[2*96*360];      // k_final W2 image

// ---------------- helpers ----------------
__device__ __forceinline__ uint32_t smem_u32(const void* p) {
    uint32_t a;
    asm("{ .reg .u64 t; cvta.to.shared.u64 t, %1; cvt.u32.u64 %0, t; }" : "=r"(a) : "l"(p));
    return a;
}
__device__ __forceinline__ void ldmat4(uint32_t* f, uint32_t addr) {
    asm volatile("ldmatrix.sync.aligned.m8n8.x4.shared.b16 {%0,%1,%2,%3}, [%4];"
        : "=r"(f[0]), "=r"(f[1]), "=r"(f[2]), "=r"(f[3]) : "r"(addr));
}
__device__ __forceinline__ void mma16816(float* c, const uint32_t* a, uint32_t b0, uint32_t b1) {
    asm volatile("mma.sync.aligned.m16n8k16.row.col.f32.f16.f16.f32 "
        "{%0,%1,%2,%3}, {%4,%5,%6,%7}, {%8,%9}, {%0,%1,%2,%3};"
        : "+f"(c[0]), "+f"(c[1]), "+f"(c[2]), "+f"(c[3])
        : "r"(a[0]), "r"(a[1]), "r"(a[2]), "r"(a[3]), "r"(b0), "r"(b1));
}
#define CPA16(sa, gp) asm volatile("cp.async.cg.shared.global [%0], [%1], 16;" :: "r"(sa), "l"(gp))
#define CPA_WAIT()    asm volatile("cp.async.wait_all;" ::: "memory")
__device__ __forceinline__ float sigf(float x)  { return 1.f / (1.f + __expf(-x)); }
__device__ __forceinline__ float tanhff(float x){ float e = __expf(2.f*x); return 1.f - 2.f/(e + 1.f); }
__device__ __forceinline__ void h2split(float v0, float v1, __half2* hi, __half2* lo) {
    __half a = __float2half_rn(v0), b = __float2half_rn(v1);
    *hi = __halves2half2(a, b);
    *lo = __halves2half2(__float2half_rn(v0 - __half2float(a)),
                         __float2half_rn(v1 - __half2float(b)));
}

// ---------------- small prep kernels ----------------
__global__ void k_detect(const unsigned int* ei_raw) {
    bool all0 = true;
    for (int i = 0; i < 16; i++) if (ei_raw[2*i + 1] != 0u) all0 = false;
    g_flag64 = all0 ? 1 : 0;
}
__global__ void k_convert(const void* ei) {
    int e = blockIdx.x * blockDim.x + threadIdx.x;
    if (e >= Ee) return;
    if (g_flag64) {
        const long long* p = (const long long*)ei;
        g_src[e] = (int)p[e]; g_tgt[e] = (int)p[Ee + e];
    } else {
        const int* p = (const int*)ei;
        g_src[e] = p[e]; g_tgt[e] = p[Ee + e];
    }
}
__global__ void k_zero() {
    int i = blockIdx.x * blockDim.x + threadIdx.x;
    if (i < Nn) {
        g_cnt_f[i] = 0; g_cnt_b[i] = 0; g_cur_f[i] = 0; g_cur_b[i] = 0;
        g_deg_f[i] = 0.f; g_deg_b[i] = 0.f;
    }
}
__global__ void k_w2(const float* __restrict__ filtW, const float* __restrict__ filtB,
                     const float* __restrict__ decW,  const float* __restrict__ decB) {
    int c = threadIdx.x, k = blockIdx.x;
    if (k < KCAT) {
        float acc = 0.f;
        for (int j = 0; j < Hh; j++) acc += filtW[k*Hh + j] * decW[j*CDEC + c];
        g_W2[k*CDEC + c] = acc;
    } else {
        float acc = decB[c];
        for (int j = 0; j < Hh; j++) acc += filtB[j] * decW[j*CDEC + c];
        g_b2[c] = acc;
    }
}
__global__ void k_w2img() {
    int idx = blockIdx.x * blockDim.x + threadIdx.x;
    if (idx >= 2*96*360) return;
    int prec = idx / 34560, rem = idx % 34560;
    int n = rem / 360, q = rem % 360;
    int c = q / 72, k = q % 72;
    float val = (k < 64) ? g_W2[(c*64 + k)*CDEC + n] : 0.f;
    __half hi = __float2half_rn(val);
    g_W2h[idx] = prec ? __float2half_rn(val - __half2float(hi)) : hi;
}
__global__ void k_wprime(const float* __restrict__ encW, const float* __restrict__ Wih) {
    int idx = blockIdx.x * blockDim.x + threadIdx.x;
    if (idx >= 192*8) return;
    int g = idx >> 3, f = idx & 7;
    float acc = 0.f;
    for (int h = 0; h < 64; h++) acc += encW[f*64 + h] * Wih[g*64 + h];
    g_Wp[g*8 + f] = acc;
}
__global__ __launch_bounds__(192)
void k_cnode(const float* __restrict__ encB, const float* __restrict__ nodeEmb,
             const float* __restrict__ Wih,  const float* __restrict__ bih,
             const float* __restrict__ bhh) {
    __shared__ float sEB[16][68];
    int tid = threadIdx.x, n0 = blockIdx.x * 16;
    for (int i = tid; i < 16*64; i += 192) {
        int nl = i >> 6, k = i & 63;
        sEB[nl][k] = encB[k] + nodeEmb[(n0 + nl)*64 + k];
    }
    __syncthreads();
    int c = tid;
    float w[64];
    #pragma unroll
    for (int k = 0; k < 64; k++) w[k] = Wih[c*64 + k];
    float bb = bih[c] + ((c < 128) ? bhh[c] : 0.f);
    for (int nl = 0; nl < 16; nl++) {
        float acc = bb;
        #pragma unroll
        for (int k = 0; k < 64; k++) acc += sEB[nl][k] * w[k];
        g_Cnode16[(size_t)(n0 + nl)*192 + c] = __float2half_rn(acc);
    }
}
__global__ void k_prepw(const float* __restrict__ Whh) {
    int idx = blockIdx.x * blockDim.x + threadIdx.x;
    if (idx >= 33792) return;
    float val = 0.f;
    if (idx < 22528) {
        int prec = idx / 11264, rem = idx % 11264;
        int n = rem / 88, k = rem % 88;
        if (k < 64)      val = Whh[n*64 + k];
        else if (k < 72) val = g_Wp[n*8 + (k - 64)];
        __half hi = __float2half_rn(val);
        g_B1Img[idx] = prec ? __float2half_rn(val - __half2float(hi)) : hi;
        return;
    }
    if (idx < 24576) {
        int q = idx - 22528;
        int prec = q / 1024, rem = q % 1024;
        int n = rem / 16, k = rem % 16;
        if (k < 8) val = g_Wp[(128 + n)*8 + k];
        __half hi = __float2half_rn(val);
        g_B2aImg[q] = prec ? __float2half_rn(val - __half2float(hi)) : hi;
        return;
    }
    {
        int q = idx - 24576;
        int prec = q / 4608, rem = q % 4608;
        int n = rem / 72, k = rem % 72;
        if (k < 64) val = Whh[(128 + n)*64 + k];
        __half hi = __float2half_rn(val);
        g_B2bImg[q] = prec ? __float2half_rn(val - __half2float(hi)) : hi;
    }
}

// ================= fused 12-step GRU v5: A_hi-only (2-pass hi/lo B) =================
// 64 rows/block, 256 thr, 2 blocks/SM. 8 warps: mw=wid&1, nw=wid>>1.
// Passes: p0 = A_hi x B_hi, p1 = A_hi x B_lo. Dropped A_lo term (~6e-5 abs gate noise).
#define GA_HI  0
#define GB1    9216
#define GB2A   54272
#define GB2B   58368
#define GC16   76800
#define GXR    101888
#define GRU_SMEM 105984

__global__ __launch_bounds__(256, 2)
void k_gru(const float* __restrict__ x, const float* __restrict__ bhh)
{
    extern __shared__ __align__(16) char sm[];
    __half* Ahi = (__half*)(sm + GA_HI);
    __half* sC  = (__half*)(sm + GC16);     // [64][196] (192 used)
    float*  sXr = (float*)(sm + GXR);

    int tid = threadIdx.x, lane = tid & 31, wid = tid >> 5;
    int mw = wid & 1, nw = wid >> 1;
    int m0 = blockIdx.x * 64;

    // one-time loads: B images + C16
    {
        const uint4* s1 = (const uint4*)g_B1Img;  uint4* d1 = (uint4*)(sm + GB1);
        for (int i = tid; i < 45056/16; i += 256) d1[i] = s1[i];
        const uint4* s2 = (const uint4*)g_B2aImg; uint4* d2 = (uint4*)(sm + GB2A);
        if (tid < 4096/16) d2[tid] = s2[tid];
        const uint4* s3 = (const uint4*)g_B2bImg; uint4* d3 = (uint4*)(sm + GB2B);
        for (int i = tid; i < 18432/16; i += 256) d3[i] = s3[i];
        for (int i = tid; i < 3072; i += 256) {
            int row = i / 48, ch = i % 48;
            int node = (m0 + row) % Nn;
            const uint2* srcc = (const uint2*)(g_Cnode16 + (size_t)node*192) + ch;
            *((uint2*)(sC + row*196) + ch) = *srcc;
        }
    }

    uint32_t sb = smem_u32(sm);

    // prefetch x[0]
    if (tid < 128) {
        int row = tid >> 1, ch = tid & 1;
        int mm = m0 + row, b2 = mm / Nn, n2 = mm - b2 * Nn;
        CPA16(sb + GXR + (row*8 + ch*4)*4, &x[(((size_t)b2*Tt + 0)*Nn + n2)*Ff + ch*4]);
    }
    CPA_WAIT();
    __syncthreads();

    // fragment indices
    int g  = lane >> 2;
    int c2 = 2 * (lane & 3);
    int arow = lane & 15, acol8 = (lane >> 4) * 8;

    // ldmatrix-B per-lane row addressing
    int ntp   = (lane >> 4) & 1;
    int khalf = (lane >> 3) & 1;
    int nnB   = nw*16 + ntp*8 + (lane & 7);
    uint32_t offR = (uint32_t)((nnB*88 + khalf*8) * 2);
    uint32_t offZ = offR + 64*88*2;
    uint32_t offN = (uint32_t)((nnB*16 + khalf*8) * 2);
    uint32_t offH = (uint32_t)((nnB*72 + khalf*8) * 2);

    float bhn[2][2];
    #pragma unroll
    for (int nt = 0; nt < 2; nt++)
        #pragma unroll
        for (int c = 0; c < 2; c++)
            bhn[nt][c] = __ldg(&bhh[128 + nw*16 + nt*8 + c2 + c]);

    float h[16];
    #pragma unroll
    for (int i = 0; i < 16; i++) h[i] = 0.f;

    int xrow = tid >> 2, xp = (tid & 3) * 2;

    for (int t = 0; t < Tt; t++) {
        int cur = t & 1;

        // ---- A-build: hi-only converts ----
        #pragma unroll
        for (int mt = 0; mt < 2; mt++)
            #pragma unroll
            for (int q2 = 0; q2 < 2; q2++) {
                int row = mw*32 + mt*16 + g + q2*8;
                #pragma unroll
                for (int nt = 0; nt < 2; nt++) {
                    int j0 = nw*16 + nt*8 + c2;
                    int hi = mt*8 + q2*4 + nt*2;
                    *(__half2*)(Ahi + row*72 + j0) = __floats2half2_rn(h[hi], h[hi+1]);
                }
            }
        *(__half2*)(Ahi + xrow*72 + 64 + xp) =
            __floats2half2_rn(sXr[cur*512 + xrow*8 + xp], sXr[cur*512 + xrow*8 + xp + 1]);
        __syncthreads();   // S1: A complete

        // prefetch x[t+1]
        if (t + 1 < Tt && tid < 128) {
            int row = tid >> 1, ch = tid & 1;
            int mm = m0 + row, b2 = mm / Nn, n2 = mm - b2 * Nn;
            CPA16(sb + GXR + ((1-cur)*512 + row*8 + ch*4)*4,
                  &x[(((size_t)b2*Tt + (t+1))*Nn + n2)*Ff + ch*4]);
        }

        // ---- 2-pass mma: A_hi x (B_hi, B_lo) ----
        float aR[2][2][4], aZ[2][2][4], aN[2][2][4], aH[2][2][4];
        #pragma unroll
        for (int i = 0; i < 2; i++)
            #pragma unroll
            for (int j = 0; j < 2; j++)
                #pragma unroll
                for (int q = 0; q < 4; q++) {
                    aR[i][j][q] = 0.f; aZ[i][j][q] = 0.f;
                    aN[i][j][q] = 0.f; aH[i][j][q] = 0.f;
                }

        #pragma unroll
        for (int p = 0; p < 2; p++) {
            uint32_t b1B = sb + GB1  + (p ? 22528u : 0u);
            uint32_t b2aB= sb + GB2A + (p ? 2048u  : 0u);
            uint32_t b2bB= sb + GB2B + (p ? 9216u  : 0u);
            #pragma unroll
            for (int ks = 0; ks < 5; ks++) {
                uint32_t afr[2][4];
                #pragma unroll
                for (int mt = 0; mt < 2; mt++)
                    ldmat4(afr[mt], sb + GA_HI + ((mw*32 + mt*16 + arow)*72 + ks*16 + acol8) * 2);

                uint32_t fR[4], fZ[4];
                ldmat4(fR, b1B + offR + ks*32);
                mma16816(aR[0][0], afr[0], fR[0], fR[1]);
                mma16816(aR[1][0], afr[1], fR[0], fR[1]);
                mma16816(aR[0][1], afr[0], fR[2], fR[3]);
                mma16816(aR[1][1], afr[1], fR[2], fR[3]);
                ldmat4(fZ, b1B + offZ + ks*32);
                mma16816(aZ[0][0], afr[0], fZ[0], fZ[1]);
                mma16816(aZ[1][0], afr[1], fZ[0], fZ[1]);
                mma16816(aZ[0][1], afr[0], fZ[2], fZ[3]);
                mma16816(aZ[1][1], afr[1], fZ[2], fZ[3]);
                if (ks == 4) {
                    uint32_t fN[4];
                    ldmat4(fN, b2aB + offN);
                    mma16816(aN[0][0], afr[0], fN[0], fN[1]);
                    mma16816(aN[1][0], afr[1], fN[0], fN[1]);
                    mma16816(aN[0][1], afr[0], fN[2], fN[3]);
                    mma16816(aN[1][1], afr[1], fN[2], fN[3]);
                } else {
                    uint32_t fH[4];
                    ldmat4(fH, b2bB + offH + ks*32);
                    mma16816(aH[0][0], afr[0], fH[0], fH[1]);
                    mma16816(aH[1][0], afr[1], fH[0], fH[1]);
                    mma16816(aH[0][1], afr[0], fH[2], fH[3]);
                    mma16816(aH[1][1], afr[1], fH[2], fH[3]);
                }
            }
        }

        // ---- gates ----
        #pragma unroll
        for (int mt = 0; mt < 2; mt++)
            #pragma unroll
            for (int q2 = 0; q2 < 2; q2++) {
                int row = mw*32 + mt*16 + g + q2*8;
                #pragma unroll
                for (int nt = 0; nt < 2; nt++) {
                    int j0 = nw*16 + nt*8 + c2;
                    float2 fr = __half22float2(*(__half2*)&sC[row*196 + j0]);
                    float2 fz = __half22float2(*(__half2*)&sC[row*196 + 64 + j0]);
                    float2 fn = __half22float2(*(__half2*)&sC[row*196 + 128 + j0]);
                    #pragma unroll
                    for (int c = 0; c < 2; c++) {
                        int ai = q2*2 + c;
                        float rv  = aR[mt][nt][ai] + (c ? fr.y : fr.x);
                        float zv  = aZ[mt][nt][ai] + (c ? fz.y : fz.x);
                        float xnv = aN[mt][nt][ai] + (c ? fn.y : fn.x);
                        float hnv = aH[mt][nt][ai] + bhn[nt][c];
                        float rg = sigf(rv), zg = sigf(zv);
                        float ng = tanhff(xnv + rg * hnv);
                        int hi = mt*8 + q2*4 + nt*2 + c;
                        h[hi] = (1.f - zg) * ng + zg * h[hi];
                    }
                }
            }

        CPA_WAIT();
        __syncthreads();   // S2: all mma done, x[t+1] landed
    }

    // ---- final h -> gmem ----
    #pragma unroll
    for (int mt = 0; mt < 2; mt++)
        #pragma unroll
        for (int q2 = 0; q2 < 2; q2++) {
            int row = mw*32 + mt*16 + g + q2*8;
            #pragma unroll
            for (int nt = 0; nt < 2; nt++) {
                int j0 = nw*16 + nt*8 + c2;
                int hi = mt*8 + q2*4 + nt*2;
                size_t o = (size_t)(m0 + row)*Hh + j0;
                *(float2*)&g_h0[o] = make_float2(h[hi], h[hi+1]);
                *(__half2*)&g_h16[o] = __halves2half2(__float2half_rn(h[hi]),
                                                      __float2half_rn(h[hi+1]));
            }
        }
}

// ---------------- CSR build ----------------
__global__ void k_count(const float* __restrict__ ew) {
    int e = blockIdx.x * blockDim.x + threadIdx.x;
    if (e >= Ee) return;
    int s = g_src[e], t = g_tgt[e];
    float w = ew[e];
    atomicAdd(&g_cnt_f[t], 1);  atomicAdd(&g_deg_f[t], w);
    atomicAdd(&g_cnt_b[s], 1);  atomicAdd(&g_deg_b[s], w);
}
__global__ void k_scan() {
    __shared__ int sbuf[1024];
    __shared__ int sOff;
    int tid = threadIdx.x;
    for (int which = 0; which < 2; ++which) {
        const int* cnt = which ? g_cnt_b : g_cnt_f;
        int* rp        = which ? g_rowptr_b : g_rowptr_f;
        if (tid == 0) { sOff = 0; rp[0] = 0; }
        __syncthreads();
        for (int base = 0; base < Nn; base += 1024) {
            int i = base + tid;
            int v = (i < Nn) ? cnt[i] : 0;
            sbuf[tid] = v;
            __syncthreads();
            for (int d = 1; d < 1024; d <<= 1) {
                int add = (tid >= d) ? sbuf[tid - d] : 0;
                __syncthreads();
                sbuf[tid] += add;
                __syncthreads();
            }
            if (i < Nn) rp[i + 1] = sOff + sbuf[tid];
            __syncthreads();
            if (tid == 0) sOff += sbuf[1023];
            __syncthreads();
        }
        __syncthreads();
    }
}
__global__ void k_fill(const float* __restrict__ ew) {
    int e = blockIdx.x * blockDim.x + threadIdx.x;
    if (e >= Ee) return;
    int s = g_src[e], t = g_tgt[e];
    float w = ew[e];
    float df = g_deg_f[t]; df = (df == 0.f) ? 1.f : df;
    int pf = g_rowptr_f[t] + atomicAdd(&g_cur_f[t], 1);
    g_adjn_f[pf] = s;  g_adjw_f[pf] = w / df;
    float db = g_deg_b[s]; db = (db == 0.f) ? 1.f : db;
    int pb = g_rowptr_b[s] + atomicAdd(&g_cur_b[s], 1);
    g_adjn_b[pb] = t;  g_adjw_b[pb] = w / db;
}

// ---------------- diffusion props (fp16 gather, fp32 accumulate) ----------------
__device__ __forceinline__ void prop16(const __half* __restrict__ hin,
                                       float* __restrict__ outF, __half* __restrict__ outH,
                                       const int* __restrict__ rowptr,
                                       const int* __restrict__ adjn,
                                       const float* __restrict__ adjw,
                                       int node, int lane) {
    int beg = rowptr[node], end = rowptr[node + 1];
    float acc[Bb][2];
    #pragma unroll
    for (int b = 0; b < Bb; b++) { acc[b][0] = 0.f; acc[b][1] = 0.f; }
    for (int e = beg; e < end; e++) {
        int s = adjn[e];
        float w = adjw[e];
        #pragma unroll
        for (int b = 0; b < Bb; b++) {
            __half2 hv = ((const __half2*)(hin + ((size_t)b * Nn + s) * Hh))[lane];
            float2 f = __half22float2(hv);
            acc[b][0] += f.x * w;
            acc[b][1] += f.y * w;
        }
    }
    #pragma unroll
    for (int b = 0; b < Bb; b++) {
        size_t o = ((size_t)b * Nn + node) * Hh + 2*lane;
        *(float2*)&outF[o] = make_float2(acc[b][0], acc[b][1]);
        if (outH)
            *(__half2*)&outH[o] = __halves2half2(__float2half_rn(acc[b][0]),
                                                 __float2half_rn(acc[b][1]));
    }
}
__global__ void k_prop_h1() {
    int gw = (blockIdx.x * blockDim.x + threadIdx.x) >> 5;
    int lane = threadIdx.x & 31;
    if (gw >= 2*Nn) return;
    if (gw < Nn) prop16(g_h16, g_z0, g_z016, g_rowptr_f, g_adjn_f, g_adjw_f, gw, lane);
    else         prop16(g_h16, g_z2, g_z216, g_rowptr_b, g_adjn_b, g_adjw_b, gw - Nn, lane);
}
__global__ void k_prop_h2() {
    int gw = (blockIdx.x * blockDim.x + threadIdx.x) >> 5;
    int lane = threadIdx.x & 31;
    if (gw >= 2*Nn) return;
    if (gw < Nn) prop16(g_z016, g_z1, (__half*)0, g_rowptr_f, g_adjn_f, g_adjw_f, gw, lane);
    else         prop16(g_z216, g_z3, (__half*)0, g_rowptr_b, g_adjn_b, g_adjw_b, gw - Nn, lane);
}

// ---------------- k_final: HMMA 3-pass hi/lo ----------------
#define FB_A     138240
#define FIN_SMEM 156672

__global__ __launch_bounds__(256, 1)
void k_final(float* __restrict__ out) {
    extern __shared__ __align__(16) char sm[];
    __half* Ahi = (__half*)(sm + FB_A);
    __half* Alo = Ahi + 64*72;

    int tid = threadIdx.x, lane = tid & 31, wid = tid >> 5;
    int mw = wid & 1, nw = wid >> 1;
    int m0 = blockIdx.x * 64;

    {
        const uint4* sw = (const uint4*)g_W2h;
        uint4* dw = (uint4*)sm;
        for (int i = tid; i < 138240/16; i += 256) dw[i] = sw[i];
    }

    int r = tid >> 2, kq = (tid & 3) * 16;
    int arow = lane & 15, acol8 = (lane >> 4) * 8;
    int bn = lane >> 2, bc2 = 2 * (lane & 3);

    float acc[2][3][4];
    #pragma unroll
    for (int i = 0; i < 2; i++)
        #pragma unroll
        for (int j = 0; j < 3; j++)
            #pragma unroll
            for (int q = 0; q < 4; q++) acc[i][j][q] = 0.f;

    uint32_t sb = smem_u32(sm);
    const float* srcs[5] = { g_h0, g_z0, g_z1, g_z2, g_z3 };

    for (int c = 0; c < 5; c++) {
        __syncthreads();
        const float* S = srcs[c] + (size_t)(m0 + r)*64 + kq;
        #pragma unroll
        for (int j = 0; j < 16; j += 2)
            h2split(S[j], S[j+1],
                    (__half2*)(Ahi + r*72 + kq + j), (__half2*)(Alo + r*72 + kq + j));
        __syncthreads();

        #pragma unroll
        for (int p = 0; p < 3; p++) {
            uint32_t aB = sb + FB_A + ((p == 1) ? 64*72*2 : 0);
            uint32_t wB = (p == 2) ? (uint32_t)(34560*2) : 0u;
            #pragma unroll
            for (int ks = 0; ks < 4; ks++) {
                uint32_t afr[2][4];
                #pragma unroll
                for (int mt = 0; mt < 2; mt++)
                    ldmat4(afr[mt], aB + ((mw*32 + mt*16 + arow)*72 + ks*16 + acol8) * 2);
                #pragma unroll
                for (int nt = 0; nt < 3; nt++) {
                    int n = nw*24 + nt*8 + bn;
                    uint32_t bo = wB + ((n*360 + c*72 + ks*16 + bc2) * 2);
                    uint32_t b0 = *(const uint32_t*)(sm + bo);
                    uint32_t b1 = *(const uint32_t*)(sm + bo + 16);
                    mma16816(acc[0][nt], afr[0], b0, b1);
                    mma16816(acc[1][nt], afr[1], b0, b1);
                }
            }
        }
    }

    int g = lane >> 2, c2 = 2 * (lane & 3);
    #pragma unroll
    for (int mt = 0; mt < 2; mt++)
        #pragma unroll
        for (int q2 = 0; q2 < 2; q2++) {
            int row = mw*32 + mt*16 + g + q2*8;
            int m = m0 + row, b = m / Nn, n = m - b * Nn;
            #pragma unroll
            for (int nt = 0; nt < 3; nt++) {
                int col = nw*24 + nt*8 + c2;
                int tt = col >> 3, f = col & 7;
                float2 v = make_float2(acc[mt][nt][q2*2]     + __ldg(&g_b2[col]),
                                       acc[mt][nt][q2*2 + 1] + __ldg(&g_b2[col + 1]));
                *(float2*)&out[(((size_t)b * HOR + tt) * Nn + n) * Ff + f] = v;
            }
        }
}

// ---------------- launch (k_gru at index 3 for ncu capture) ----------------
extern "C" void kernel_launch(void* const* d_in, const int* in_sizes, int n_in,
                              void* d_out, int out_size) {
    const float* x     = (const float*)d_in[0];
    const void*  ei    = d_in[1];
    const float* ew    = (const float*)d_in[2];
    const float* encW  = (const float*)d_in[3];
    const float* encB  = (const float*)d_in[4];
    const float* nemb  = (const float*)d_in[5];
    const float* Wih   = (const float*)d_in[6];
    const float* Whh   = (const float*)d_in[7];
    const float* bih   = (const float*)d_in[8];
    const float* bhh   = (const float*)d_in[9];
    const float* filtW = (const float*)d_in[10];
    const float* filtB = (const float*)d_in[11];
    const float* decW  = (const float*)d_in[12];
    const float* decB  = (const float*)d_in[13];
    float* out = (float*)d_out;

    cudaFuncSetAttribute(k_gru,   cudaFuncAttributeMaxDynamicSharedMemorySize, GRU_SMEM);
    cudaFuncSetAttribute(k_final, cudaFuncAttributeMaxDynamicSharedMemorySize, FIN_SMEM);

    k_wprime<<<6, 256>>>(encW, Wih);                       // 0
    k_cnode<<<Nn/16, 192>>>(encB, nemb, Wih, bih, bhh);    // 1
    k_prepw<<<(33792 + 255) / 256, 256>>>(Whh);            // 2
    k_gru<<<Mm / 64, 256, GRU_SMEM>>>(x, bhh);             // 3  <- ncu captures this
    k_detect<<<1, 1>>>((const unsigned int*)ei);           // 4
    k_convert<<<(Ee + 255) / 256, 256>>>(ei);              // 5
    k_zero<<<(Nn + 255) / 256, 256>>>();                   // 6
    k_w2<<<KCAT + 1, CDEC>>>(filtW, filtB, decW, decB);    // 7
    k_w2img<<<(2*96*360 + 255) / 256, 256>>>();            // 8
    k_count<<<(Ee + 255) / 256, 256>>>(ew);                // 9
    k_scan<<<1, 1024>>>();                                 // 10
    k_fill<<<(Ee + 255) / 256, 256>>>(ew);                 // 11
    k_prop_h1<<<(2*Nn*32 + 255) / 256, 256>>>();           // 12
    k_prop_h2<<<(2*Nn*32 + 255) / 256, 256>>>();           // 13
    k_final<<<Mm / 64, 256, FIN_SMEM>>>(out);              // 14
}

// round 16
// speedup vs baseline: 3.0006x; 1.0824x over previous
#include <cuda_runtime.h>
#include <cuda_fp16.h>
#include <math.h>
#include <stdint.h>

#define Nn   10000
#define Bb   8
#define Tt   12
#define Ff   8
#define Hh   64
#define Ee   320000
#define HOR  12
#define Mm   (Bb*Nn)
#define KCAT 320
#define CDEC 96

// ---------------- device scratch ----------------
__device__ float g_h0[Mm*Hh];
__device__ float g_z0[Mm*Hh];
__device__ float g_z1[Mm*Hh];
__device__ float g_z2[Mm*Hh];
__device__ float g_z3[Mm*Hh];
__device__ __half g_h16[Mm*Hh];
__device__ __half g_z016[Mm*Hh];
__device__ __half g_z216[Mm*Hh];
__device__ int   g_src[Ee], g_tgt[Ee];
__device__ int   g_rowptr_f[Nn+1], g_rowptr_b[Nn+1];
__device__ int   g_cnt_f[Nn], g_cnt_b[Nn], g_cur_f[Nn], g_cur_b[Nn];
__device__ float g_deg_f[Nn], g_deg_b[Nn];
__device__ int   g_adjn_f[Ee]; __device__ float g_adjw_f[Ee];
__device__ int   g_adjn_b[Ee]; __device__ float g_adjw_b[Ee];
__device__ float g_W2[KCAT*CDEC];
__device__ float g_b2[CDEC];
__device__ int   g_flag64;
__device__ float g_Wp[192*8];
__device__ __half g_Cnode16[(size_t)Nn*192];

__device__ __half g_B1Img [2*128*88];
__device__ __half g_B2aImg[2*64*16];
__device__ __half g_B2bImg[2*64*72];
__device__ __half g_W2h[2*96*360];

// ---------------- helpers ----------------
__device__ __forceinline__ uint32_t smem_u32(const void* p) {
    uint32_t a;
    asm("{ .reg .u64 t; cvta.to.shared.u64 t, %1; cvt.u32.u64 %0, t; }" : "=r"(a) : "l"(p));
    return a;
}
__device__ __forceinline__ void ldmat4(uint32_t* f, uint32_t addr) {
    asm volatile("ldmatrix.sync.aligned.m8n8.x4.shared.b16 {%0,%1,%2,%3}, [%4];"
        : "=r"(f[0]), "=r"(f[1]), "=r"(f[2]), "=r"(f[3]) : "r"(addr));
}
__device__ __forceinline__ void mma16816(float* c, const uint32_t* a, uint32_t b0, uint32_t b1) {
    asm volatile("mma.sync.aligned.m16n8k16.row.col.f32.f16.f16.f32 "
        "{%0,%1,%2,%3}, {%4,%5,%6,%7}, {%8,%9}, {%0,%1,%2,%3};"
        : "+f"(c[0]), "+f"(c[1]), "+f"(c[2]), "+f"(c[3])
        : "r"(a[0]), "r"(a[1]), "r"(a[2]), "r"(a[3]), "r"(b0), "r"(b1));
}
#define CPA16(sa, gp) asm volatile("cp.async.cg.shared.global [%0], [%1], 16;" :: "r"(sa), "l"(gp))
#define CPA_WAIT()    asm volatile("cp.async.wait_all;" ::: "memory")
__device__ __forceinline__ float sigf(float x)  { return 1.f / (1.f + __expf(-x)); }
__device__ __forceinline__ float tanhff(float x){ float e = __expf(2.f*x); return 1.f - 2.f/(e + 1.f); }
__device__ __forceinline__ void h2split(float v0, float v1, __half2* hi, __half2* lo) {
    __half a = __float2half_rn(v0), b = __float2half_rn(v1);
    *hi = __halves2half2(a, b);
    *lo = __halves2half2(__float2half_rn(v0 - __half2float(a)),
                         __float2half_rn(v1 - __half2float(b)));
}

// ---------------- small prep kernels ----------------
__global__ void k_detect(const unsigned int* ei_raw) {
    bool all0 = true;
    for (int i = 0; i < 16; i++) if (ei_raw[2*i + 1] != 0u) all0 = false;
    g_flag64 = all0 ? 1 : 0;
}
__global__ void k_convert(const void* ei) {
    int e = blockIdx.x * blockDim.x + threadIdx.x;
    if (e >= Ee) return;
    if (g_flag64) {
        const long long* p = (const long long*)ei;
        g_src[e] = (int)p[e]; g_tgt[e] = (int)p[Ee + e];
    } else {
        const int* p = (const int*)ei;
        g_src[e] = p[e]; g_tgt[e] = p[Ee + e];
    }
}
__global__ void k_zero() {
    int i = blockIdx.x * blockDim.x + threadIdx.x;
    if (i < Nn) {
        g_cnt_f[i] = 0; g_cnt_b[i] = 0; g_cur_f[i] = 0; g_cur_b[i] = 0;
        g_deg_f[i] = 0.f; g_deg_b[i] = 0.f;
    }
}
__global__ void k_w2(const float* __restrict__ filtW, const float* __restrict__ filtB,
                     const float* __restrict__ decW,  const float* __restrict__ decB) {
    int c = threadIdx.x, k = blockIdx.x;
    if (k < KCAT) {
        float acc = 0.f;
        for (int j = 0; j < Hh; j++) acc += filtW[k*Hh + j] * decW[j*CDEC + c];
        g_W2[k*CDEC + c] = acc;
    } else {
        float acc = decB[c];
        for (int j = 0; j < Hh; j++) acc += filtB[j] * decW[j*CDEC + c];
        g_b2[c] = acc;
    }
}
__global__ void k_w2img() {
    int idx = blockIdx.x * blockDim.x + threadIdx.x;
    if (idx >= 2*96*360) return;
    int prec = idx / 34560, rem = idx % 34560;
    int n = rem / 360, q = rem % 360;
    int c = q / 72, k = q % 72;
    float val = (k < 64) ? g_W2[(c*64 + k)*CDEC + n] : 0.f;
    __half hi = __float2half_rn(val);
    g_W2h[idx] = prec ? __float2half_rn(val - __half2float(hi)) : hi;
}
__global__ void k_wprime(const float* __restrict__ encW, const float* __restrict__ Wih) {
    int idx = blockIdx.x * blockDim.x + threadIdx.x;
    if (idx >= 192*8) return;
    int g = idx >> 3, f = idx & 7;
    float acc = 0.f;
    for (int h = 0; h < 64; h++) acc += encW[f*64 + h] * Wih[g*64 + h];
    g_Wp[g*8 + f] = acc;
}
__global__ __launch_bounds__(192)
void k_cnode(const float* __restrict__ encB, const float* __restrict__ nodeEmb,
             const float* __restrict__ Wih,  const float* __restrict__ bih,
             const float* __restrict__ bhh) {
    __shared__ float sEB[16][68];
    int tid = threadIdx.x, n0 = blockIdx.x * 16;
    for (int i = tid; i < 16*64; i += 192) {
        int nl = i >> 6, k = i & 63;
        sEB[nl][k] = encB[k] + nodeEmb[(n0 + nl)*64 + k];
    }
    __syncthreads();
    int c = tid;
    float w[64];
    #pragma unroll
    for (int k = 0; k < 64; k++) w[k] = Wih[c*64 + k];
    float bb = bih[c] + ((c < 128) ? bhh[c] : 0.f);
    for (int nl = 0; nl < 16; nl++) {
        float acc = bb;
        #pragma unroll
        for (int k = 0; k < 64; k++) acc += sEB[nl][k] * w[k];
        g_Cnode16[(size_t)(n0 + nl)*192 + c] = __float2half_rn(acc);
    }
}
__global__ void k_prepw(const float* __restrict__ Whh) {
    int idx = blockIdx.x * blockDim.x + threadIdx.x;
    if (idx >= 33792) return;
    float val = 0.f;
    if (idx < 22528) {
        int prec = idx / 11264, rem = idx % 11264;
        int n = rem / 88, k = rem % 88;
        if (k < 64)      val = Whh[n*64 + k];
        else if (k < 72) val = g_Wp[n*8 + (k - 64)];
        __half hi = __float2half_rn(val);
        g_B1Img[idx] = prec ? __float2half_rn(val - __half2float(hi)) : hi;
        return;
    }
    if (idx < 24576) {
        int q = idx - 22528;
        int prec = q / 1024, rem = q % 1024;
        int n = rem / 16, k = rem % 16;
        if (k < 8) val = g_Wp[(128 + n)*8 + k];
        __half hi = __float2half_rn(val);
        g_B2aImg[q] = prec ? __float2half_rn(val - __half2float(hi)) : hi;
        return;
    }
    {
        int q = idx - 24576;
        int prec = q / 4608, rem = q % 4608;
        int n = rem / 72, k = rem % 72;
        if (k < 64) val = Whh[(128 + n)*64 + k];
        __half hi = __float2half_rn(val);
        g_B2bImg[q] = prec ? __float2half_rn(val - __half2float(hi)) : hi;
    }
}

// ================= fused 12-step GRU v5 (R15 winner, unchanged) =================
#define GA_HI  0
#define GB1    9216
#define GB2A   54272
#define GB2B   58368
#define GC16   76800
#define GXR    101888
#define GRU_SMEM 105984

__global__ __launch_bounds__(256, 2)
void k_gru(const float* __restrict__ x, const float* __restrict__ bhh)
{
    extern __shared__ __align__(16) char sm[];
    __half* Ahi = (__half*)(sm + GA_HI);
    __half* sC  = (__half*)(sm + GC16);
    float*  sXr = (float*)(sm + GXR);

    int tid = threadIdx.x, lane = tid & 31, wid = tid >> 5;
    int mw = wid & 1, nw = wid >> 1;
    int m0 = blockIdx.x * 64;

    {
        const uint4* s1 = (const uint4*)g_B1Img;  uint4* d1 = (uint4*)(sm + GB1);
        for (int i = tid; i < 45056/16; i += 256) d1[i] = s1[i];
        const uint4* s2 = (const uint4*)g_B2aImg; uint4* d2 = (uint4*)(sm + GB2A);
        if (tid < 4096/16) d2[tid] = s2[tid];
        const uint4* s3 = (const uint4*)g_B2bImg; uint4* d3 = (uint4*)(sm + GB2B);
        for (int i = tid; i < 18432/16; i += 256) d3[i] = s3[i];
        for (int i = tid; i < 3072; i += 256) {
            int row = i / 48, ch = i % 48;
            int node = (m0 + row) % Nn;
            const uint2* srcc = (const uint2*)(g_Cnode16 + (size_t)node*192) + ch;
            *((uint2*)(sC + row*196) + ch) = *srcc;
        }
    }

    uint32_t sb = smem_u32(sm);

    if (tid < 128) {
        int row = tid >> 1, ch = tid & 1;
        int mm = m0 + row, b2 = mm / Nn, n2 = mm - b2 * Nn;
        CPA16(sb + GXR + (row*8 + ch*4)*4, &x[(((size_t)b2*Tt + 0)*Nn + n2)*Ff + ch*4]);
    }
    CPA_WAIT();
    __syncthreads();

    int g  = lane >> 2;
    int c2 = 2 * (lane & 3);
    int arow = lane & 15, acol8 = (lane >> 4) * 8;

    int ntp   = (lane >> 4) & 1;
    int khalf = (lane >> 3) & 1;
    int nnB   = nw*16 + ntp*8 + (lane & 7);
    uint32_t offR = (uint32_t)((nnB*88 + khalf*8) * 2);
    uint32_t offZ = offR + 64*88*2;
    uint32_t offN = (uint32_t)((nnB*16 + khalf*8) * 2);
    uint32_t offH = (uint32_t)((nnB*72 + khalf*8) * 2);

    float bhn[2][2];
    #pragma unroll
    for (int nt = 0; nt < 2; nt++)
        #pragma unroll
        for (int c = 0; c < 2; c++)
            bhn[nt][c] = __ldg(&bhh[128 + nw*16 + nt*8 + c2 + c]);

    float h[16];
    #pragma unroll
    for (int i = 0; i < 16; i++) h[i] = 0.f;

    int xrow = tid >> 2, xp = (tid & 3) * 2;

    for (int t = 0; t < Tt; t++) {
        int cur = t & 1;

        #pragma unroll
        for (int mt = 0; mt < 2; mt++)
            #pragma unroll
            for (int q2 = 0; q2 < 2; q2++) {
                int row = mw*32 + mt*16 + g + q2*8;
                #pragma unroll
                for (int nt = 0; nt < 2; nt++) {
                    int j0 = nw*16 + nt*8 + c2;
                    int hi = mt*8 + q2*4 + nt*2;
                    *(__half2*)(Ahi + row*72 + j0) = __floats2half2_rn(h[hi], h[hi+1]);
                }
            }
        *(__half2*)(Ahi + xrow*72 + 64 + xp) =
            __floats2half2_rn(sXr[cur*512 + xrow*8 + xp], sXr[cur*512 + xrow*8 + xp + 1]);
        __syncthreads();

        if (t + 1 < Tt && tid < 128) {
            int row = tid >> 1, ch = tid & 1;
            int mm = m0 + row, b2 = mm / Nn, n2 = mm - b2 * Nn;
            CPA16(sb + GXR + ((1-cur)*512 + row*8 + ch*4)*4,
                  &x[(((size_t)b2*Tt + (t+1))*Nn + n2)*Ff + ch*4]);
        }

        float aR[2][2][4], aZ[2][2][4], aN[2][2][4], aH[2][2][4];
        #pragma unroll
        for (int i = 0; i < 2; i++)
            #pragma unroll
            for (int j = 0; j < 2; j++)
                #pragma unroll
                for (int q = 0; q < 4; q++) {
                    aR[i][j][q] = 0.f; aZ[i][j][q] = 0.f;
                    aN[i][j][q] = 0.f; aH[i][j][q] = 0.f;
                }

        #pragma unroll
        for (int p = 0; p < 2; p++) {
            uint32_t b1B = sb + GB1  + (p ? 22528u : 0u);
            uint32_t b2aB= sb + GB2A + (p ? 2048u  : 0u);
            uint32_t b2bB= sb + GB2B + (p ? 9216u  : 0u);
            #pragma unroll
            for (int ks = 0; ks < 5; ks++) {
                uint32_t afr[2][4];
                #pragma unroll
                for (int mt = 0; mt < 2; mt++)
                    ldmat4(afr[mt], sb + GA_HI + ((mw*32 + mt*16 + arow)*72 + ks*16 + acol8) * 2);

                uint32_t fR[4], fZ[4];
                ldmat4(fR, b1B + offR + ks*32);
                mma16816(aR[0][0], afr[0], fR[0], fR[1]);
                mma16816(aR[1][0], afr[1], fR[0], fR[1]);
                mma16816(aR[0][1], afr[0], fR[2], fR[3]);
                mma16816(aR[1][1], afr[1], fR[2], fR[3]);
                ldmat4(fZ, b1B + offZ + ks*32);
                mma16816(aZ[0][0], afr[0], fZ[0], fZ[1]);
                mma16816(aZ[1][0], afr[1], fZ[0], fZ[1]);
                mma16816(aZ[0][1], afr[0], fZ[2], fZ[3]);
                mma16816(aZ[1][1], afr[1], fZ[2], fZ[3]);
                if (ks == 4) {
                    uint32_t fN[4];
                    ldmat4(fN, b2aB + offN);
                    mma16816(aN[0][0], afr[0], fN[0], fN[1]);
                    mma16816(aN[1][0], afr[1], fN[0], fN[1]);
                    mma16816(aN[0][1], afr[0], fN[2], fN[3]);
                    mma16816(aN[1][1], afr[1], fN[2], fN[3]);
                } else {
                    uint32_t fH[4];
                    ldmat4(fH, b2bB + offH + ks*32);
                    mma16816(aH[0][0], afr[0], fH[0], fH[1]);
                    mma16816(aH[1][0], afr[1], fH[0], fH[1]);
                    mma16816(aH[0][1], afr[0], fH[2], fH[3]);
                    mma16816(aH[1][1], afr[1], fH[2], fH[3]);
                }
            }
        }

        #pragma unroll
        for (int mt = 0; mt < 2; mt++)
            #pragma unroll
            for (int q2 = 0; q2 < 2; q2++) {
                int row = mw*32 + mt*16 + g + q2*8;
                #pragma unroll
                for (int nt = 0; nt < 2; nt++) {
                    int j0 = nw*16 + nt*8 + c2;
                    float2 fr = __half22float2(*(__half2*)&sC[row*196 + j0]);
                    float2 fz = __half22float2(*(__half2*)&sC[row*196 + 64 + j0]);
                    float2 fn = __half22float2(*(__half2*)&sC[row*196 + 128 + j0]);
                    #pragma unroll
                    for (int c = 0; c < 2; c++) {
                        int ai = q2*2 + c;
                        float rv  = aR[mt][nt][ai] + (c ? fr.y : fr.x);
                        float zv  = aZ[mt][nt][ai] + (c ? fz.y : fz.x);
                        float xnv = aN[mt][nt][ai] + (c ? fn.y : fn.x);
                        float hnv = aH[mt][nt][ai] + bhn[nt][c];
                        float rg = sigf(rv), zg = sigf(zv);
                        float ng = tanhff(xnv + rg * hnv);
                        int hi = mt*8 + q2*4 + nt*2 + c;
                        h[hi] = (1.f - zg) * ng + zg * h[hi];
                    }
                }
            }

        CPA_WAIT();
        __syncthreads();
    }

    #pragma unroll
    for (int mt = 0; mt < 2; mt++)
        #pragma unroll
        for (int q2 = 0; q2 < 2; q2++) {
            int row = mw*32 + mt*16 + g + q2*8;
            #pragma unroll
            for (int nt = 0; nt < 2; nt++) {
                int j0 = nw*16 + nt*8 + c2;
                int hi = mt*8 + q2*4 + nt*2;
                size_t o = (size_t)(m0 + row)*Hh + j0;
                *(float2*)&g_h0[o] = make_float2(h[hi], h[hi+1]);
                *(__half2*)&g_h16[o] = __halves2half2(__float2half_rn(h[hi]),
                                                      __float2half_rn(h[hi+1]));
            }
        }
}

// ---------------- CSR build ----------------
__global__ void k_count(const float* __restrict__ ew) {
    int e = blockIdx.x * blockDim.x + threadIdx.x;
    if (e >= Ee) return;
    int s = g_src[e], t = g_tgt[e];
    float w = ew[e];
    atomicAdd(&g_cnt_f[t], 1);  atomicAdd(&g_deg_f[t], w);
    atomicAdd(&g_cnt_b[s], 1);  atomicAdd(&g_deg_b[s], w);
}

// thread-coarsened single-block scan: 256 threads x 40 nodes
__global__ __launch_bounds__(256)
void k_scan2() {
    __shared__ int wsum[8];
    int tid = threadIdx.x, lane = tid & 31, w = tid >> 5;
    for (int which = 0; which < 2; ++which) {
        const int* cnt = which ? g_cnt_b : g_cnt_f;
        int* rp        = which ? g_rowptr_b : g_rowptr_f;
        int base = tid * 40;
        int sum = 0;
        for (int j = 0; j < 40; j++) {
            int i = base + j;
            if (i < Nn) sum += cnt[i];
        }
        int v = sum;
        #pragma unroll
        for (int off = 1; off < 32; off <<= 1) {
            int n = __shfl_up_sync(0xFFFFFFFFu, v, off);
            if (lane >= off) v += n;
        }
        if (lane == 31) wsum[w] = v;
        __syncthreads();
        if (tid == 0) {
            int r = 0;
            #pragma unroll
            for (int k = 0; k < 8; k++) { int t2 = wsum[k]; wsum[k] = r; r += t2; }
        }
        __syncthreads();
        int running = v - sum + wsum[w];
        for (int j = 0; j < 40; j++) {
            int i = base + j;
            if (i < Nn) { running += cnt[i]; rp[i + 1] = running; }
        }
        if (tid == 0) rp[0] = 0;
        __syncthreads();
    }
}

__global__ void k_fill(const float* __restrict__ ew) {
    int e = blockIdx.x * blockDim.x + threadIdx.x;
    if (e >= Ee) return;
    int s = g_src[e], t = g_tgt[e];
    float w = ew[e];
    float df = g_deg_f[t]; df = (df == 0.f) ? 1.f : df;
    int pf = g_rowptr_f[t] + atomicAdd(&g_cur_f[t], 1);
    g_adjn_f[pf] = s;  g_adjw_f[pf] = w / df;
    float db = g_deg_b[s]; db = (db == 0.f) ? 1.f : db;
    int pb = g_rowptr_b[s] + atomicAdd(&g_cur_b[s], 1);
    g_adjn_b[pb] = t;  g_adjw_b[pb] = w / db;
}

// ---------------- diffusion props ----------------
__device__ __forceinline__ void prop16(const __half* __restrict__ hin,
                                       float* __restrict__ outF, __half* __restrict__ outH,
                                       const int* __restrict__ rowptr,
                                       const int* __restrict__ adjn,
                                       const float* __restrict__ adjw,
                                       int node, int lane) {
    int beg = rowptr[node], end = rowptr[node + 1];
    float acc[Bb][2];
    #pragma unroll
    for (int b = 0; b < Bb; b++) { acc[b][0] = 0.f; acc[b][1] = 0.f; }
    for (int e = beg; e < end; e++) {
        int s = adjn[e];
        float w = adjw[e];
        #pragma unroll
        for (int b = 0; b < Bb; b++) {
            __half2 hv = ((const __half2*)(hin + ((size_t)b * Nn + s) * Hh))[lane];
            float2 f = __half22float2(hv);
            acc[b][0] += f.x * w;
            acc[b][1] += f.y * w;
        }
    }
    #pragma unroll
    for (int b = 0; b < Bb; b++) {
        size_t o = ((size_t)b * Nn + node) * Hh + 2*lane;
        *(float2*)&outF[o] = make_float2(acc[b][0], acc[b][1]);
        if (outH)
            *(__half2*)&outH[o] = __halves2half2(__float2half_rn(acc[b][0]),
                                                 __float2half_rn(acc[b][1]));
    }
}
__global__ void k_prop_h1() {
    int gw = (blockIdx.x * blockDim.x + threadIdx.x) >> 5;
    int lane = threadIdx.x & 31;
    if (gw >= 2*Nn) return;
    if (gw < Nn) prop16(g_h16, g_z0, g_z016, g_rowptr_f, g_adjn_f, g_adjw_f, gw, lane);
    else         prop16(g_h16, g_z2, g_z216, g_rowptr_b, g_adjn_b, g_adjw_b, gw - Nn, lane);
}
__global__ void k_prop_h2() {
    int gw = (blockIdx.x * blockDim.x + threadIdx.x) >> 5;
    int lane = threadIdx.x & 31;
    if (gw >= 2*Nn) return;
    if (gw < Nn) prop16(g_z016, g_z1, (__half*)0, g_rowptr_f, g_adjn_f, g_adjw_f, gw, lane);
    else         prop16(g_z216, g_z3, (__half*)0, g_rowptr_b, g_adjn_b, g_adjw_b, gw - Nn, lane);
}

// ---------------- k_final: HMMA 3-pass hi/lo ----------------
#define FB_A     138240
#define FIN_SMEM 156672

__global__ __launch_bounds__(256, 1)
void k_final(float* __restrict__ out) {
    extern __shared__ __align__(16) char sm[];
    __half* Ahi = (__half*)(sm + FB_A);
    __half* Alo = Ahi + 64*72;

    int tid = threadIdx.x, lane = tid & 31, wid = tid >> 5;
    int mw = wid & 1, nw = wid >> 1;
    int m0 = blockIdx.x * 64;

    {
        const uint4* sw = (const uint4*)g_W2h;
        uint4* dw = (uint4*)sm;
        for (int i = tid; i < 138240/16; i += 256) dw[i] = sw[i];
    }

    int r = tid >> 2, kq = (tid & 3) * 16;
    int arow = lane & 15, acol8 = (lane >> 4) * 8;
    int bn = lane >> 2, bc2 = 2 * (lane & 3);

    float acc[2][3][4];
    #pragma unroll
    for (int i = 0; i < 2; i++)
        #pragma unroll
        for (int j = 0; j < 3; j++)
            #pragma unroll
            for (int q = 0; q < 4; q++) acc[i][j][q] = 0.f;

    uint32_t sb = smem_u32(sm);
    const float* srcs[5] = { g_h0, g_z0, g_z1, g_z2, g_z3 };

    for (int c = 0; c < 5; c++) {
        __syncthreads();
        const float* S = srcs[c] + (size_t)(m0 + r)*64 + kq;
        #pragma unroll
        for (int j = 0; j < 16; j += 2)
            h2split(S[j], S[j+1],
                    (__half2*)(Ahi + r*72 + kq + j), (__half2*)(Alo + r*72 + kq + j));
        __syncthreads();

        #pragma unroll
        for (int p = 0; p < 3; p++) {
            uint32_t aB = sb + FB_A + ((p == 1) ? 64*72*2 : 0);
            uint32_t wB = (p == 2) ? (uint32_t)(34560*2) : 0u;
            #pragma unroll
            for (int ks = 0; ks < 4; ks++) {
                uint32_t afr[2][4];
                #pragma unroll
                for (int mt = 0; mt < 2; mt++)
                    ldmat4(afr[mt], aB + ((mw*32 + mt*16 + arow)*72 + ks*16 + acol8) * 2);
                #pragma unroll
                for (int nt = 0; nt < 3; nt++) {
                    int n = nw*24 + nt*8 + bn;
                    uint32_t bo = wB + ((n*360 + c*72 + ks*16 + bc2) * 2);
                    uint32_t b0 = *(const uint32_t*)(sm + bo);
                    uint32_t b1 = *(const uint32_t*)(sm + bo + 16);
                    mma16816(acc[0][nt], afr[0], b0, b1);
                    mma16816(acc[1][nt], afr[1], b0, b1);
                }
            }
        }
    }

    int g = lane >> 2, c2 = 2 * (lane & 3);
    #pragma unroll
    for (int mt = 0; mt < 2; mt++)
        #pragma unroll
        for (int q2 = 0; q2 < 2; q2++) {
            int row = mw*32 + mt*16 + g + q2*8;
            int m = m0 + row, b = m / Nn, n = m - b * Nn;
            #pragma unroll
            for (int nt = 0; nt < 3; nt++) {
                int col = nw*24 + nt*8 + c2;
                int tt = col >> 3, f = col & 7;
                float2 v = make_float2(acc[mt][nt][q2*2]     + __ldg(&g_b2[col]),
                                       acc[mt][nt][q2*2 + 1] + __ldg(&g_b2[col + 1]));
                *(float2*)&out[(((size_t)b * HOR + tt) * Nn + n) * Ff + f] = v;
            }
        }
}

// ---------------- launch: fork CSR/w2 branch onto a second stream ----------------
extern "C" void kernel_launch(void* const* d_in, const int* in_sizes, int n_in,
                              void* d_out, int out_size) {
    const float* x     = (const float*)d_in[0];
    const void*  ei    = d_in[1];
    const float* ew    = (const float*)d_in[2];
    const float* encW  = (const float*)d_in[3];
    const float* encB  = (const float*)d_in[4];
    const float* nemb  = (const float*)d_in[5];
    const float* Wih   = (const float*)d_in[6];
    const float* Whh   = (const float*)d_in[7];
    const float* bih   = (const float*)d_in[8];
    const float* bhh   = (const float*)d_in[9];
    const float* filtW = (const float*)d_in[10];
    const float* filtB = (const float*)d_in[11];
    const float* decW  = (const float*)d_in[12];
    const float* decB  = (const float*)d_in[13];
    float* out = (float*)d_out;

    cudaFuncSetAttribute(k_gru,   cudaFuncAttributeMaxDynamicSharedMemorySize, GRU_SMEM);
    cudaFuncSetAttribute(k_final, cudaFuncAttributeMaxDynamicSharedMemorySize, FIN_SMEM);

    // one-time side stream + events (created on first, uncaptured, call)
    static cudaStream_t s2 = 0;
    static cudaEvent_t evFork = 0, evJoin = 0;
    static int tried = 0;
    if (!tried) {
        tried = 1;
        if (cudaStreamCreateWithFlags(&s2, cudaStreamNonBlocking) != cudaSuccess) s2 = 0;
        if (s2) {
            if (cudaEventCreateWithFlags(&evFork, cudaEventDisableTiming) != cudaSuccess ||
                cudaEventCreateWithFlags(&evJoin, cudaEventDisableTiming) != cudaSuccess) {
                s2 = 0;
            }
        }
    }
    cudaStream_t sB = s2 ? s2 : 0;

    if (s2) {
        cudaEventRecord(evFork, 0);
        cudaStreamWaitEvent(s2, evFork, 0);
    }

    // branch A (stream 0): GRU chain. branch B (sB): CSR + W2 chain.
    k_wprime<<<6, 256, 0, 0>>>(encW, Wih);                        // 0
    k_cnode<<<Nn/16, 192, 0, 0>>>(encB, nemb, Wih, bih, bhh);     // 1
    k_prepw<<<(33792 + 255) / 256, 256, 0, 0>>>(Whh);             // 2
    k_detect<<<1, 1, 0, sB>>>((const unsigned int*)ei);           // 3
    k_convert<<<(Ee + 255) / 256, 256, 0, sB>>>(ei);              // 4
    k_gru<<<Mm / 64, 256, GRU_SMEM, 0>>>(x, bhh);                 // 5  <- ncu captures this
    k_zero<<<(Nn + 255) / 256, 256, 0, sB>>>();                   // 6
    k_count<<<(Ee + 255) / 256, 256, 0, sB>>>(ew);                // 7
    k_scan2<<<1, 256, 0, sB>>>();                                 // 8
    k_fill<<<(Ee + 255) / 256, 256, 0, sB>>>(ew);                 // 9
    k_w2<<<KCAT + 1, CDEC, 0, sB>>>(filtW, filtB, decW, decB);    // 10
    k_w2img<<<(2*96*360 + 255) / 256, 256, 0, sB>>>();            // 11

    if (s2) {
        cudaEventRecord(evJoin, s2);
        cudaStreamWaitEvent(0, evJoin, 0);
    }

    k_prop_h1<<<(2*Nn*32 + 255) / 256, 256, 0, 0>>>();            // 12
    k_prop_h2<<<(2*Nn*32 + 255) / 256, 256, 0, 0>>>();            // 13
    k_final<<<Mm / 64, 256, FIN_SMEM, 0>>>(out);                  // 14
}